// round 4
// baseline (speedup 1.0000x reference)
#include <cuda_runtime.h>
#include <cuda_bf16.h>
#include <cstdint>
#include <math.h>

// ---------------- problem constants ----------------
constexpr int B_  = 2;
constexpr int S_  = 2048;
constexpr int E_  = 1024;
constexpr int H_  = 16;
constexpr int DK_ = 64;
constexpr int HID_= 4096;
constexpr int M_  = B_ * S_;       // 4096 rows
constexpr int NQKV_ = 3 * E_;      // 3072 fused qkv output cols
constexpr int QKV_LD = NQKV_;

// ================= PTX helpers (base sm_103: mma.sync/ldmatrix/cp.async) ==
__device__ __forceinline__ uint32_t smem_to_u32(const void* p) {
    uint32_t a;
    asm("{ .reg .u64 t; cvta.to.shared.u64 t, %1; cvt.u32.u64 %0, t; }"
        : "=r"(a) : "l"(p));
    return a;
}
__device__ __forceinline__ void mma16816(float* d, const uint32_t* a, const uint32_t* b) {
    asm volatile("mma.sync.aligned.m16n8k16.row.col.f32.bf16.bf16.f32 "
        "{%0,%1,%2,%3}, {%4,%5,%6,%7}, {%8,%9}, {%0,%1,%2,%3};"
        : "+f"(d[0]), "+f"(d[1]), "+f"(d[2]), "+f"(d[3])
        : "r"(a[0]), "r"(a[1]), "r"(a[2]), "r"(a[3]), "r"(b[0]), "r"(b[1]));
}
__device__ __forceinline__ void ldsm_x4(uint32_t* r, uint32_t addr) {
    asm volatile("ldmatrix.sync.aligned.m8n8.x4.shared.b16 {%0,%1,%2,%3}, [%4];"
        : "=r"(r[0]), "=r"(r[1]), "=r"(r[2]), "=r"(r[3]) : "r"(addr));
}
__device__ __forceinline__ void ldsm_x2(uint32_t* r, uint32_t addr) {
    asm volatile("ldmatrix.sync.aligned.m8n8.x2.shared.b16 {%0,%1}, [%2];"
        : "=r"(r[0]), "=r"(r[1]) : "r"(addr));
}
__device__ __forceinline__ void ldsm_x2t(uint32_t* r, uint32_t addr) {
    asm volatile("ldmatrix.sync.aligned.m8n8.x2.trans.shared.b16 {%0,%1}, [%2];"
        : "=r"(r[0]), "=r"(r[1]) : "r"(addr));
}
__device__ __forceinline__ void cp_async16(uint32_t dst, const void* src) {
    asm volatile("cp.async.cg.shared.global [%0], [%1], 16;" :: "r"(dst), "l"(src));
}
#define CP_COMMIT() asm volatile("cp.async.commit_group;")
__device__ __forceinline__ uint32_t packbf2(float a, float b) {
    __nv_bfloat162 h = __floats2bfloat162_rn(a, b);
    return *(uint32_t*)&h;
}

// ---------------- scratch (device globals) --------------------------------
__device__ __align__(16) float g_x  [M_ * E_];
__device__ __align__(16) float g_xo [M_ * E_];
__device__ __align__(16) float g_y  [M_ * E_];
__device__ __align__(16) __nv_bfloat16 g_qkv_hi[M_ * NQKV_], g_qkv_lo[M_ * NQKV_];
__device__ __align__(16) __nv_bfloat16 g_xhi[M_ * E_],  g_xlo[M_ * E_];
__device__ __align__(16) __nv_bfloat16 g_yhi[M_ * E_],  g_ylo[M_ * E_];
__device__ __align__(16) __nv_bfloat16 g_hhi[M_ * HID_], g_hlo[M_ * HID_];
__device__ __align__(16) __nv_bfloat16 g_wqkv_hi[NQKV_ * E_], g_wqkv_lo[NQKV_ * E_];
__device__ __align__(16) __nv_bfloat16 g_w1t_hi[HID_ * E_],   g_w1t_lo[HID_ * E_];
__device__ __align__(16) __nv_bfloat16 g_w2t_hi[E_ * HID_],   g_w2t_lo[E_ * HID_];
__device__ float g_bcat[NQKV_];

// ---------------- transpose + fp32 -> bf16 hi/lo (optional scale) ----------
__global__ void transpose_cvt(const float* __restrict__ in,
                              __nv_bfloat16* __restrict__ ohi,
                              __nv_bfloat16* __restrict__ olo,
                              int R, int C, long inBatch, long outBatch,
                              float scale) {
    __shared__ float tile[32][33];
    in  += (size_t)blockIdx.z * inBatch;
    ohi += (size_t)blockIdx.z * outBatch;
    olo += (size_t)blockIdx.z * outBatch;
    int c0 = blockIdx.x * 32, r0 = blockIdx.y * 32;
    int tx = threadIdx.x, ty = threadIdx.y;
    #pragma unroll
    for (int j = 0; j < 4; j++)
        tile[ty + j * 8][tx] = in[(size_t)(r0 + ty + j * 8) * C + c0 + tx];
    __syncthreads();
    #pragma unroll
    for (int j = 0; j < 4; j++) {
        float v = tile[tx][ty + j * 8] * scale;
        __nv_bfloat16 hi = __float2bfloat16(v);
        float lo = v - __bfloat162float(hi);
        size_t o = (size_t)(c0 + ty + j * 8) * R + r0 + tx;
        ohi[o] = hi;
        olo[o] = __float2bfloat16(lo);
    }
}

__global__ void bias_cat_kernel(const float* __restrict__ bq,
                                const float* __restrict__ bk,
                                const float* __restrict__ bv,
                                float* __restrict__ bcat) {
    int n = blockIdx.x * 256 + threadIdx.x;
    const float* src = (n < 1024) ? bq : ((n < 2048) ? bk : bv);
    float sc = (n < 1024) ? 0.125f : 1.f;     // fold 1/sqrt(DK) into q bias
    bcat[n] = src[n & 1023] * sc;
}

// ---------------- LayerNorm: fp32 out + bf16 hi/lo out ---------------------
__global__ void ln_kernel(const float* __restrict__ in,
                          const float* __restrict__ w,
                          const float* __restrict__ b,
                          float* __restrict__ out,
                          __nv_bfloat16* __restrict__ ohi,
                          __nv_bfloat16* __restrict__ olo) {
    int row = blockIdx.x;
    int t = threadIdx.x;
    const float4* ip = (const float4*)(in + (size_t)row * E_);
    float4 v = ip[t];
    float s  = v.x + v.y + v.z + v.w;
    float sq = v.x*v.x + v.y*v.y + v.z*v.z + v.w*v.w;
    #pragma unroll
    for (int o = 16; o; o >>= 1) {
        s  += __shfl_xor_sync(0xffffffffu, s,  o);
        sq += __shfl_xor_sync(0xffffffffu, sq, o);
    }
    __shared__ float ss[8], ssq[8];
    __shared__ float mu_s, inv_s;
    if ((t & 31) == 0) { ss[t >> 5] = s; ssq[t >> 5] = sq; }
    __syncthreads();
    if (t < 32) {
        float s2  = (t < 8) ? ss[t]  : 0.f;
        float sq2 = (t < 8) ? ssq[t] : 0.f;
        #pragma unroll
        for (int o = 4; o; o >>= 1) {
            s2  += __shfl_xor_sync(0xffffffffu, s2,  o);
            sq2 += __shfl_xor_sync(0xffffffffu, sq2, o);
        }
        if (t == 0) {
            float mu  = s2 * (1.f / E_);
            float var = sq2 * (1.f / E_) - mu * mu;
            mu_s  = mu;
            inv_s = rsqrtf(var + 1e-5f);
        }
    }
    __syncthreads();
    float mu = mu_s, inv = inv_s;
    float4 wv = ((const float4*)w)[t];
    float4 bv = ((const float4*)b)[t];
    float4 o4;
    o4.x = (v.x - mu) * inv * wv.x + bv.x;
    o4.y = (v.y - mu) * inv * wv.y + bv.y;
    o4.z = (v.z - mu) * inv * wv.z + bv.z;
    o4.w = (v.w - mu) * inv * wv.w + bv.w;
    ((float4*)(out + (size_t)row * E_))[t] = o4;
    __nv_bfloat16 h0 = __float2bfloat16(o4.x), h1 = __float2bfloat16(o4.y);
    __nv_bfloat16 h2 = __float2bfloat16(o4.z), h3 = __float2bfloat16(o4.w);
    __nv_bfloat162 hp0; hp0.x = h0; hp0.y = h1;
    __nv_bfloat162 hp1; hp1.x = h2; hp1.y = h3;
    ((__nv_bfloat162*)(ohi + (size_t)row * E_))[2*t]   = hp0;
    ((__nv_bfloat162*)(ohi + (size_t)row * E_))[2*t+1] = hp1;
    __nv_bfloat162 lp0, lp1;
    lp0.x = __float2bfloat16(o4.x - __bfloat162float(h0));
    lp0.y = __float2bfloat16(o4.y - __bfloat162float(h1));
    lp1.x = __float2bfloat16(o4.z - __bfloat162float(h2));
    lp1.y = __float2bfloat16(o4.w - __bfloat162float(h3));
    ((__nv_bfloat162*)(olo + (size_t)row * E_))[2*t]   = lp0;
    ((__nv_bfloat162*)(olo + (size_t)row * E_))[2*t+1] = lp1;
}

// ---------------- HMMA GEMM: C[M,N] = (Ahi+Alo) @ (Bhi+Blo)^T --------------
// CTA tile 128x128, 8 warps of 64x32, K chunk 32, 3-stage cp.async pipeline.
// mode 1: relu -> Chi/Clo | mode 2: fp32 + bias + resid | mode 3: Chi/Clo + bias
constexpr int GSTRIDE_B = 80;                // bytes per smem row (40 bf16)
constexpr int GTILE_B   = 128 * GSTRIDE_B;   // 10240 per array
constexpr int GBUF_B    = 4 * GTILE_B;       // 40960 per stage
constexpr int GSTAGES   = 3;
constexpr int GEMM_SMEM = GSTAGES * GBUF_B;  // 122880

__global__ __launch_bounds__(256)
void gemm_mma(const __nv_bfloat16* __restrict__ Ahi, const __nv_bfloat16* __restrict__ Alo,
              const __nv_bfloat16* __restrict__ Bhi, const __nv_bfloat16* __restrict__ Blo,
              const float* __restrict__ bias, const float* __restrict__ resid,
              float* __restrict__ Cf,
              __nv_bfloat16* __restrict__ Chi, __nv_bfloat16* __restrict__ Clo,
              int K, int N, int mode) {
    extern __shared__ char smraw[];
    uint32_t sb = smem_to_u32(smraw);
    int t = threadIdx.x, lane = t & 31, wid = t >> 5;
    int bm = blockIdx.y * 128, bn = blockIdx.x * 128;
    int wm = wid & 1, wn = wid >> 1;

    const __nv_bfloat16* gsrc[4] = {
        Ahi + (size_t)bm * K, Alo + (size_t)bm * K,
        Bhi + (size_t)bn * K, Blo + (size_t)bn * K };

    float acc[4][4][4];
    #pragma unroll
    for (int i = 0; i < 4; i++)
        #pragma unroll
        for (int j = 0; j < 4; j++)
            #pragma unroll
            for (int e = 0; e < 4; e++) acc[i][j][e] = 0.f;

    int nch = K >> 5;
    int ldrow = t >> 2, ldseg = t & 3;      // 64 rows per 256-thr pass

    // ---- prologue: stages 0..min(GSTAGES-1, nch-1) ----
    #pragma unroll
    for (int p = 0; p < GSTAGES - 1; p++) {
        if (p < nch) {
            uint32_t base = sb + p * GBUF_B;
            int k0 = p << 5;
            #pragma unroll
            for (int arr = 0; arr < 4; arr++) {
                uint32_t dst = base + arr * GTILE_B;
                #pragma unroll
                for (int f = 0; f < 2; f++) {
                    int row = ldrow + f * 64;
                    cp_async16(dst + row * GSTRIDE_B + ldseg * 16,
                               gsrc[arr] + (size_t)row * K + k0 + ldseg * 8);
                }
            }
        }
        CP_COMMIT();
    }

    for (int c = 0; c < nch; c++) {
        if (c + GSTAGES - 1 < nch) {
            int k0 = (c + GSTAGES - 1) << 5;
            uint32_t base = sb + ((c + GSTAGES - 1) % GSTAGES) * GBUF_B;
            #pragma unroll
            for (int arr = 0; arr < 4; arr++) {
                uint32_t dst = base + arr * GTILE_B;
                #pragma unroll
                for (int f = 0; f < 2; f++) {
                    int row = ldrow + f * 64;
                    cp_async16(dst + row * GSTRIDE_B + ldseg * 16,
                               gsrc[arr] + (size_t)row * K + k0 + ldseg * 8);
                }
            }
            CP_COMMIT();
            asm volatile("cp.async.wait_group %0;" :: "n"(GSTAGES - 1));
        } else {
            asm volatile("cp.async.wait_group 0;");
        }
        __syncthreads();

        uint32_t base = sb + (c % GSTAGES) * GBUF_B;
        uint32_t aHiB = base;
        uint32_t aLoB = base + GTILE_B;
        uint32_t bHiB = base + 2 * GTILE_B;
        uint32_t bLoB = base + 3 * GTILE_B;

        #pragma unroll
        for (int ks = 0; ks < 2; ks++) {
            int k0 = ks * 16;
            int arow = wm * 64 + (lane & 15);
            int acol = k0 + (lane >> 4) * 8;
            int brow = wn * 32 + (lane & 7);
            int bcol = k0 + ((lane >> 3) & 1) * 8;

            uint32_t ah[4][4], bh[4][2], bl[4][2];
            #pragma unroll
            for (int mt = 0; mt < 4; mt++)
                ldsm_x4(ah[mt], aHiB + (arow + mt * 16) * GSTRIDE_B + acol * 2);
            #pragma unroll
            for (int nt = 0; nt < 4; nt++) {
                ldsm_x2(bh[nt], bHiB + (brow + nt * 8) * GSTRIDE_B + bcol * 2);
                ldsm_x2(bl[nt], bLoB + (brow + nt * 8) * GSTRIDE_B + bcol * 2);
            }
            #pragma unroll
            for (int nt = 0; nt < 4; nt++)
                #pragma unroll
                for (int mt = 0; mt < 4; mt++) {
                    mma16816(acc[mt][nt], ah[mt], bh[nt]);
                    mma16816(acc[mt][nt], ah[mt], bl[nt]);
                }
            uint32_t al[4][4];
            #pragma unroll
            for (int mt = 0; mt < 4; mt++)
                ldsm_x4(al[mt], aLoB + (arow + mt * 16) * GSTRIDE_B + acol * 2);
            #pragma unroll
            for (int nt = 0; nt < 4; nt++)
                #pragma unroll
                for (int mt = 0; mt < 4; mt++)
                    mma16816(acc[mt][nt], al[mt], bh[nt]);
        }
        __syncthreads();
    }

    // ---- epilogue ----
    int r = lane >> 2, q2 = (lane & 3) * 2;
    #pragma unroll
    for (int mt = 0; mt < 4; mt++) {
        int row0 = bm + wm * 64 + mt * 16 + r;
        #pragma unroll
        for (int nt = 0; nt < 4; nt++) {
            int col = bn + wn * 32 + nt * 8 + q2;
            float b0 = bias[col], b1 = bias[col + 1];
            float v0 = acc[mt][nt][0] + b0, v1 = acc[mt][nt][1] + b1;
            float v2 = acc[mt][nt][2] + b0, v3 = acc[mt][nt][3] + b1;
            size_t gi0 = (size_t)row0 * N + col;
            size_t gi1 = gi0 + (size_t)8 * N;
            if (mode == 2) {
                float2 r0 = *(const float2*)(resid + gi0);
                float2 r1 = *(const float2*)(resid + gi1);
                *(float2*)(Cf + gi0) = make_float2(v0 + r0.x, v1 + r0.y);
                *(float2*)(Cf + gi1) = make_float2(v2 + r1.x, v3 + r1.y);
            } else {
                if (mode == 1) {
                    v0 = fmaxf(v0, 0.f); v1 = fmaxf(v1, 0.f);
                    v2 = fmaxf(v2, 0.f); v3 = fmaxf(v3, 0.f);
                }
                __nv_bfloat162 h0; h0.x = __float2bfloat16(v0); h0.y = __float2bfloat16(v1);
                __nv_bfloat162 h1; h1.x = __float2bfloat16(v2); h1.y = __float2bfloat16(v3);
                *(__nv_bfloat162*)(Chi + gi0) = h0;
                *(__nv_bfloat162*)(Chi + gi1) = h1;
                __nv_bfloat162 l0, l1;
                l0.x = __float2bfloat16(v0 - __bfloat162float(h0.x));
                l0.y = __float2bfloat16(v1 - __bfloat162float(h0.y));
                l1.x = __float2bfloat16(v2 - __bfloat162float(h1.x));
                l1.y = __float2bfloat16(v3 - __bfloat162float(h1.y));
                *(__nv_bfloat162*)(Clo + gi0) = l0;
                *(__nv_bfloat162*)(Clo + gi1) = l1;
            }
        }
    }
}

// ---------------- HMMA flash attention (pre-split bf16 QKV) ----------------
// CTA: 128 q rows (8 warps x 16), kv tiles of 64, double-buffered cp.async.
constexpr int AST = 144;                       // row stride bytes (64 bf16 + pad)
constexpr int AOFF_QHI = 0;
constexpr int AOFF_QLO = 128 * AST;            // 18432
constexpr int AOFF_KV  = 2 * 128 * AST;        // 36864
constexpr int KV_STAGE = 4 * 64 * AST;         // 36864 (Khi,Klo,Vhi,Vlo)
constexpr int ATTN_SMEM = AOFF_KV + 2 * KV_STAGE;  // 110592

__device__ __forceinline__ void cp_kv_tile(uint32_t base,
        const __nv_bfloat16* khi, const __nv_bfloat16* klo,
        const __nv_bfloat16* vhi, const __nv_bfloat16* vlo, int t) {
    #pragma unroll
    for (int f = 0; f < 2; f++) {
        int idx = t + f * 256;
        int row = idx >> 3, seg = idx & 7;
        uint32_t o = row * AST + seg * 16;
        size_t go = (size_t)row * QKV_LD + seg * 8;
        cp_async16(base + o,                khi + go);
        cp_async16(base + 64 * AST + o,     klo + go);
        cp_async16(base + 2 * 64 * AST + o, vhi + go);
        cp_async16(base + 3 * 64 * AST + o, vlo + go);
    }
}

__global__ __launch_bounds__(256)
void attn_mma(const __nv_bfloat16* __restrict__ qkv_hi,
              const __nv_bfloat16* __restrict__ qkv_lo,
              const float* __restrict__ x,
              float* __restrict__ xo) {
    extern __shared__ char smraw[];
    uint32_t sb = smem_to_u32(smraw);
    int qt = blockIdx.x, h = blockIdx.y, b = blockIdx.z;
    int t = threadIdx.x, lane = t & 31, wid = t >> 5;

    const __nv_bfloat16* qhi = qkv_hi + (size_t)(b * S_ + qt * 128) * QKV_LD + h * 64;
    const __nv_bfloat16* qlo = qkv_lo + (size_t)(b * S_ + qt * 128) * QKV_LD + h * 64;
    const __nv_bfloat16* khi0 = qkv_hi + (size_t)(b * S_) * QKV_LD + 1024 + h * 64;
    const __nv_bfloat16* klo0 = qkv_lo + (size_t)(b * S_) * QKV_LD + 1024 + h * 64;
    const __nv_bfloat16* vhi0 = khi0 + 1024;
    const __nv_bfloat16* vlo0 = klo0 + 1024;

    // ---- prologue: Q tile (128 rows hi+lo) + KV tile 0, one group ----
    #pragma unroll
    for (int f = 0; f < 4; f++) {
        int idx = t + f * 256;
        int row = idx >> 3, seg = idx & 7;
        uint32_t o = row * AST + seg * 16;
        size_t go = (size_t)row * QKV_LD + seg * 8;
        cp_async16(sb + AOFF_QHI + o, qhi + go);
        cp_async16(sb + AOFF_QLO + o, qlo + go);
    }
    cp_kv_tile(sb + AOFF_KV, khi0, klo0, vhi0, vlo0, t);
    CP_COMMIT();

    float o[8][4];
    #pragma unroll
    for (int i = 0; i < 8; i++)
        #pragma unroll
        for (int j = 0; j < 4; j++) o[i][j] = 0.f;
    float m0 = -INFINITY, m1 = -INFINITY, l0 = 0.f, l1 = 0.f;

    int r = lane >> 2, q2 = (lane & 3) * 2;
    int grow0 = qt * 128 + wid * 16 + r;
    int grow1 = grow0 + 8;

    int nkt = 2 * qt + 2;
    for (int kt = 0; kt < nkt; kt++) {
        if (kt + 1 < nkt) {
            size_t koff = (size_t)((kt + 1) * 64) * QKV_LD;
            cp_kv_tile(sb + AOFF_KV + ((kt + 1) & 1) * KV_STAGE,
                       khi0 + koff, klo0 + koff, vhi0 + koff, vlo0 + koff, t);
            CP_COMMIT();
            asm volatile("cp.async.wait_group 1;");
        } else {
            asm volatile("cp.async.wait_group 0;");
        }
        __syncthreads();

        uint32_t kvb = sb + AOFF_KV + (kt & 1) * KV_STAGE;
        uint32_t kHiB = kvb, kLoB = kvb + 64 * AST;
        uint32_t vHiB = kvb + 2 * 64 * AST, vLoB = kvb + 3 * 64 * AST;

        // ---- scores S = Q K^T (3 passes) ----
        float s[8][4];
        #pragma unroll
        for (int i = 0; i < 8; i++)
            #pragma unroll
            for (int j = 0; j < 4; j++) s[i][j] = 0.f;

        int arow = wid * 16 + (lane & 15);
        int brow = lane & 7;
        #pragma unroll
        for (int ksIdx = 0; ksIdx < 4; ksIdx++) {
            int k0 = ksIdx * 16;
            int acol = k0 + (lane >> 4) * 8;
            int bcol = k0 + ((lane >> 3) & 1) * 8;
            uint32_t qh[4], ql[4];
            ldsm_x4(qh, sb + AOFF_QHI + arow * AST + acol * 2);
            ldsm_x4(ql, sb + AOFF_QLO + arow * AST + acol * 2);
            #pragma unroll
            for (int nt = 0; nt < 8; nt++) {
                uint32_t kh[2], kl[2];
                ldsm_x2(kh, kHiB + (nt * 8 + brow) * AST + bcol * 2);
                ldsm_x2(kl, kLoB + (nt * 8 + brow) * AST + bcol * 2);
                mma16816(s[nt], qh, kh);
                mma16816(s[nt], ql, kh);
                mma16816(s[nt], qh, kl);
            }
        }

        // ---- causal mask (diagonal tiles only) ----
        if (kt >= 2 * qt) {
            #pragma unroll
            for (int nt = 0; nt < 8; nt++) {
                int gc = kt * 64 + nt * 8 + q2;
                if (gc > grow0)     s[nt][0] = -INFINITY;
                if (gc + 1 > grow0) s[nt][1] = -INFINITY;
                if (gc > grow1)     s[nt][2] = -INFINITY;
                if (gc + 1 > grow1) s[nt][3] = -INFINITY;
            }
        }

        // ---- online softmax ----
        float mx0 = -INFINITY, mx1 = -INFINITY;
        #pragma unroll
        for (int nt = 0; nt < 8; nt++) {
            mx0 = fmaxf(mx0, fmaxf(s[nt][0], s[nt][1]));
            mx1 = fmaxf(mx1, fmaxf(s[nt][2], s[nt][3]));
        }
        mx0 = fmaxf(mx0, __shfl_xor_sync(0xffffffffu, mx0, 1));
        mx0 = fmaxf(mx0, __shfl_xor_sync(0xffffffffu, mx0, 2));
        mx1 = fmaxf(mx1, __shfl_xor_sync(0xffffffffu, mx1, 1));
        mx1 = fmaxf(mx1, __shfl_xor_sync(0xffffffffu, mx1, 2));
        float mn0 = fmaxf(m0, mx0), mn1 = fmaxf(m1, mx1);
        float c0 = __expf(m0 - mn0), c1 = __expf(m1 - mn1);
        float ps0 = 0.f, ps1 = 0.f;
        #pragma unroll
        for (int nt = 0; nt < 8; nt++) {
            s[nt][0] = __expf(s[nt][0] - mn0);
            s[nt][1] = __expf(s[nt][1] - mn0);
            s[nt][2] = __expf(s[nt][2] - mn1);
            s[nt][3] = __expf(s[nt][3] - mn1);
            ps0 += s[nt][0] + s[nt][1];
            ps1 += s[nt][2] + s[nt][3];
        }
        ps0 += __shfl_xor_sync(0xffffffffu, ps0, 1);
        ps0 += __shfl_xor_sync(0xffffffffu, ps0, 2);
        ps1 += __shfl_xor_sync(0xffffffffu, ps1, 1);
        ps1 += __shfl_xor_sync(0xffffffffu, ps1, 2);
        l0 = l0 * c0 + ps0;
        l1 = l1 * c1 + ps1;
        m0 = mn0; m1 = mn1;
        #pragma unroll
        for (int dt = 0; dt < 8; dt++) {
            o[dt][0] *= c0; o[dt][1] *= c0;
            o[dt][2] *= c1; o[dt][3] *= c1;
        }

        // ---- O += P @ V (P in regs; V hi/lo via ldmatrix.trans) ----
        #pragma unroll
        for (int ksIdx = 0; ksIdx < 4; ksIdx++) {
            uint32_t a[4];
            a[0] = packbf2(s[2*ksIdx][0],   s[2*ksIdx][1]);
            a[1] = packbf2(s[2*ksIdx][2],   s[2*ksIdx][3]);
            a[2] = packbf2(s[2*ksIdx+1][0], s[2*ksIdx+1][1]);
            a[3] = packbf2(s[2*ksIdx+1][2], s[2*ksIdx+1][3]);
            int vrow = ksIdx * 16 + (lane & 15);
            #pragma unroll
            for (int dt = 0; dt < 8; dt++) {
                uint32_t vh[2], vl[2];
                ldsm_x2t(vh, vHiB + vrow * AST + dt * 16);
                ldsm_x2t(vl, vLoB + vrow * AST + dt * 16);
                mma16816(o[dt], a, vh);
                mma16816(o[dt], a, vl);
            }
        }
        __syncthreads();   // reads done before next prefetch overwrites
    }

    // ---- epilogue: o/l + residual ----
    float il0 = 1.f / l0, il1 = 1.f / l1;
    int row0 = b * S_ + qt * 128 + wid * 16 + r;
    int row1 = row0 + 8;
    #pragma unroll
    for (int dt = 0; dt < 8; dt++) {
        int col = h * 64 + dt * 8 + q2;
        size_t gi0 = (size_t)row0 * E_ + col;
        size_t gi1 = (size_t)row1 * E_ + col;
        float2 x0 = *(const float2*)(x + gi0);
        float2 x1 = *(const float2*)(x + gi1);
        *(float2*)(xo + gi0) = make_float2(x0.x + o[dt][0] * il0,
                                           x0.y + o[dt][1] * il0);
        *(float2*)(xo + gi1) = make_float2(x1.x + o[dt][2] * il1,
                                           x1.y + o[dt][3] * il1);
    }
}

// ---------------- launcher -------------------------------------------------
extern "C" void kernel_launch(void* const* d_in, const int* in_sizes, int n_in,
                              void* d_out, int out_size) {
    const float* emb   = (const float*)d_in[0];
    const float* Wq    = (const float*)d_in[1];
    const float* bq    = (const float*)d_in[2];
    const float* Wk    = (const float*)d_in[3];
    const float* bk    = (const float*)d_in[4];
    const float* Wv    = (const float*)d_in[5];
    const float* bv    = (const float*)d_in[6];
    const float* ln1_w = (const float*)d_in[7];
    const float* ln1_b = (const float*)d_in[8];
    const float* ln2_w = (const float*)d_in[9];
    const float* ln2_b = (const float*)d_in[10];
    const float* W1    = (const float*)d_in[11];
    const float* b1    = (const float*)d_in[12];
    const float* W2    = (const float*)d_in[13];
    const float* b2    = (const float*)d_in[14];
    float* out = (float*)d_out;

    float *px, *pxo, *py, *pbcat;
    __nv_bfloat16 *pqh, *pql, *pxhi, *pxlo, *pyhi, *pylo, *phhi, *phlo;
    __nv_bfloat16 *pwqh, *pwql, *pw1h, *pw1l, *pw2h, *pw2l;
    cudaGetSymbolAddress((void**)&px,   g_x);
    cudaGetSymbolAddress((void**)&pxo,  g_xo);
    cudaGetSymbolAddress((void**)&py,   g_y);
    cudaGetSymbolAddress((void**)&pbcat,g_bcat);
    cudaGetSymbolAddress((void**)&pqh,  g_qkv_hi);
    cudaGetSymbolAddress((void**)&pql,  g_qkv_lo);
    cudaGetSymbolAddress((void**)&pxhi, g_xhi);
    cudaGetSymbolAddress((void**)&pxlo, g_xlo);
    cudaGetSymbolAddress((void**)&pyhi, g_yhi);
    cudaGetSymbolAddress((void**)&pylo, g_ylo);
    cudaGetSymbolAddress((void**)&phhi, g_hhi);
    cudaGetSymbolAddress((void**)&phlo, g_hlo);
    cudaGetSymbolAddress((void**)&pwqh, g_wqkv_hi);
    cudaGetSymbolAddress((void**)&pwql, g_wqkv_lo);
    cudaGetSymbolAddress((void**)&pw1h, g_w1t_hi);
    cudaGetSymbolAddress((void**)&pw1l, g_w1t_lo);
    cudaGetSymbolAddress((void**)&pw2h, g_w2t_hi);
    cudaGetSymbolAddress((void**)&pw2l, g_w2t_lo);

    cudaFuncSetAttribute(gemm_mma,
                         cudaFuncAttributeMaxDynamicSharedMemorySize, GEMM_SMEM);
    cudaFuncSetAttribute(attn_mma,
                         cudaFuncAttributeMaxDynamicSharedMemorySize, ATTN_SMEM);

    dim3 tb(32, 8);
    // 1/sqrt(DK) folded into Wq (scale=0.125)
    transpose_cvt<<<dim3(2, 32, 16), tb>>>(Wq, pwqh,           pwql,           E_, DK_, (long)E_*DK_, (long)DK_*E_, 0.125f);
    transpose_cvt<<<dim3(2, 32, 16), tb>>>(Wk, pwqh + 1024*E_, pwql + 1024*E_, E_, DK_, (long)E_*DK_, (long)DK_*E_, 1.f);
    transpose_cvt<<<dim3(2, 32, 16), tb>>>(Wv, pwqh + 2048*E_, pwql + 2048*E_, E_, DK_, (long)E_*DK_, (long)DK_*E_, 1.f);
    transpose_cvt<<<dim3(HID_/32, E_/32, 1), tb>>>(W1, pw1h, pw1l, E_, HID_, 0, 0, 1.f);
    transpose_cvt<<<dim3(E_/32, HID_/32, 1), tb>>>(W2, pw2h, pw2l, HID_, E_, 0, 0, 1.f);
    bias_cat_kernel<<<NQKV_/256, 256>>>(bq, bk, bv, pbcat);

    // LN1 -> x fp32 + hi/lo
    ln_kernel<<<M_, 256>>>(emb, ln1_w, ln1_b, px, pxhi, pxlo);

    // fused QKV (scaled q) -> bf16 hi/lo directly
    gemm_mma<<<dim3(NQKV_/128, M_/128), 256, GEMM_SMEM>>>(
        pxhi, pxlo, pwqh, pwql, pbcat, nullptr, nullptr, pqh, pql,
        E_, NQKV_, 3);

    // attention + residual -> g_xo
    attn_mma<<<dim3(S_/128, H_, B_), 256, ATTN_SMEM>>>(pqh, pql, px, pxo);

    // LN2 -> y fp32 + hi/lo
    ln_kernel<<<M_, 256>>>(pxo, ln2_w, ln2_b, py, pyhi, pylo);

    // FFN1: h = relu(y @ W1 + b1) -> bf16 hi/lo
    gemm_mma<<<dim3(HID_/128, M_/128), 256, GEMM_SMEM>>>(
        pyhi, pylo, pw1h, pw1l, b1, nullptr, nullptr, phhi, phlo,
        E_, HID_, 1);

    // FFN2: out = y + h @ W2 + b2
    gemm_mma<<<dim3(E_/128, M_/128), 256, GEMM_SMEM>>>(
        phhi, phlo, pw2h, pw2l, b2, py, out, nullptr, nullptr,
        HID_, E_, 2);
}

// round 5
// speedup vs baseline: 1.0146x; 1.0146x over previous
#include <cuda_runtime.h>
#include <cuda_bf16.h>
#include <cstdint>
#include <math.h>

// ---------------- problem constants ----------------
constexpr int B_  = 2;
constexpr int S_  = 2048;
constexpr int E_  = 1024;
constexpr int H_  = 16;
constexpr int DK_ = 64;
constexpr int HID_= 4096;
constexpr int M_  = B_ * S_;       // 4096 rows
constexpr int NQKV_ = 3 * E_;      // 3072 fused qkv output cols
constexpr int QKV_LD = NQKV_;

// ================= PTX helpers (base sm_103: mma.sync/ldmatrix/cp.async) ==
__device__ __forceinline__ uint32_t smem_to_u32(const void* p) {
    uint32_t a;
    asm("{ .reg .u64 t; cvta.to.shared.u64 t, %1; cvt.u32.u64 %0, t; }"
        : "=r"(a) : "l"(p));
    return a;
}
__device__ __forceinline__ void mma16816(float* d, const uint32_t* a, const uint32_t* b) {
    asm volatile("mma.sync.aligned.m16n8k16.row.col.f32.bf16.bf16.f32 "
        "{%0,%1,%2,%3}, {%4,%5,%6,%7}, {%8,%9}, {%0,%1,%2,%3};"
        : "+f"(d[0]), "+f"(d[1]), "+f"(d[2]), "+f"(d[3])
        : "r"(a[0]), "r"(a[1]), "r"(a[2]), "r"(a[3]), "r"(b[0]), "r"(b[1]));
}
__device__ __forceinline__ void ldsm_x4(uint32_t* r, uint32_t addr) {
    asm volatile("ldmatrix.sync.aligned.m8n8.x4.shared.b16 {%0,%1,%2,%3}, [%4];"
        : "=r"(r[0]), "=r"(r[1]), "=r"(r[2]), "=r"(r[3]) : "r"(addr));
}
__device__ __forceinline__ void ldsm_x2(uint32_t* r, uint32_t addr) {
    asm volatile("ldmatrix.sync.aligned.m8n8.x2.shared.b16 {%0,%1}, [%2];"
        : "=r"(r[0]), "=r"(r[1]) : "r"(addr));
}
__device__ __forceinline__ void ldsm_x2t(uint32_t* r, uint32_t addr) {
    asm volatile("ldmatrix.sync.aligned.m8n8.x2.trans.shared.b16 {%0,%1}, [%2];"
        : "=r"(r[0]), "=r"(r[1]) : "r"(addr));
}
__device__ __forceinline__ void cp_async16(uint32_t dst, const void* src) {
    asm volatile("cp.async.cg.shared.global [%0], [%1], 16;" :: "r"(dst), "l"(src));
}
#define CP_COMMIT() asm volatile("cp.async.commit_group;")
__device__ __forceinline__ uint32_t packbf2(float a, float b) {
    __nv_bfloat162 h = __floats2bfloat162_rn(a, b);
    return *(uint32_t*)&h;
}

// ---------------- scratch (device globals) --------------------------------
__device__ __align__(16) float g_x  [M_ * E_];
__device__ __align__(16) float g_xo [M_ * E_];
__device__ __align__(16) float g_y  [M_ * E_];
__device__ __align__(16) __nv_bfloat16 g_qkv_hi[M_ * NQKV_], g_qkv_lo[M_ * NQKV_];
__device__ __align__(16) __nv_bfloat16 g_xhi[M_ * E_],  g_xlo[M_ * E_];
__device__ __align__(16) __nv_bfloat16 g_yhi[M_ * E_],  g_ylo[M_ * E_];
__device__ __align__(16) __nv_bfloat16 g_hhi[M_ * HID_], g_hlo[M_ * HID_];
__device__ __align__(16) __nv_bfloat16 g_wqkv_hi[NQKV_ * E_], g_wqkv_lo[NQKV_ * E_];
__device__ __align__(16) __nv_bfloat16 g_w1t_hi[HID_ * E_],   g_w1t_lo[HID_ * E_];
__device__ __align__(16) __nv_bfloat16 g_w2t_hi[E_ * HID_],   g_w2t_lo[E_ * HID_];
__device__ float g_bcat[NQKV_];

// ---------------- merged prep: all weight transposes + bias concat ---------
// block id ranges: [0,3072) Wq/Wk/Wv | [3072,7168) W1 | [7168,11264) W2
//                  [11264,11276) bias concat
__device__ __forceinline__ void transpose_tile(
        const float* __restrict__ in, __nv_bfloat16* __restrict__ ohi,
        __nv_bfloat16* __restrict__ olo, int R, int C,
        int c0, int r0, float scale, int tx, int ty) {
    __shared__ float tile[32][33];
    #pragma unroll
    for (int j = 0; j < 4; j++)
        tile[ty + j * 8][tx] = in[(size_t)(r0 + ty + j * 8) * C + c0 + tx];
    __syncthreads();
    #pragma unroll
    for (int j = 0; j < 4; j++) {
        float v = tile[tx][ty + j * 8] * scale;
        __nv_bfloat16 hi = __float2bfloat16(v);
        float lo = v - __bfloat162float(hi);
        size_t o = (size_t)(c0 + ty + j * 8) * R + r0 + tx;
        ohi[o] = hi;
        olo[o] = __float2bfloat16(lo);
    }
}

__global__ void prep_kernel(const float* __restrict__ Wq, const float* __restrict__ Wk,
                            const float* __restrict__ Wv, const float* __restrict__ W1,
                            const float* __restrict__ W2,
                            const float* __restrict__ bq, const float* __restrict__ bk,
                            const float* __restrict__ bv,
                            __nv_bfloat16* __restrict__ wqkv_hi,
                            __nv_bfloat16* __restrict__ wqkv_lo,
                            __nv_bfloat16* __restrict__ w1h, __nv_bfloat16* __restrict__ w1l,
                            __nv_bfloat16* __restrict__ w2h, __nv_bfloat16* __restrict__ w2l,
                            float* __restrict__ bcat) {
    int id = blockIdx.x;
    int tx = threadIdx.x, ty = threadIdx.y;
    if (id < 3072) {
        int which = id >> 10;                  // 0=q,1=k,2=v
        int local = id & 1023;
        int z = local >> 6;                    // head
        int rem = local & 63;
        int cx = rem & 1, ry = rem >> 1;
        const float* src = (which == 0) ? Wq : (which == 1) ? Wk : Wv;
        float scale = (which == 0) ? 0.125f : 1.f;
        transpose_tile(src + (size_t)z * E_ * DK_,
                       wqkv_hi + (size_t)which * 1024 * E_ + (size_t)z * DK_ * E_,
                       wqkv_lo + (size_t)which * 1024 * E_ + (size_t)z * DK_ * E_,
                       E_, DK_, cx * 32, ry * 32, scale, tx, ty);
    } else if (id < 7168) {
        int local = id - 3072;
        int cx = local & 127, ry = local >> 7;
        transpose_tile(W1, w1h, w1l, E_, HID_, cx * 32, ry * 32, 1.f, tx, ty);
    } else if (id < 11264) {
        int local = id - 7168;
        int cx = local & 31, ry = local >> 5;
        transpose_tile(W2, w2h, w2l, HID_, E_, cx * 32, ry * 32, 1.f, tx, ty);
    } else {
        int n = (id - 11264) * 256 + ty * 32 + tx;
        const float* src = (n < 1024) ? bq : ((n < 2048) ? bk : bv);
        float sc = (n < 1024) ? 0.125f : 1.f;
        bcat[n] = src[n & 1023] * sc;
    }
}

// ---------------- LayerNorm: fp32 out + bf16 hi/lo out ---------------------
__global__ void ln_kernel(const float* __restrict__ in,
                          const float* __restrict__ w,
                          const float* __restrict__ b,
                          float* __restrict__ out,
                          __nv_bfloat16* __restrict__ ohi,
                          __nv_bfloat16* __restrict__ olo) {
    int row = blockIdx.x;
    int t = threadIdx.x;
    const float4* ip = (const float4*)(in + (size_t)row * E_);
    float4 v = ip[t];
    float s  = v.x + v.y + v.z + v.w;
    float sq = v.x*v.x + v.y*v.y + v.z*v.z + v.w*v.w;
    #pragma unroll
    for (int o = 16; o; o >>= 1) {
        s  += __shfl_xor_sync(0xffffffffu, s,  o);
        sq += __shfl_xor_sync(0xffffffffu, sq, o);
    }
    __shared__ float ss[8], ssq[8];
    __shared__ float mu_s, inv_s;
    if ((t & 31) == 0) { ss[t >> 5] = s; ssq[t >> 5] = sq; }
    __syncthreads();
    if (t < 32) {
        float s2  = (t < 8) ? ss[t]  : 0.f;
        float sq2 = (t < 8) ? ssq[t] : 0.f;
        #pragma unroll
        for (int o = 4; o; o >>= 1) {
            s2  += __shfl_xor_sync(0xffffffffu, s2,  o);
            sq2 += __shfl_xor_sync(0xffffffffu, sq2, o);
        }
        if (t == 0) {
            float mu  = s2 * (1.f / E_);
            float var = sq2 * (1.f / E_) - mu * mu;
            mu_s  = mu;
            inv_s = rsqrtf(var + 1e-5f);
        }
    }
    __syncthreads();
    float mu = mu_s, inv = inv_s;
    float4 wv = ((const float4*)w)[t];
    float4 bv = ((const float4*)b)[t];
    float4 o4;
    o4.x = (v.x - mu) * inv * wv.x + bv.x;
    o4.y = (v.y - mu) * inv * wv.y + bv.y;
    o4.z = (v.z - mu) * inv * wv.z + bv.z;
    o4.w = (v.w - mu) * inv * wv.w + bv.w;
    ((float4*)(out + (size_t)row * E_))[t] = o4;
    __nv_bfloat16 h0 = __float2bfloat16(o4.x), h1 = __float2bfloat16(o4.y);
    __nv_bfloat16 h2 = __float2bfloat16(o4.z), h3 = __float2bfloat16(o4.w);
    __nv_bfloat162 hp0; hp0.x = h0; hp0.y = h1;
    __nv_bfloat162 hp1; hp1.x = h2; hp1.y = h3;
    ((__nv_bfloat162*)(ohi + (size_t)row * E_))[2*t]   = hp0;
    ((__nv_bfloat162*)(ohi + (size_t)row * E_))[2*t+1] = hp1;
    __nv_bfloat162 lp0, lp1;
    lp0.x = __float2bfloat16(o4.x - __bfloat162float(h0));
    lp0.y = __float2bfloat16(o4.y - __bfloat162float(h1));
    lp1.x = __float2bfloat16(o4.z - __bfloat162float(h2));
    lp1.y = __float2bfloat16(o4.w - __bfloat162float(h3));
    ((__nv_bfloat162*)(olo + (size_t)row * E_))[2*t]   = lp0;
    ((__nv_bfloat162*)(olo + (size_t)row * E_))[2*t+1] = lp1;
}

// ---------------- HMMA GEMM: C[M,N] = (Ahi+Alo) @ (Bhi+Blo)^T --------------
// CTA tile 128x128, 8 warps of 64x32, K chunk 32, 2-stage cp.async pipeline.
// mode 1: relu -> Chi/Clo | mode 2: fp32 + bias + resid | mode 3: Chi/Clo + bias
constexpr int GSTRIDE_B = 80;                // bytes per smem row (40 bf16)
constexpr int GTILE_B   = 128 * GSTRIDE_B;   // 10240 per array
constexpr int GBUF_B    = 4 * GTILE_B;       // 40960 per stage
constexpr int GSTAGES   = 2;
constexpr int GEMM_SMEM = GSTAGES * GBUF_B;  // 81920 -> 2 CTAs/SM

__global__ __launch_bounds__(256)
void gemm_mma(const __nv_bfloat16* __restrict__ Ahi, const __nv_bfloat16* __restrict__ Alo,
              const __nv_bfloat16* __restrict__ Bhi, const __nv_bfloat16* __restrict__ Blo,
              const float* __restrict__ bias, const float* __restrict__ resid,
              float* __restrict__ Cf,
              __nv_bfloat16* __restrict__ Chi, __nv_bfloat16* __restrict__ Clo,
              int K, int N, int mode) {
    extern __shared__ char smraw[];
    uint32_t sb = smem_to_u32(smraw);
    int t = threadIdx.x, lane = t & 31, wid = t >> 5;
    int bm = blockIdx.y * 128, bn = blockIdx.x * 128;
    int wm = wid & 1, wn = wid >> 1;

    const __nv_bfloat16* gsrc[4] = {
        Ahi + (size_t)bm * K, Alo + (size_t)bm * K,
        Bhi + (size_t)bn * K, Blo + (size_t)bn * K };

    float acc[4][4][4];
    #pragma unroll
    for (int i = 0; i < 4; i++)
        #pragma unroll
        for (int j = 0; j < 4; j++)
            #pragma unroll
            for (int e = 0; e < 4; e++) acc[i][j][e] = 0.f;

    int nch = K >> 5;
    int ldrow = t >> 2, ldseg = t & 3;      // 64 rows per 256-thr pass

    // ---- prologue: stage 0 ----
    {
        uint32_t base = sb;
        #pragma unroll
        for (int arr = 0; arr < 4; arr++) {
            uint32_t dst = base + arr * GTILE_B;
            #pragma unroll
            for (int f = 0; f < 2; f++) {
                int row = ldrow + f * 64;
                cp_async16(dst + row * GSTRIDE_B + ldseg * 16,
                           gsrc[arr] + (size_t)row * K + ldseg * 8);
            }
        }
        CP_COMMIT();
    }

    for (int c = 0; c < nch; c++) {
        if (c + 1 < nch) {
            int k0 = (c + 1) << 5;
            uint32_t base = sb + ((c + 1) & 1) * GBUF_B;
            #pragma unroll
            for (int arr = 0; arr < 4; arr++) {
                uint32_t dst = base + arr * GTILE_B;
                #pragma unroll
                for (int f = 0; f < 2; f++) {
                    int row = ldrow + f * 64;
                    cp_async16(dst + row * GSTRIDE_B + ldseg * 16,
                               gsrc[arr] + (size_t)row * K + k0 + ldseg * 8);
                }
            }
            CP_COMMIT();
            asm volatile("cp.async.wait_group 1;");
        } else {
            asm volatile("cp.async.wait_group 0;");
        }
        __syncthreads();

        uint32_t base = sb + (c & 1) * GBUF_B;
        uint32_t aHiB = base;
        uint32_t aLoB = base + GTILE_B;
        uint32_t bHiB = base + 2 * GTILE_B;
        uint32_t bLoB = base + 3 * GTILE_B;

        #pragma unroll
        for (int ks = 0; ks < 2; ks++) {
            int k0 = ks * 16;
            int arow = wm * 64 + (lane & 15);
            int acol = k0 + (lane >> 4) * 8;
            int brow = wn * 32 + (lane & 7);
            int bcol = k0 + ((lane >> 3) & 1) * 8;

            uint32_t ah[4][4], bh[4][2], bl[4][2];
            #pragma unroll
            for (int mt = 0; mt < 4; mt++)
                ldsm_x4(ah[mt], aHiB + (arow + mt * 16) * GSTRIDE_B + acol * 2);
            #pragma unroll
            for (int nt = 0; nt < 4; nt++) {
                ldsm_x2(bh[nt], bHiB + (brow + nt * 8) * GSTRIDE_B + bcol * 2);
                ldsm_x2(bl[nt], bLoB + (brow + nt * 8) * GSTRIDE_B + bcol * 2);
            }
            #pragma unroll
            for (int nt = 0; nt < 4; nt++)
                #pragma unroll
                for (int mt = 0; mt < 4; mt++) {
                    mma16816(acc[mt][nt], ah[mt], bh[nt]);
                    mma16816(acc[mt][nt], ah[mt], bl[nt]);
                }
            uint32_t al[4][4];
            #pragma unroll
            for (int mt = 0; mt < 4; mt++)
                ldsm_x4(al[mt], aLoB + (arow + mt * 16) * GSTRIDE_B + acol * 2);
            #pragma unroll
            for (int nt = 0; nt < 4; nt++)
                #pragma unroll
                for (int mt = 0; mt < 4; mt++)
                    mma16816(acc[mt][nt], al[mt], bh[nt]);
        }
        __syncthreads();
    }

    // ---- epilogue ----
    int r = lane >> 2, q2 = (lane & 3) * 2;
    #pragma unroll
    for (int mt = 0; mt < 4; mt++) {
        int row0 = bm + wm * 64 + mt * 16 + r;
        #pragma unroll
        for (int nt = 0; nt < 4; nt++) {
            int col = bn + wn * 32 + nt * 8 + q2;
            float b0 = bias[col], b1 = bias[col + 1];
            float v0 = acc[mt][nt][0] + b0, v1 = acc[mt][nt][1] + b1;
            float v2 = acc[mt][nt][2] + b0, v3 = acc[mt][nt][3] + b1;
            size_t gi0 = (size_t)row0 * N + col;
            size_t gi1 = gi0 + (size_t)8 * N;
            if (mode == 2) {
                float2 r0 = *(const float2*)(resid + gi0);
                float2 r1 = *(const float2*)(resid + gi1);
                *(float2*)(Cf + gi0) = make_float2(v0 + r0.x, v1 + r0.y);
                *(float2*)(Cf + gi1) = make_float2(v2 + r1.x, v3 + r1.y);
            } else {
                if (mode == 1) {
                    v0 = fmaxf(v0, 0.f); v1 = fmaxf(v1, 0.f);
                    v2 = fmaxf(v2, 0.f); v3 = fmaxf(v3, 0.f);
                }
                __nv_bfloat162 h0; h0.x = __float2bfloat16(v0); h0.y = __float2bfloat16(v1);
                __nv_bfloat162 h1; h1.x = __float2bfloat16(v2); h1.y = __float2bfloat16(v3);
                *(__nv_bfloat162*)(Chi + gi0) = h0;
                *(__nv_bfloat162*)(Chi + gi1) = h1;
                __nv_bfloat162 l0, l1;
                l0.x = __float2bfloat16(v0 - __bfloat162float(h0.x));
                l0.y = __float2bfloat16(v1 - __bfloat162float(h0.y));
                l1.x = __float2bfloat16(v2 - __bfloat162float(h1.x));
                l1.y = __float2bfloat16(v3 - __bfloat162float(h1.y));
                *(__nv_bfloat162*)(Clo + gi0) = l0;
                *(__nv_bfloat162*)(Clo + gi1) = l1;
            }
        }
    }
}

// ---------------- HMMA flash attention (pre-split bf16 QKV) ----------------
// CTA: 128 q rows (8 warps x 16), kv tiles of 64, double-buffered cp.async.
// qt reversed (heaviest CTAs launch first) for causal load balance.
constexpr int AST = 144;                       // row stride bytes (64 bf16 + pad)
constexpr int AOFF_QHI = 0;
constexpr int AOFF_QLO = 128 * AST;            // 18432
constexpr int AOFF_KV  = 2 * 128 * AST;        // 36864
constexpr int KV_STAGE = 4 * 64 * AST;         // 36864 (Khi,Klo,Vhi,Vlo)
constexpr int ATTN_SMEM = AOFF_KV + 2 * KV_STAGE;  // 110592

__device__ __forceinline__ void cp_kv_tile(uint32_t base,
        const __nv_bfloat16* khi, const __nv_bfloat16* klo,
        const __nv_bfloat16* vhi, const __nv_bfloat16* vlo, int t) {
    #pragma unroll
    for (int f = 0; f < 2; f++) {
        int idx = t + f * 256;
        int row = idx >> 3, seg = idx & 7;
        uint32_t o = row * AST + seg * 16;
        size_t go = (size_t)row * QKV_LD + seg * 8;
        cp_async16(base + o,                khi + go);
        cp_async16(base + 64 * AST + o,     klo + go);
        cp_async16(base + 2 * 64 * AST + o, vhi + go);
        cp_async16(base + 3 * 64 * AST + o, vlo + go);
    }
}

__global__ __launch_bounds__(256)
void attn_mma(const __nv_bfloat16* __restrict__ qkv_hi,
              const __nv_bfloat16* __restrict__ qkv_lo,
              const float* __restrict__ x,
              float* __restrict__ xo) {
    extern __shared__ char smraw[];
    uint32_t sb = smem_to_u32(smraw);
    int qt = gridDim.x - 1 - blockIdx.x;       // heavy tiles first
    int h = blockIdx.y, b = blockIdx.z;
    int t = threadIdx.x, lane = t & 31, wid = t >> 5;

    const __nv_bfloat16* qhi = qkv_hi + (size_t)(b * S_ + qt * 128) * QKV_LD + h * 64;
    const __nv_bfloat16* qlo = qkv_lo + (size_t)(b * S_ + qt * 128) * QKV_LD + h * 64;
    const __nv_bfloat16* khi0 = qkv_hi + (size_t)(b * S_) * QKV_LD + 1024 + h * 64;
    const __nv_bfloat16* klo0 = qkv_lo + (size_t)(b * S_) * QKV_LD + 1024 + h * 64;
    const __nv_bfloat16* vhi0 = khi0 + 1024;
    const __nv_bfloat16* vlo0 = klo0 + 1024;

    // ---- prologue: Q tile (128 rows hi+lo) + KV tile 0 ----
    #pragma unroll
    for (int f = 0; f < 4; f++) {
        int idx = t + f * 256;
        int row = idx >> 3, seg = idx & 7;
        uint32_t o = row * AST + seg * 16;
        size_t go = (size_t)row * QKV_LD + seg * 8;
        cp_async16(sb + AOFF_QHI + o, qhi + go);
        cp_async16(sb + AOFF_QLO + o, qlo + go);
    }
    cp_kv_tile(sb + AOFF_KV, khi0, klo0, vhi0, vlo0, t);
    CP_COMMIT();

    float o[8][4];
    #pragma unroll
    for (int i = 0; i < 8; i++)
        #pragma unroll
        for (int j = 0; j < 4; j++) o[i][j] = 0.f;
    float m0 = -INFINITY, m1 = -INFINITY, l0 = 0.f, l1 = 0.f;

    int r = lane >> 2, q2 = (lane & 3) * 2;
    int grow0 = qt * 128 + wid * 16 + r;
    int grow1 = grow0 + 8;

    int nkt = 2 * qt + 2;
    for (int kt = 0; kt < nkt; kt++) {
        if (kt + 1 < nkt) {
            size_t koff = (size_t)((kt + 1) * 64) * QKV_LD;
            cp_kv_tile(sb + AOFF_KV + ((kt + 1) & 1) * KV_STAGE,
                       khi0 + koff, klo0 + koff, vhi0 + koff, vlo0 + koff, t);
            CP_COMMIT();
            asm volatile("cp.async.wait_group 1;");
        } else {
            asm volatile("cp.async.wait_group 0;");
        }
        __syncthreads();

        uint32_t kvb = sb + AOFF_KV + (kt & 1) * KV_STAGE;
        uint32_t kHiB = kvb, kLoB = kvb + 64 * AST;
        uint32_t vHiB = kvb + 2 * 64 * AST, vLoB = kvb + 3 * 64 * AST;

        // ---- scores S = Q K^T (3 passes) ----
        float s[8][4];
        #pragma unroll
        for (int i = 0; i < 8; i++)
            #pragma unroll
            for (int j = 0; j < 4; j++) s[i][j] = 0.f;

        int arow = wid * 16 + (lane & 15);
        int brow = lane & 7;
        #pragma unroll
        for (int ksIdx = 0; ksIdx < 4; ksIdx++) {
            int k0 = ksIdx * 16;
            int acol = k0 + (lane >> 4) * 8;
            int bcol = k0 + ((lane >> 3) & 1) * 8;
            uint32_t qh[4], ql[4];
            ldsm_x4(qh, sb + AOFF_QHI + arow * AST + acol * 2);
            ldsm_x4(ql, sb + AOFF_QLO + arow * AST + acol * 2);
            #pragma unroll
            for (int nt = 0; nt < 8; nt++) {
                uint32_t kh[2], kl[2];
                ldsm_x2(kh, kHiB + (nt * 8 + brow) * AST + bcol * 2);
                ldsm_x2(kl, kLoB + (nt * 8 + brow) * AST + bcol * 2);
                mma16816(s[nt], qh, kh);
                mma16816(s[nt], ql, kh);
                mma16816(s[nt], qh, kl);
            }
        }

        // ---- causal mask (diagonal tiles only) ----
        if (kt >= 2 * qt) {
            #pragma unroll
            for (int nt = 0; nt < 8; nt++) {
                int gc = kt * 64 + nt * 8 + q2;
                if (gc > grow0)     s[nt][0] = -INFINITY;
                if (gc + 1 > grow0) s[nt][1] = -INFINITY;
                if (gc > grow1)     s[nt][2] = -INFINITY;
                if (gc + 1 > grow1) s[nt][3] = -INFINITY;
            }
        }

        // ---- online softmax ----
        float mx0 = -INFINITY, mx1 = -INFINITY;
        #pragma unroll
        for (int nt = 0; nt < 8; nt++) {
            mx0 = fmaxf(mx0, fmaxf(s[nt][0], s[nt][1]));
            mx1 = fmaxf(mx1, fmaxf(s[nt][2], s[nt][3]));
        }
        mx0 = fmaxf(mx0, __shfl_xor_sync(0xffffffffu, mx0, 1));
        mx0 = fmaxf(mx0, __shfl_xor_sync(0xffffffffu, mx0, 2));
        mx1 = fmaxf(mx1, __shfl_xor_sync(0xffffffffu, mx1, 1));
        mx1 = fmaxf(mx1, __shfl_xor_sync(0xffffffffu, mx1, 2));
        float mn0 = fmaxf(m0, mx0), mn1 = fmaxf(m1, mx1);
        float c0 = __expf(m0 - mn0), c1 = __expf(m1 - mn1);
        float ps0 = 0.f, ps1 = 0.f;
        #pragma unroll
        for (int nt = 0; nt < 8; nt++) {
            s[nt][0] = __expf(s[nt][0] - mn0);
            s[nt][1] = __expf(s[nt][1] - mn0);
            s[nt][2] = __expf(s[nt][2] - mn1);
            s[nt][3] = __expf(s[nt][3] - mn1);
            ps0 += s[nt][0] + s[nt][1];
            ps1 += s[nt][2] + s[nt][3];
        }
        ps0 += __shfl_xor_sync(0xffffffffu, ps0, 1);
        ps0 += __shfl_xor_sync(0xffffffffu, ps0, 2);
        ps1 += __shfl_xor_sync(0xffffffffu, ps1, 1);
        ps1 += __shfl_xor_sync(0xffffffffu, ps1, 2);
        l0 = l0 * c0 + ps0;
        l1 = l1 * c1 + ps1;
        m0 = mn0; m1 = mn1;
        #pragma unroll
        for (int dt = 0; dt < 8; dt++) {
            o[dt][0] *= c0; o[dt][1] *= c0;
            o[dt][2] *= c1; o[dt][3] *= c1;
        }

        // ---- O += P @ V (P in regs; V hi/lo via ldmatrix.trans) ----
        #pragma unroll
        for (int ksIdx = 0; ksIdx < 4; ksIdx++) {
            uint32_t a[4];
            a[0] = packbf2(s[2*ksIdx][0],   s[2*ksIdx][1]);
            a[1] = packbf2(s[2*ksIdx][2],   s[2*ksIdx][3]);
            a[2] = packbf2(s[2*ksIdx+1][0], s[2*ksIdx+1][1]);
            a[3] = packbf2(s[2*ksIdx+1][2], s[2*ksIdx+1][3]);
            int vrow = ksIdx * 16 + (lane & 15);
            #pragma unroll
            for (int dt = 0; dt < 8; dt++) {
                uint32_t vh[2], vl[2];
                ldsm_x2t(vh, vHiB + vrow * AST + dt * 16);
                ldsm_x2t(vl, vLoB + vrow * AST + dt * 16);
                mma16816(o[dt], a, vh);
                mma16816(o[dt], a, vl);
            }
        }
        __syncthreads();   // reads done before next prefetch overwrites
    }

    // ---- epilogue: o/l + residual ----
    float il0 = 1.f / l0, il1 = 1.f / l1;
    int row0 = b * S_ + qt * 128 + wid * 16 + r;
    int row1 = row0 + 8;
    #pragma unroll
    for (int dt = 0; dt < 8; dt++) {
        int col = h * 64 + dt * 8 + q2;
        size_t gi0 = (size_t)row0 * E_ + col;
        size_t gi1 = (size_t)row1 * E_ + col;
        float2 x0 = *(const float2*)(x + gi0);
        float2 x1 = *(const float2*)(x + gi1);
        *(float2*)(xo + gi0) = make_float2(x0.x + o[dt][0] * il0,
                                           x0.y + o[dt][1] * il0);
        *(float2*)(xo + gi1) = make_float2(x1.x + o[dt][2] * il1,
                                           x1.y + o[dt][3] * il1);
    }
}

// ---------------- launcher -------------------------------------------------
extern "C" void kernel_launch(void* const* d_in, const int* in_sizes, int n_in,
                              void* d_out, int out_size) {
    const float* emb   = (const float*)d_in[0];
    const float* Wq    = (const float*)d_in[1];
    const float* bq    = (const float*)d_in[2];
    const float* Wk    = (const float*)d_in[3];
    const float* bk    = (const float*)d_in[4];
    const float* Wv    = (const float*)d_in[5];
    const float* bv    = (const float*)d_in[6];
    const float* ln1_w = (const float*)d_in[7];
    const float* ln1_b = (const float*)d_in[8];
    const float* ln2_w = (const float*)d_in[9];
    const float* ln2_b = (const float*)d_in[10];
    const float* W1    = (const float*)d_in[11];
    const float* b1    = (const float*)d_in[12];
    const float* W2    = (const float*)d_in[13];
    const float* b2    = (const float*)d_in[14];
    float* out = (float*)d_out;

    float *px, *pxo, *py, *pbcat;
    __nv_bfloat16 *pqh, *pql, *pxhi, *pxlo, *pyhi, *pylo, *phhi, *phlo;
    __nv_bfloat16 *pwqh, *pwql, *pw1h, *pw1l, *pw2h, *pw2l;
    cudaGetSymbolAddress((void**)&px,   g_x);
    cudaGetSymbolAddress((void**)&pxo,  g_xo);
    cudaGetSymbolAddress((void**)&py,   g_y);
    cudaGetSymbolAddress((void**)&pbcat,g_bcat);
    cudaGetSymbolAddress((void**)&pqh,  g_qkv_hi);
    cudaGetSymbolAddress((void**)&pql,  g_qkv_lo);
    cudaGetSymbolAddress((void**)&pxhi, g_xhi);
    cudaGetSymbolAddress((void**)&pxlo, g_xlo);
    cudaGetSymbolAddress((void**)&pyhi, g_yhi);
    cudaGetSymbolAddress((void**)&pylo, g_ylo);
    cudaGetSymbolAddress((void**)&phhi, g_hhi);
    cudaGetSymbolAddress((void**)&phlo, g_hlo);
    cudaGetSymbolAddress((void**)&pwqh, g_wqkv_hi);
    cudaGetSymbolAddress((void**)&pwql, g_wqkv_lo);
    cudaGetSymbolAddress((void**)&pw1h, g_w1t_hi);
    cudaGetSymbolAddress((void**)&pw1l, g_w1t_lo);
    cudaGetSymbolAddress((void**)&pw2h, g_w2t_hi);
    cudaGetSymbolAddress((void**)&pw2l, g_w2t_lo);

    cudaFuncSetAttribute(gemm_mma,
                         cudaFuncAttributeMaxDynamicSharedMemorySize, GEMM_SMEM);
    cudaFuncSetAttribute(attn_mma,
                         cudaFuncAttributeMaxDynamicSharedMemorySize, ATTN_SMEM);

    // launch 0: all prep (transposes + bias concat) in one kernel
    prep_kernel<<<11276, dim3(32, 8)>>>(Wq, Wk, Wv, W1, W2, bq, bk, bv,
                                        pwqh, pwql, pw1h, pw1l, pw2h, pw2l, pbcat);

    // launch 1: LN1 -> x fp32 + hi/lo
    ln_kernel<<<M_, 256>>>(emb, ln1_w, ln1_b, px, pxhi, pxlo);

    // launch 2: fused QKV (scaled q) -> bf16 hi/lo
    gemm_mma<<<dim3(NQKV_/128, M_/128), 256, GEMM_SMEM>>>(
        pxhi, pxlo, pwqh, pwql, pbcat, nullptr, nullptr, pqh, pql,
        E_, NQKV_, 3);

    // launch 3: attention + residual -> g_xo
    attn_mma<<<dim3(S_/128, H_, B_), 256, ATTN_SMEM>>>(pqh, pql, px, pxo);

    // launch 4: LN2 -> y fp32 + hi/lo
    ln_kernel<<<M_, 256>>>(pxo, ln2_w, ln2_b, py, pyhi, pylo);

    // launch 5: FFN1: h = relu(y @ W1 + b1) -> bf16 hi/lo
    gemm_mma<<<dim3(HID_/128, M_/128), 256, GEMM_SMEM>>>(
        pyhi, pylo, pw1h, pw1l, b1, nullptr, nullptr, phhi, phlo,
        E_, HID_, 1);

    // launch 6: FFN2: out = y + h @ W2 + b2
    gemm_mma<<<dim3(E_/128, M_/128), 256, GEMM_SMEM>>>(
        phhi, phlo, pw2h, pw2l, b2, py, out, nullptr, nullptr,
        HID_, E_, 2);
}

// round 6
// speedup vs baseline: 1.5014x; 1.4798x over previous
#include <cuda_runtime.h>
#include <cuda_fp16.h>
#include <cstdint>
#include <math.h>

// ---------------- problem constants ----------------
constexpr int B_  = 2;
constexpr int S_  = 2048;
constexpr int E_  = 1024;
constexpr int H_  = 16;
constexpr int DK_ = 64;
constexpr int HID_= 4096;
constexpr int M_  = B_ * S_;       // 4096 rows
constexpr int NQKV_ = 3 * E_;      // 3072 fused qkv output cols
constexpr int QKV_LD = NQKV_;

// ================= PTX helpers (base sm_103: mma.sync/ldmatrix/cp.async) ==
__device__ __forceinline__ uint32_t smem_to_u32(const void* p) {
    uint32_t a;
    asm("{ .reg .u64 t; cvta.to.shared.u64 t, %1; cvt.u32.u64 %0, t; }"
        : "=r"(a) : "l"(p));
    return a;
}
__device__ __forceinline__ void mma16816(float* d, const uint32_t* a, const uint32_t* b) {
    asm volatile("mma.sync.aligned.m16n8k16.row.col.f32.f16.f16.f32 "
        "{%0,%1,%2,%3}, {%4,%5,%6,%7}, {%8,%9}, {%0,%1,%2,%3};"
        : "+f"(d[0]), "+f"(d[1]), "+f"(d[2]), "+f"(d[3])
        : "r"(a[0]), "r"(a[1]), "r"(a[2]), "r"(a[3]), "r"(b[0]), "r"(b[1]));
}
__device__ __forceinline__ void ldsm_x4(uint32_t* r, uint32_t addr) {
    asm volatile("ldmatrix.sync.aligned.m8n8.x4.shared.b16 {%0,%1,%2,%3}, [%4];"
        : "=r"(r[0]), "=r"(r[1]), "=r"(r[2]), "=r"(r[3]) : "r"(addr));
}
__device__ __forceinline__ void ldsm_x2(uint32_t* r, uint32_t addr) {
    asm volatile("ldmatrix.sync.aligned.m8n8.x2.shared.b16 {%0,%1}, [%2];"
        : "=r"(r[0]), "=r"(r[1]) : "r"(addr));
}
__device__ __forceinline__ void ldsm_x2t(uint32_t* r, uint32_t addr) {
    asm volatile("ldmatrix.sync.aligned.m8n8.x2.trans.shared.b16 {%0,%1}, [%2];"
        : "=r"(r[0]), "=r"(r[1]) : "r"(addr));
}
__device__ __forceinline__ void cp_async16(uint32_t dst, const void* src) {
    asm volatile("cp.async.cg.shared.global [%0], [%1], 16;" :: "r"(dst), "l"(src));
}
#define CP_COMMIT() asm volatile("cp.async.commit_group;")
__device__ __forceinline__ uint32_t packh2(float a, float b) {
    __half2 h = __floats2half2_rn(a, b);
    return *(uint32_t*)&h;
}

// ---------------- scratch (device globals) --------------------------------
__device__ __align__(16) float g_x  [M_ * E_];
__device__ __align__(16) float g_xo [M_ * E_];
__device__ __align__(16) float g_y  [M_ * E_];
__device__ __align__(16) __half g_qkv_hi[M_ * NQKV_], g_qkv_lo[M_ * NQKV_];
__device__ __align__(16) __half g_xhi[M_ * E_],  g_xlo[M_ * E_];
__device__ __align__(16) __half g_yhi[M_ * E_],  g_ylo[M_ * E_];
__device__ __align__(16) __half g_hhi[M_ * HID_], g_hlo[M_ * HID_];
__device__ __align__(16) __half g_wqkv[NQKV_ * E_];     // weights: hi only
__device__ __align__(16) __half g_w1t[HID_ * E_];
__device__ __align__(16) __half g_w2t[E_ * HID_];
__device__ float g_bcat[NQKV_];

// ---------------- merged prep: weight transposes (hi only) + bias concat ---
__device__ __forceinline__ void transpose_tile(
        const float* __restrict__ in, __half* __restrict__ oh,
        int R, int C, int c0, int r0, float scale, int tx, int ty) {
    __shared__ float tile[32][33];
    #pragma unroll
    for (int j = 0; j < 4; j++)
        tile[ty + j * 8][tx] = in[(size_t)(r0 + ty + j * 8) * C + c0 + tx];
    __syncthreads();
    #pragma unroll
    for (int j = 0; j < 4; j++) {
        float v = tile[tx][ty + j * 8] * scale;
        oh[(size_t)(c0 + ty + j * 8) * R + r0 + tx] = __float2half_rn(v);
    }
}

__global__ void prep_kernel(const float* __restrict__ Wq, const float* __restrict__ Wk,
                            const float* __restrict__ Wv, const float* __restrict__ W1,
                            const float* __restrict__ W2,
                            const float* __restrict__ bq, const float* __restrict__ bk,
                            const float* __restrict__ bv,
                            __half* __restrict__ wqkv,
                            __half* __restrict__ w1t, __half* __restrict__ w2t,
                            float* __restrict__ bcat) {
    int id = blockIdx.x;
    int tx = threadIdx.x, ty = threadIdx.y;
    if (id < 3072) {
        int which = id >> 10;                  // 0=q,1=k,2=v
        int local = id & 1023;
        int z = local >> 6;                    // head
        int rem = local & 63;
        int cx = rem & 1, ry = rem >> 1;
        const float* src = (which == 0) ? Wq : (which == 1) ? Wk : Wv;
        float scale = (which == 0) ? 0.125f : 1.f;
        transpose_tile(src + (size_t)z * E_ * DK_,
                       wqkv + (size_t)which * 1024 * E_ + (size_t)z * DK_ * E_,
                       E_, DK_, cx * 32, ry * 32, scale, tx, ty);
    } else if (id < 7168) {
        int local = id - 3072;
        int cx = local & 127, ry = local >> 7;
        transpose_tile(W1, w1t, E_, HID_, cx * 32, ry * 32, 1.f, tx, ty);
    } else if (id < 11264) {
        int local = id - 7168;
        int cx = local & 31, ry = local >> 5;
        transpose_tile(W2, w2t, HID_, E_, cx * 32, ry * 32, 1.f, tx, ty);
    } else {
        int n = (id - 11264) * 256 + ty * 32 + tx;
        const float* src = (n < 1024) ? bq : ((n < 2048) ? bk : bv);
        float sc = (n < 1024) ? 0.125f : 1.f;
        bcat[n] = src[n & 1023] * sc;
    }
}

// ---------------- LayerNorm: fp32 out + fp16 hi/lo out ---------------------
__global__ void ln_kernel(const float* __restrict__ in,
                          const float* __restrict__ w,
                          const float* __restrict__ b,
                          float* __restrict__ out,
                          __half* __restrict__ ohi,
                          __half* __restrict__ olo) {
    int row = blockIdx.x;
    int t = threadIdx.x;
    const float4* ip = (const float4*)(in + (size_t)row * E_);
    float4 v = ip[t];
    float s  = v.x + v.y + v.z + v.w;
    float sq = v.x*v.x + v.y*v.y + v.z*v.z + v.w*v.w;
    #pragma unroll
    for (int o = 16; o; o >>= 1) {
        s  += __shfl_xor_sync(0xffffffffu, s,  o);
        sq += __shfl_xor_sync(0xffffffffu, sq, o);
    }
    __shared__ float ss[8], ssq[8];
    __shared__ float mu_s, inv_s;
    if ((t & 31) == 0) { ss[t >> 5] = s; ssq[t >> 5] = sq; }
    __syncthreads();
    if (t < 32) {
        float s2  = (t < 8) ? ss[t]  : 0.f;
        float sq2 = (t < 8) ? ssq[t] : 0.f;
        #pragma unroll
        for (int o = 4; o; o >>= 1) {
            s2  += __shfl_xor_sync(0xffffffffu, s2,  o);
            sq2 += __shfl_xor_sync(0xffffffffu, sq2, o);
        }
        if (t == 0) {
            float mu  = s2 * (1.f / E_);
            float var = sq2 * (1.f / E_) - mu * mu;
            mu_s  = mu;
            inv_s = rsqrtf(var + 1e-5f);
        }
    }
    __syncthreads();
    float mu = mu_s, inv = inv_s;
    float4 wv = ((const float4*)w)[t];
    float4 bv = ((const float4*)b)[t];
    float4 o4;
    o4.x = (v.x - mu) * inv * wv.x + bv.x;
    o4.y = (v.y - mu) * inv * wv.y + bv.y;
    o4.z = (v.z - mu) * inv * wv.z + bv.z;
    o4.w = (v.w - mu) * inv * wv.w + bv.w;
    ((float4*)(out + (size_t)row * E_))[t] = o4;
    __half h0 = __float2half_rn(o4.x), h1 = __float2half_rn(o4.y);
    __half h2 = __float2half_rn(o4.z), h3 = __float2half_rn(o4.w);
    __half2 hp0; hp0.x = h0; hp0.y = h1;
    __half2 hp1; hp1.x = h2; hp1.y = h3;
    ((__half2*)(ohi + (size_t)row * E_))[2*t]   = hp0;
    ((__half2*)(ohi + (size_t)row * E_))[2*t+1] = hp1;
    __half2 lp0, lp1;
    lp0.x = __float2half_rn(o4.x - __half2float(h0));
    lp0.y = __float2half_rn(o4.y - __half2float(h1));
    lp1.x = __float2half_rn(o4.z - __half2float(h2));
    lp1.y = __float2half_rn(o4.w - __half2float(h3));
    ((__half2*)(olo + (size_t)row * E_))[2*t]   = lp0;
    ((__half2*)(olo + (size_t)row * E_))[2*t+1] = lp1;
}

// ---------------- HMMA GEMM: C[M,N] = (Ahi+Alo) @ Bhi^T (fp16, 2-pass) -----
// CTA tile 128x128, 8 warps of 64x32, K chunk 32, 2-stage cp.async pipeline.
// mode 1: relu -> Chi/Clo | mode 2: fp32 + bias + resid | mode 3: Chi/Clo + bias
constexpr int GSTRIDE_B = 80;                // bytes per smem row (40 fp16)
constexpr int GTILE_B   = 128 * GSTRIDE_B;   // 10240 per array
constexpr int GBUF_B    = 3 * GTILE_B;       // 30720 per stage (Ahi,Alo,Bhi)
constexpr int GSTAGES   = 2;
constexpr int GEMM_SMEM = GSTAGES * GBUF_B;  // 61440

__global__ __launch_bounds__(256)
void gemm_mma(const __half* __restrict__ Ahi, const __half* __restrict__ Alo,
              const __half* __restrict__ Bhi,
              const float* __restrict__ bias, const float* __restrict__ resid,
              float* __restrict__ Cf,
              __half* __restrict__ Chi, __half* __restrict__ Clo,
              int K, int N, int mode) {
    extern __shared__ char smraw[];
    uint32_t sb = smem_to_u32(smraw);
    int t = threadIdx.x, lane = t & 31, wid = t >> 5;
    int bm = blockIdx.y * 128, bn = blockIdx.x * 128;
    int wm = wid & 1, wn = wid >> 1;

    const __half* gsrc[3] = {
        Ahi + (size_t)bm * K, Alo + (size_t)bm * K, Bhi + (size_t)bn * K };

    float acc[4][4][4];
    #pragma unroll
    for (int i = 0; i < 4; i++)
        #pragma unroll
        for (int j = 0; j < 4; j++)
            #pragma unroll
            for (int e = 0; e < 4; e++) acc[i][j][e] = 0.f;

    int nch = K >> 5;
    int ldrow = t >> 2, ldseg = t & 3;      // 64 rows per 256-thr pass

    // ---- prologue: stage 0 ----
    {
        #pragma unroll
        for (int arr = 0; arr < 3; arr++) {
            uint32_t dst = sb + arr * GTILE_B;
            #pragma unroll
            for (int f = 0; f < 2; f++) {
                int row = ldrow + f * 64;
                cp_async16(dst + row * GSTRIDE_B + ldseg * 16,
                           gsrc[arr] + (size_t)row * K + ldseg * 8);
            }
        }
        CP_COMMIT();
    }

    for (int c = 0; c < nch; c++) {
        if (c + 1 < nch) {
            int k0 = (c + 1) << 5;
            uint32_t base = sb + ((c + 1) & 1) * GBUF_B;
            #pragma unroll
            for (int arr = 0; arr < 3; arr++) {
                uint32_t dst = base + arr * GTILE_B;
                #pragma unroll
                for (int f = 0; f < 2; f++) {
                    int row = ldrow + f * 64;
                    cp_async16(dst + row * GSTRIDE_B + ldseg * 16,
                               gsrc[arr] + (size_t)row * K + k0 + ldseg * 8);
                }
            }
            CP_COMMIT();
            asm volatile("cp.async.wait_group 1;");
        } else {
            asm volatile("cp.async.wait_group 0;");
        }
        __syncthreads();

        uint32_t base = sb + (c & 1) * GBUF_B;
        uint32_t aHiB = base;
        uint32_t aLoB = base + GTILE_B;
        uint32_t bHiB = base + 2 * GTILE_B;

        #pragma unroll
        for (int ks = 0; ks < 2; ks++) {
            int k0 = ks * 16;
            int arow = wm * 64 + (lane & 15);
            int acol = k0 + (lane >> 4) * 8;
            int brow = wn * 32 + (lane & 7);
            int bcol = k0 + ((lane >> 3) & 1) * 8;

            uint32_t ah[4][4], bh[4][2];
            #pragma unroll
            for (int mt = 0; mt < 4; mt++)
                ldsm_x4(ah[mt], aHiB + (arow + mt * 16) * GSTRIDE_B + acol * 2);
            #pragma unroll
            for (int nt = 0; nt < 4; nt++)
                ldsm_x2(bh[nt], bHiB + (brow + nt * 8) * GSTRIDE_B + bcol * 2);
            #pragma unroll
            for (int nt = 0; nt < 4; nt++)
                #pragma unroll
                for (int mt = 0; mt < 4; mt++)
                    mma16816(acc[mt][nt], ah[mt], bh[nt]);
            uint32_t al[4][4];
            #pragma unroll
            for (int mt = 0; mt < 4; mt++)
                ldsm_x4(al[mt], aLoB + (arow + mt * 16) * GSTRIDE_B + acol * 2);
            #pragma unroll
            for (int nt = 0; nt < 4; nt++)
                #pragma unroll
                for (int mt = 0; mt < 4; mt++)
                    mma16816(acc[mt][nt], al[mt], bh[nt]);
        }
        __syncthreads();
    }

    // ---- epilogue ----
    int r = lane >> 2, q2 = (lane & 3) * 2;
    #pragma unroll
    for (int mt = 0; mt < 4; mt++) {
        int row0 = bm + wm * 64 + mt * 16 + r;
        #pragma unroll
        for (int nt = 0; nt < 4; nt++) {
            int col = bn + wn * 32 + nt * 8 + q2;
            float b0 = bias[col], b1 = bias[col + 1];
            float v0 = acc[mt][nt][0] + b0, v1 = acc[mt][nt][1] + b1;
            float v2 = acc[mt][nt][2] + b0, v3 = acc[mt][nt][3] + b1;
            size_t gi0 = (size_t)row0 * N + col;
            size_t gi1 = gi0 + (size_t)8 * N;
            if (mode == 2) {
                float2 r0 = *(const float2*)(resid + gi0);
                float2 r1 = *(const float2*)(resid + gi1);
                *(float2*)(Cf + gi0) = make_float2(v0 + r0.x, v1 + r0.y);
                *(float2*)(Cf + gi1) = make_float2(v2 + r1.x, v3 + r1.y);
            } else {
                if (mode == 1) {
                    v0 = fmaxf(v0, 0.f); v1 = fmaxf(v1, 0.f);
                    v2 = fmaxf(v2, 0.f); v3 = fmaxf(v3, 0.f);
                }
                __half h0 = __float2half_rn(v0), h1 = __float2half_rn(v1);
                __half h2 = __float2half_rn(v2), h3 = __float2half_rn(v3);
                __half2 hp0; hp0.x = h0; hp0.y = h1;
                __half2 hp1; hp1.x = h2; hp1.y = h3;
                *(__half2*)(Chi + gi0) = hp0;
                *(__half2*)(Chi + gi1) = hp1;
                __half2 lp0, lp1;
                lp0.x = __float2half_rn(v0 - __half2float(h0));
                lp0.y = __float2half_rn(v1 - __half2float(h1));
                lp1.x = __float2half_rn(v2 - __half2float(h2));
                lp1.y = __float2half_rn(v3 - __half2float(h3));
                *(__half2*)(Clo + gi0) = lp0;
                *(__half2*)(Clo + gi1) = lp1;
            }
        }
    }
}

// ---------------- HMMA flash attention (fp16) ------------------------------
// CTA: 128 q rows (8 warps x 16), kv tiles of 64, double-buffered cp.async.
// QK^T: 3 passes (score accuracy). PV: 1 pass (P fp16, V hi only).
constexpr int AST = 144;                       // row stride bytes (64 fp16 + pad)
constexpr int AOFF_QHI = 0;
constexpr int AOFF_QLO = 128 * AST;            // 18432
constexpr int AOFF_KV  = 2 * 128 * AST;        // 36864
constexpr int KV_STAGE = 3 * 64 * AST;         // 27648 (Khi,Klo,Vhi)
constexpr int ATTN_SMEM = AOFF_KV + 2 * KV_STAGE;  // 92160

__device__ __forceinline__ void cp_kv_tile(uint32_t base,
        const __half* khi, const __half* klo, const __half* vhi, int t) {
    #pragma unroll
    for (int f = 0; f < 2; f++) {
        int idx = t + f * 256;
        int row = idx >> 3, seg = idx & 7;
        uint32_t o = row * AST + seg * 16;
        size_t go = (size_t)row * QKV_LD + seg * 8;
        cp_async16(base + o,                khi + go);
        cp_async16(base + 64 * AST + o,     klo + go);
        cp_async16(base + 2 * 64 * AST + o, vhi + go);
    }
}

__global__ __launch_bounds__(256)
void attn_mma(const __half* __restrict__ qkv_hi,
              const __half* __restrict__ qkv_lo,
              const float* __restrict__ x,
              float* __restrict__ xo) {
    extern __shared__ char smraw[];
    uint32_t sb = smem_to_u32(smraw);
    int qt = gridDim.x - 1 - blockIdx.x;       // heavy tiles first
    int h = blockIdx.y, b = blockIdx.z;
    int t = threadIdx.x, lane = t & 31, wid = t >> 5;

    const __half* qhi = qkv_hi + (size_t)(b * S_ + qt * 128) * QKV_LD + h * 64;
    const __half* qlo = qkv_lo + (size_t)(b * S_ + qt * 128) * QKV_LD + h * 64;
    const __half* khi0 = qkv_hi + (size_t)(b * S_) * QKV_LD + 1024 + h * 64;
    const __half* klo0 = qkv_lo + (size_t)(b * S_) * QKV_LD + 1024 + h * 64;
    const __half* vhi0 = khi0 + 1024;

    // ---- prologue: Q tile (hi+lo) + KV tile 0 ----
    #pragma unroll
    for (int f = 0; f < 4; f++) {
        int idx = t + f * 256;
        int row = idx >> 3, seg = idx & 7;
        uint32_t o = row * AST + seg * 16;
        size_t go = (size_t)row * QKV_LD + seg * 8;
        cp_async16(sb + AOFF_QHI + o, qhi + go);
        cp_async16(sb + AOFF_QLO + o, qlo + go);
    }
    cp_kv_tile(sb + AOFF_KV, khi0, klo0, vhi0, t);
    CP_COMMIT();

    float o[8][4];
    #pragma unroll
    for (int i = 0; i < 8; i++)
        #pragma unroll
        for (int j = 0; j < 4; j++) o[i][j] = 0.f;
    float m0 = -INFINITY, m1 = -INFINITY, l0 = 0.f, l1 = 0.f;

    int r = lane >> 2, q2 = (lane & 3) * 2;
    int grow0 = qt * 128 + wid * 16 + r;
    int grow1 = grow0 + 8;

    int nkt = 2 * qt + 2;
    for (int kt = 0; kt < nkt; kt++) {
        if (kt + 1 < nkt) {
            size_t koff = (size_t)((kt + 1) * 64) * QKV_LD;
            cp_kv_tile(sb + AOFF_KV + ((kt + 1) & 1) * KV_STAGE,
                       khi0 + koff, klo0 + koff, vhi0 + koff, t);
            CP_COMMIT();
            asm volatile("cp.async.wait_group 1;");
        } else {
            asm volatile("cp.async.wait_group 0;");
        }
        __syncthreads();

        uint32_t kvb = sb + AOFF_KV + (kt & 1) * KV_STAGE;
        uint32_t kHiB = kvb, kLoB = kvb + 64 * AST;
        uint32_t vHiB = kvb + 2 * 64 * AST;

        // ---- scores S = Q K^T (3 passes, fp16 => ~2^-22 error) ----
        float s[8][4];
        #pragma unroll
        for (int i = 0; i < 8; i++)
            #pragma unroll
            for (int j = 0; j < 4; j++) s[i][j] = 0.f;

        int arow = wid * 16 + (lane & 15);
        int brow = lane & 7;
        #pragma unroll
        for (int ksIdx = 0; ksIdx < 4; ksIdx++) {
            int k0 = ksIdx * 16;
            int acol = k0 + (lane >> 4) * 8;
            int bcol = k0 + ((lane >> 3) & 1) * 8;
            uint32_t qh[4], ql[4];
            ldsm_x4(qh, sb + AOFF_QHI + arow * AST + acol * 2);
            ldsm_x4(ql, sb + AOFF_QLO + arow * AST + acol * 2);
            #pragma unroll
            for (int nt = 0; nt < 8; nt++) {
                uint32_t kh[2], kl[2];
                ldsm_x2(kh, kHiB + (nt * 8 + brow) * AST + bcol * 2);
                ldsm_x2(kl, kLoB + (nt * 8 + brow) * AST + bcol * 2);
                mma16816(s[nt], qh, kh);
                mma16816(s[nt], ql, kh);
                mma16816(s[nt], qh, kl);
            }
        }

        // ---- causal mask (diagonal tiles only) ----
        if (kt >= 2 * qt) {
            #pragma unroll
            for (int nt = 0; nt < 8; nt++) {
                int gc = kt * 64 + nt * 8 + q2;
                if (gc > grow0)     s[nt][0] = -INFINITY;
                if (gc + 1 > grow0) s[nt][1] = -INFINITY;
                if (gc > grow1)     s[nt][2] = -INFINITY;
                if (gc + 1 > grow1) s[nt][3] = -INFINITY;
            }
        }

        // ---- online softmax ----
        float mx0 = -INFINITY, mx1 = -INFINITY;
        #pragma unroll
        for (int nt = 0; nt < 8; nt++) {
            mx0 = fmaxf(mx0, fmaxf(s[nt][0], s[nt][1]));
            mx1 = fmaxf(mx1, fmaxf(s[nt][2], s[nt][3]));
        }
        mx0 = fmaxf(mx0, __shfl_xor_sync(0xffffffffu, mx0, 1));
        mx0 = fmaxf(mx0, __shfl_xor_sync(0xffffffffu, mx0, 2));
        mx1 = fmaxf(mx1, __shfl_xor_sync(0xffffffffu, mx1, 1));
        mx1 = fmaxf(mx1, __shfl_xor_sync(0xffffffffu, mx1, 2));
        float mn0 = fmaxf(m0, mx0), mn1 = fmaxf(m1, mx1);
        float c0 = __expf(m0 - mn0), c1 = __expf(m1 - mn1);
        float ps0 = 0.f, ps1 = 0.f;
        #pragma unroll
        for (int nt = 0; nt < 8; nt++) {
            s[nt][0] = __expf(s[nt][0] - mn0);
            s[nt][1] = __expf(s[nt][1] - mn0);
            s[nt][2] = __expf(s[nt][2] - mn1);
            s[nt][3] = __expf(s[nt][3] - mn1);
            ps0 += s[nt][0] + s[nt][1];
            ps1 += s[nt][2] + s[nt][3];
        }
        ps0 += __shfl_xor_sync(0xffffffffu, ps0, 1);
        ps0 += __shfl_xor_sync(0xffffffffu, ps0, 2);
        ps1 += __shfl_xor_sync(0xffffffffu, ps1, 1);
        ps1 += __shfl_xor_sync(0xffffffffu, ps1, 2);
        l0 = l0 * c0 + ps0;
        l1 = l1 * c1 + ps1;
        m0 = mn0; m1 = mn1;
        #pragma unroll
        for (int dt = 0; dt < 8; dt++) {
            o[dt][0] *= c0; o[dt][1] *= c0;
            o[dt][2] *= c1; o[dt][3] *= c1;
        }

        // ---- O += P @ Vhi (P fp16 in regs; 1 pass) ----
        #pragma unroll
        for (int ksIdx = 0; ksIdx < 4; ksIdx++) {
            uint32_t a[4];
            a[0] = packh2(s[2*ksIdx][0],   s[2*ksIdx][1]);
            a[1] = packh2(s[2*ksIdx][2],   s[2*ksIdx][3]);
            a[2] = packh2(s[2*ksIdx+1][0], s[2*ksIdx+1][1]);
            a[3] = packh2(s[2*ksIdx+1][2], s[2*ksIdx+1][3]);
            int vrow = ksIdx * 16 + (lane & 15);
            #pragma unroll
            for (int dt = 0; dt < 8; dt++) {
                uint32_t vh[2];
                ldsm_x2t(vh, vHiB + vrow * AST + dt * 16);
                mma16816(o[dt], a, vh);
            }
        }
        __syncthreads();   // reads done before next prefetch overwrites
    }

    // ---- epilogue: o/l + residual ----
    float il0 = 1.f / l0, il1 = 1.f / l1;
    int row0 = b * S_ + qt * 128 + wid * 16 + r;
    int row1 = row0 + 8;
    #pragma unroll
    for (int dt = 0; dt < 8; dt++) {
        int col = h * 64 + dt * 8 + q2;
        size_t gi0 = (size_t)row0 * E_ + col;
        size_t gi1 = (size_t)row1 * E_ + col;
        float2 x0 = *(const float2*)(x + gi0);
        float2 x1 = *(const float2*)(x + gi1);
        *(float2*)(xo + gi0) = make_float2(x0.x + o[dt][0] * il0,
                                           x0.y + o[dt][1] * il0);
        *(float2*)(xo + gi1) = make_float2(x1.x + o[dt][2] * il1,
                                           x1.y + o[dt][3] * il1);
    }
}

// ---------------- launcher -------------------------------------------------
extern "C" void kernel_launch(void* const* d_in, const int* in_sizes, int n_in,
                              void* d_out, int out_size) {
    const float* emb   = (const float*)d_in[0];
    const float* Wq    = (const float*)d_in[1];
    const float* bq    = (const float*)d_in[2];
    const float* Wk    = (const float*)d_in[3];
    const float* bk    = (const float*)d_in[4];
    const float* Wv    = (const float*)d_in[5];
    const float* bv    = (const float*)d_in[6];
    const float* ln1_w = (const float*)d_in[7];
    const float* ln1_b = (const float*)d_in[8];
    const float* ln2_w = (const float*)d_in[9];
    const float* ln2_b = (const float*)d_in[10];
    const float* W1    = (const float*)d_in[11];
    const float* b1    = (const float*)d_in[12];
    const float* W2    = (const float*)d_in[13];
    const float* b2    = (const float*)d_in[14];
    float* out = (float*)d_out;

    float *px, *pxo, *py, *pbcat;
    __half *pqh, *pql, *pxhi, *pxlo, *pyhi, *pylo, *phhi, *phlo;
    __half *pwq, *pw1, *pw2;
    cudaGetSymbolAddress((void**)&px,   g_x);
    cudaGetSymbolAddress((void**)&pxo,  g_xo);
    cudaGetSymbolAddress((void**)&py,   g_y);
    cudaGetSymbolAddress((void**)&pbcat,g_bcat);
    cudaGetSymbolAddress((void**)&pqh,  g_qkv_hi);
    cudaGetSymbolAddress((void**)&pql,  g_qkv_lo);
    cudaGetSymbolAddress((void**)&pxhi, g_xhi);
    cudaGetSymbolAddress((void**)&pxlo, g_xlo);
    cudaGetSymbolAddress((void**)&pyhi, g_yhi);
    cudaGetSymbolAddress((void**)&pylo, g_ylo);
    cudaGetSymbolAddress((void**)&phhi, g_hhi);
    cudaGetSymbolAddress((void**)&phlo, g_hlo);
    cudaGetSymbolAddress((void**)&pwq,  g_wqkv);
    cudaGetSymbolAddress((void**)&pw1,  g_w1t);
    cudaGetSymbolAddress((void**)&pw2,  g_w2t);

    cudaFuncSetAttribute(gemm_mma,
                         cudaFuncAttributeMaxDynamicSharedMemorySize, GEMM_SMEM);
    cudaFuncSetAttribute(attn_mma,
                         cudaFuncAttributeMaxDynamicSharedMemorySize, ATTN_SMEM);

    // launch 0: all prep (transposes + bias concat) in one kernel
    prep_kernel<<<11276, dim3(32, 8)>>>(Wq, Wk, Wv, W1, W2, bq, bk, bv,
                                        pwq, pw1, pw2, pbcat);

    // launch 1: LN1 -> x fp32 + hi/lo
    ln_kernel<<<M_, 256>>>(emb, ln1_w, ln1_b, px, pxhi, pxlo);

    // launch 2: fused QKV (scaled q) -> fp16 hi/lo
    gemm_mma<<<dim3(NQKV_/128, M_/128), 256, GEMM_SMEM>>>(
        pxhi, pxlo, pwq, pbcat, nullptr, nullptr, pqh, pql,
        E_, NQKV_, 3);

    // launch 3: attention + residual -> g_xo
    attn_mma<<<dim3(S_/128, H_, B_), 256, ATTN_SMEM>>>(pqh, pql, px, pxo);

    // launch 4: LN2 -> y fp32 + hi/lo
    ln_kernel<<<M_, 256>>>(pxo, ln2_w, ln2_b, py, pyhi, pylo);

    // launch 5: FFN1: h = relu(y @ W1 + b1) -> fp16 hi/lo
    gemm_mma<<<dim3(HID_/128, M_/128), 256, GEMM_SMEM>>>(
        pyhi, pylo, pw1, b1, nullptr, nullptr, phhi, phlo,
        E_, HID_, 1);

    // launch 6: FFN2: out = y + h @ W2 + b2
    gemm_mma<<<dim3(E_/128, M_/128), 256, GEMM_SMEM>>>(
        phhi, phlo, pw2, b2, py, out, nullptr, nullptr,
        HID_, E_, 2);
}

// round 7
// speedup vs baseline: 1.5057x; 1.0029x over previous
#include <cuda_runtime.h>
#include <cuda_fp16.h>
#include <cstdint>
#include <math.h>

// ---------------- problem constants ----------------
constexpr int B_  = 2;
constexpr int S_  = 2048;
constexpr int E_  = 1024;
constexpr int H_  = 16;
constexpr int DK_ = 64;
constexpr int HID_= 4096;
constexpr int M_  = B_ * S_;       // 4096 rows
constexpr int NQKV_ = 3 * E_;      // 3072 fused qkv output cols
constexpr int QKV_LD = NQKV_;

// ================= PTX helpers (base sm_103: mma.sync/ldmatrix/cp.async) ==
__device__ __forceinline__ uint32_t smem_to_u32(const void* p) {
    uint32_t a;
    asm("{ .reg .u64 t; cvta.to.shared.u64 t, %1; cvt.u32.u64 %0, t; }"
        : "=r"(a) : "l"(p));
    return a;
}
__device__ __forceinline__ void mma16816(float* d, const uint32_t* a, const uint32_t* b) {
    asm volatile("mma.sync.aligned.m16n8k16.row.col.f32.f16.f16.f32 "
        "{%0,%1,%2,%3}, {%4,%5,%6,%7}, {%8,%9}, {%0,%1,%2,%3};"
        : "+f"(d[0]), "+f"(d[1]), "+f"(d[2]), "+f"(d[3])
        : "r"(a[0]), "r"(a[1]), "r"(a[2]), "r"(a[3]), "r"(b[0]), "r"(b[1]));
}
__device__ __forceinline__ void ldsm_x4(uint32_t* r, uint32_t addr) {
    asm volatile("ldmatrix.sync.aligned.m8n8.x4.shared.b16 {%0,%1,%2,%3}, [%4];"
        : "=r"(r[0]), "=r"(r[1]), "=r"(r[2]), "=r"(r[3]) : "r"(addr));
}
__device__ __forceinline__ void ldsm_x4t(uint32_t* r, uint32_t addr) {
    asm volatile("ldmatrix.sync.aligned.m8n8.x4.trans.shared.b16 {%0,%1,%2,%3}, [%4];"
        : "=r"(r[0]), "=r"(r[1]), "=r"(r[2]), "=r"(r[3]) : "r"(addr));
}
__device__ __forceinline__ void cp_async16(uint32_t dst, const void* src) {
    asm volatile("cp.async.cg.shared.global [%0], [%1], 16;" :: "r"(dst), "l"(src));
}
#define CP_COMMIT() asm volatile("cp.async.commit_group;")
__device__ __forceinline__ uint32_t packh2(float a, float b) {
    __half2 h = __floats2half2_rn(a, b);
    return *(uint32_t*)&h;
}

// ---------------- scratch (device globals) --------------------------------
__device__ __align__(16) float g_x  [M_ * E_];
__device__ __align__(16) float g_xo [M_ * E_];
__device__ __align__(16) float g_y  [M_ * E_];
__device__ __align__(16) __half g_qkv_hi[M_ * NQKV_], g_qkv_lo[M_ * NQKV_];
__device__ __align__(16) __half g_xhi[M_ * E_],  g_xlo[M_ * E_];
__device__ __align__(16) __half g_yhi[M_ * E_],  g_ylo[M_ * E_];
__device__ __align__(16) __half g_hhi[M_ * HID_], g_hlo[M_ * HID_];
__device__ __align__(16) __half g_wqkv[NQKV_ * E_];     // weights: hi only
__device__ __align__(16) __half g_w1t[HID_ * E_];
__device__ __align__(16) __half g_w2t[E_ * HID_];
__device__ float g_bcat[NQKV_];

// ---------------- merged prep: weight transposes (hi only) + bias concat ---
__device__ __forceinline__ void transpose_tile(
        const float* __restrict__ in, __half* __restrict__ oh,
        int R, int C, int c0, int r0, float scale, int tx, int ty) {
    __shared__ float tile[32][33];
    #pragma unroll
    for (int j = 0; j < 4; j++)
        tile[ty + j * 8][tx] = in[(size_t)(r0 + ty + j * 8) * C + c0 + tx];
    __syncthreads();
    #pragma unroll
    for (int j = 0; j < 4; j++) {
        float v = tile[tx][ty + j * 8] * scale;
        oh[(size_t)(c0 + ty + j * 8) * R + r0 + tx] = __float2half_rn(v);
    }
}

__global__ void prep_kernel(const float* __restrict__ Wq, const float* __restrict__ Wk,
                            const float* __restrict__ Wv, const float* __restrict__ W1,
                            const float* __restrict__ W2,
                            const float* __restrict__ bq, const float* __restrict__ bk,
                            const float* __restrict__ bv,
                            __half* __restrict__ wqkv,
                            __half* __restrict__ w1t, __half* __restrict__ w2t,
                            float* __restrict__ bcat) {
    int id = blockIdx.x;
    int tx = threadIdx.x, ty = threadIdx.y;
    if (id < 3072) {
        int which = id >> 10;                  // 0=q,1=k,2=v
        int local = id & 1023;
        int z = local >> 6;                    // head
        int rem = local & 63;
        int cx = rem & 1, ry = rem >> 1;
        const float* src = (which == 0) ? Wq : (which == 1) ? Wk : Wv;
        float scale = (which == 0) ? 0.125f : 1.f;
        transpose_tile(src + (size_t)z * E_ * DK_,
                       wqkv + (size_t)which * 1024 * E_ + (size_t)z * DK_ * E_,
                       E_, DK_, cx * 32, ry * 32, scale, tx, ty);
    } else if (id < 7168) {
        int local = id - 3072;
        int cx = local & 127, ry = local >> 7;
        transpose_tile(W1, w1t, E_, HID_, cx * 32, ry * 32, 1.f, tx, ty);
    } else if (id < 11264) {
        int local = id - 7168;
        int cx = local & 31, ry = local >> 5;
        transpose_tile(W2, w2t, HID_, E_, cx * 32, ry * 32, 1.f, tx, ty);
    } else {
        int n = (id - 11264) * 256 + ty * 32 + tx;
        const float* src = (n < 1024) ? bq : ((n < 2048) ? bk : bv);
        float sc = (n < 1024) ? 0.125f : 1.f;
        bcat[n] = src[n & 1023] * sc;
    }
}

// ---------------- LayerNorm: fp32 out + fp16 hi/lo out ---------------------
__global__ void ln_kernel(const float* __restrict__ in,
                          const float* __restrict__ w,
                          const float* __restrict__ b,
                          float* __restrict__ out,
                          __half* __restrict__ ohi,
                          __half* __restrict__ olo) {
    int row = blockIdx.x;
    int t = threadIdx.x;
    const float4* ip = (const float4*)(in + (size_t)row * E_);
    float4 v = ip[t];
    float s  = v.x + v.y + v.z + v.w;
    float sq = v.x*v.x + v.y*v.y + v.z*v.z + v.w*v.w;
    #pragma unroll
    for (int o = 16; o; o >>= 1) {
        s  += __shfl_xor_sync(0xffffffffu, s,  o);
        sq += __shfl_xor_sync(0xffffffffu, sq, o);
    }
    __shared__ float ss[8], ssq[8];
    __shared__ float mu_s, inv_s;
    if ((t & 31) == 0) { ss[t >> 5] = s; ssq[t >> 5] = sq; }
    __syncthreads();
    if (t < 32) {
        float s2  = (t < 8) ? ss[t]  : 0.f;
        float sq2 = (t < 8) ? ssq[t] : 0.f;
        #pragma unroll
        for (int o = 4; o; o >>= 1) {
            s2  += __shfl_xor_sync(0xffffffffu, s2,  o);
            sq2 += __shfl_xor_sync(0xffffffffu, sq2, o);
        }
        if (t == 0) {
            float mu  = s2 * (1.f / E_);
            float var = sq2 * (1.f / E_) - mu * mu;
            mu_s  = mu;
            inv_s = rsqrtf(var + 1e-5f);
        }
    }
    __syncthreads();
    float mu = mu_s, inv = inv_s;
    float4 wv = ((const float4*)w)[t];
    float4 bv = ((const float4*)b)[t];
    float4 o4;
    o4.x = (v.x - mu) * inv * wv.x + bv.x;
    o4.y = (v.y - mu) * inv * wv.y + bv.y;
    o4.z = (v.z - mu) * inv * wv.z + bv.z;
    o4.w = (v.w - mu) * inv * wv.w + bv.w;
    ((float4*)(out + (size_t)row * E_))[t] = o4;
    __half h0 = __float2half_rn(o4.x), h1 = __float2half_rn(o4.y);
    __half h2 = __float2half_rn(o4.z), h3 = __float2half_rn(o4.w);
    __half2 hp0; hp0.x = h0; hp0.y = h1;
    __half2 hp1; hp1.x = h2; hp1.y = h3;
    ((__half2*)(ohi + (size_t)row * E_))[2*t]   = hp0;
    ((__half2*)(ohi + (size_t)row * E_))[2*t+1] = hp1;
    __half2 lp0, lp1;
    lp0.x = __float2half_rn(o4.x - __half2float(h0));
    lp0.y = __float2half_rn(o4.y - __half2float(h1));
    lp1.x = __float2half_rn(o4.z - __half2float(h2));
    lp1.y = __float2half_rn(o4.w - __half2float(h3));
    ((__half2*)(olo + (size_t)row * E_))[2*t]   = lp0;
    ((__half2*)(olo + (size_t)row * E_))[2*t+1] = lp1;
}

// ---------------- HMMA GEMM: C[M,N] = (Ahi+Alo) @ Bhi^T (fp16, 2-pass) -----
// CTA tile 128x128, 8 warps of 64x32, K chunk 32, 3-stage cp.async pipeline.
// mode 1: relu -> Chi/Clo | mode 2: fp32 + bias + resid | mode 3: Chi/Clo + bias
constexpr int GSTRIDE_B = 80;                // bytes per smem row (40 fp16)
constexpr int GTILE_B   = 128 * GSTRIDE_B;   // 10240 per array
constexpr int GBUF_B    = 3 * GTILE_B;       // 30720 per stage (Ahi,Alo,Bhi)
constexpr int GSTAGES   = 3;
constexpr int GEMM_SMEM = GSTAGES * GBUF_B;  // 92160 -> still 2 CTAs/SM

__global__ __launch_bounds__(256)
void gemm_mma(const __half* __restrict__ Ahi, const __half* __restrict__ Alo,
              const __half* __restrict__ Bhi,
              const float* __restrict__ bias, const float* __restrict__ resid,
              float* __restrict__ Cf,
              __half* __restrict__ Chi, __half* __restrict__ Clo,
              int K, int N, int mode) {
    extern __shared__ char smraw[];
    uint32_t sb = smem_to_u32(smraw);
    int t = threadIdx.x, lane = t & 31, wid = t >> 5;
    int bm = blockIdx.y * 128, bn = blockIdx.x * 128;
    int wm = wid & 1, wn = wid >> 1;

    const __half* gsrc[3] = {
        Ahi + (size_t)bm * K, Alo + (size_t)bm * K, Bhi + (size_t)bn * K };

    float acc[4][4][4];
    #pragma unroll
    for (int i = 0; i < 4; i++)
        #pragma unroll
        for (int j = 0; j < 4; j++)
            #pragma unroll
            for (int e = 0; e < 4; e++) acc[i][j][e] = 0.f;

    int nch = K >> 5;
    int ldrow = t >> 2, ldseg = t & 3;      // 64 rows per 256-thr pass

    // ---- prologue: stages 0,1 ----
    #pragma unroll
    for (int p = 0; p < GSTAGES - 1; p++) {
        if (p < nch) {
            uint32_t base = sb + p * GBUF_B;
            int k0 = p << 5;
            #pragma unroll
            for (int arr = 0; arr < 3; arr++) {
                uint32_t dst = base + arr * GTILE_B;
                #pragma unroll
                for (int f = 0; f < 2; f++) {
                    int row = ldrow + f * 64;
                    cp_async16(dst + row * GSTRIDE_B + ldseg * 16,
                               gsrc[arr] + (size_t)row * K + k0 + ldseg * 8);
                }
            }
        }
        CP_COMMIT();
    }

    // ldmatrix lane addressing (constant across chunks)
    int arow = wm * 64 + (lane & 15);
    int acolsel = (lane >> 4) * 8;
    // B x4: pair p covers nt=2p,2p+1
    int brow4 = wn * 32 + ((lane >> 4) & 1) * 8 + (lane & 7);
    int bcolsel = ((lane >> 3) & 1) * 8;

    for (int c = 0; c < nch; c++) {
        if (c + GSTAGES - 1 < nch) {
            int k0 = (c + GSTAGES - 1) << 5;
            uint32_t base = sb + ((c + GSTAGES - 1) % GSTAGES) * GBUF_B;
            #pragma unroll
            for (int arr = 0; arr < 3; arr++) {
                uint32_t dst = base + arr * GTILE_B;
                #pragma unroll
                for (int f = 0; f < 2; f++) {
                    int row = ldrow + f * 64;
                    cp_async16(dst + row * GSTRIDE_B + ldseg * 16,
                               gsrc[arr] + (size_t)row * K + k0 + ldseg * 8);
                }
            }
            CP_COMMIT();
            asm volatile("cp.async.wait_group 2;");
        } else if (c + 1 < nch) {
            asm volatile("cp.async.wait_group 1;");
        } else {
            asm volatile("cp.async.wait_group 0;");
        }
        __syncthreads();

        uint32_t base = sb + (c % GSTAGES) * GBUF_B;
        uint32_t aHiB = base;
        uint32_t aLoB = base + GTILE_B;
        uint32_t bHiB = base + 2 * GTILE_B;

        #pragma unroll
        for (int ks = 0; ks < 2; ks++) {
            int k0 = ks * 16;
            int acol = k0 + acolsel;
            int bcol = k0 + bcolsel;

            uint32_t ah[4][4], bh[4][2];
            #pragma unroll
            for (int mt = 0; mt < 4; mt++)
                ldsm_x4(ah[mt], aHiB + (arow + mt * 16) * GSTRIDE_B + acol * 2);
            #pragma unroll
            for (int p = 0; p < 2; p++) {
                uint32_t tmp[4];
                ldsm_x4(tmp, bHiB + (brow4 + p * 16) * GSTRIDE_B + bcol * 2);
                bh[2*p][0] = tmp[0]; bh[2*p][1] = tmp[1];
                bh[2*p+1][0] = tmp[2]; bh[2*p+1][1] = tmp[3];
            }
            #pragma unroll
            for (int nt = 0; nt < 4; nt++)
                #pragma unroll
                for (int mt = 0; mt < 4; mt++)
                    mma16816(acc[mt][nt], ah[mt], bh[nt]);
            uint32_t al[4][4];
            #pragma unroll
            for (int mt = 0; mt < 4; mt++)
                ldsm_x4(al[mt], aLoB + (arow + mt * 16) * GSTRIDE_B + acol * 2);
            #pragma unroll
            for (int nt = 0; nt < 4; nt++)
                #pragma unroll
                for (int mt = 0; mt < 4; mt++)
                    mma16816(acc[mt][nt], al[mt], bh[nt]);
        }
        __syncthreads();
    }

    // ---- epilogue ----
    int r = lane >> 2, q2 = (lane & 3) * 2;
    #pragma unroll
    for (int mt = 0; mt < 4; mt++) {
        int row0 = bm + wm * 64 + mt * 16 + r;
        #pragma unroll
        for (int nt = 0; nt < 4; nt++) {
            int col = bn + wn * 32 + nt * 8 + q2;
            float b0 = bias[col], b1 = bias[col + 1];
            float v0 = acc[mt][nt][0] + b0, v1 = acc[mt][nt][1] + b1;
            float v2 = acc[mt][nt][2] + b0, v3 = acc[mt][nt][3] + b1;
            size_t gi0 = (size_t)row0 * N + col;
            size_t gi1 = gi0 + (size_t)8 * N;
            if (mode == 2) {
                float2 r0 = *(const float2*)(resid + gi0);
                float2 r1 = *(const float2*)(resid + gi1);
                *(float2*)(Cf + gi0) = make_float2(v0 + r0.x, v1 + r0.y);
                *(float2*)(Cf + gi1) = make_float2(v2 + r1.x, v3 + r1.y);
            } else {
                if (mode == 1) {
                    v0 = fmaxf(v0, 0.f); v1 = fmaxf(v1, 0.f);
                    v2 = fmaxf(v2, 0.f); v3 = fmaxf(v3, 0.f);
                }
                __half h0 = __float2half_rn(v0), h1 = __float2half_rn(v1);
                __half h2 = __float2half_rn(v2), h3 = __float2half_rn(v3);
                __half2 hp0; hp0.x = h0; hp0.y = h1;
                __half2 hp1; hp1.x = h2; hp1.y = h3;
                *(__half2*)(Chi + gi0) = hp0;
                *(__half2*)(Chi + gi1) = hp1;
                __half2 lp0, lp1;
                lp0.x = __float2half_rn(v0 - __half2float(h0));
                lp0.y = __float2half_rn(v1 - __half2float(h1));
                lp1.x = __float2half_rn(v2 - __half2float(h2));
                lp1.y = __float2half_rn(v3 - __half2float(h3));
                *(__half2*)(Clo + gi0) = lp0;
                *(__half2*)(Clo + gi1) = lp1;
            }
        }
    }
}

// ---------------- HMMA flash attention (fp16) ------------------------------
// CTA: 128 q rows (8 warps x 16), kv tiles of 64, double-buffered cp.async.
// QK^T: 3 passes (score accuracy). PV: 1 pass (P fp16, V hi only).
constexpr int AST = 144;                       // row stride bytes (64 fp16 + pad)
constexpr int AOFF_QHI = 0;
constexpr int AOFF_QLO = 128 * AST;            // 18432
constexpr int AOFF_KV  = 2 * 128 * AST;        // 36864
constexpr int KV_STAGE = 3 * 64 * AST;         // 27648 (Khi,Klo,Vhi)
constexpr int ATTN_SMEM = AOFF_KV + 2 * KV_STAGE;  // 92160

__device__ __forceinline__ void cp_kv_tile(uint32_t base,
        const __half* khi, const __half* klo, const __half* vhi, int t) {
    #pragma unroll
    for (int f = 0; f < 2; f++) {
        int idx = t + f * 256;
        int row = idx >> 3, seg = idx & 7;
        uint32_t o = row * AST + seg * 16;
        size_t go = (size_t)row * QKV_LD + seg * 8;
        cp_async16(base + o,                khi + go);
        cp_async16(base + 64 * AST + o,     klo + go);
        cp_async16(base + 2 * 64 * AST + o, vhi + go);
    }
}

__global__ __launch_bounds__(256)
void attn_mma(const __half* __restrict__ qkv_hi,
              const __half* __restrict__ qkv_lo,
              const float* __restrict__ x,
              float* __restrict__ xo) {
    extern __shared__ char smraw[];
    uint32_t sb = smem_to_u32(smraw);
    int qt = gridDim.x - 1 - blockIdx.x;       // heavy tiles first
    int h = blockIdx.y, b = blockIdx.z;
    int t = threadIdx.x, lane = t & 31, wid = t >> 5;

    const __half* qhi = qkv_hi + (size_t)(b * S_ + qt * 128) * QKV_LD + h * 64;
    const __half* qlo = qkv_lo + (size_t)(b * S_ + qt * 128) * QKV_LD + h * 64;
    const __half* khi0 = qkv_hi + (size_t)(b * S_) * QKV_LD + 1024 + h * 64;
    const __half* klo0 = qkv_lo + (size_t)(b * S_) * QKV_LD + 1024 + h * 64;
    const __half* vhi0 = khi0 + 1024;

    // ---- prologue: Q tile (hi+lo) + KV tile 0 ----
    #pragma unroll
    for (int f = 0; f < 4; f++) {
        int idx = t + f * 256;
        int row = idx >> 3, seg = idx & 7;
        uint32_t o = row * AST + seg * 16;
        size_t go = (size_t)row * QKV_LD + seg * 8;
        cp_async16(sb + AOFF_QHI + o, qhi + go);
        cp_async16(sb + AOFF_QLO + o, qlo + go);
    }
    cp_kv_tile(sb + AOFF_KV, khi0, klo0, vhi0, t);
    CP_COMMIT();

    float o[8][4];
    #pragma unroll
    for (int i = 0; i < 8; i++)
        #pragma unroll
        for (int j = 0; j < 4; j++) o[i][j] = 0.f;
    float m0 = -INFINITY, m1 = -INFINITY, l0 = 0.f, l1 = 0.f;

    int r = lane >> 2, q2 = (lane & 3) * 2;
    int grow0 = qt * 128 + wid * 16 + r;
    int grow1 = grow0 + 8;

    // ldmatrix addressing
    int arow = wid * 16 + (lane & 15);
    int acolsel = (lane >> 4) * 8;
    int krow4 = ((lane >> 4) & 1) * 8 + (lane & 7);    // + pair*16
    int kcolsel = ((lane >> 3) & 1) * 8;
    int vrow4 = lane & 15;                             // + ksIdx*16
    int vcolsel = ((lane >> 4) & 1) * 16;              // bytes, + pair*32

    int nkt = 2 * qt + 2;
    for (int kt = 0; kt < nkt; kt++) {
        if (kt + 1 < nkt) {
            size_t koff = (size_t)((kt + 1) * 64) * QKV_LD;
            cp_kv_tile(sb + AOFF_KV + ((kt + 1) & 1) * KV_STAGE,
                       khi0 + koff, klo0 + koff, vhi0 + koff, t);
            CP_COMMIT();
            asm volatile("cp.async.wait_group 1;");
        } else {
            asm volatile("cp.async.wait_group 0;");
        }
        __syncthreads();

        uint32_t kvb = sb + AOFF_KV + (kt & 1) * KV_STAGE;
        uint32_t kHiB = kvb, kLoB = kvb + 64 * AST;
        uint32_t vHiB = kvb + 2 * 64 * AST;

        // ---- scores S = Q K^T (3 passes, fp16 => ~2^-22 error) ----
        float s[8][4];
        #pragma unroll
        for (int i = 0; i < 8; i++)
            #pragma unroll
            for (int j = 0; j < 4; j++) s[i][j] = 0.f;

        #pragma unroll
        for (int ksIdx = 0; ksIdx < 4; ksIdx++) {
            int k0 = ksIdx * 16;
            int acol = k0 + acolsel;
            int bcol = k0 + kcolsel;
            uint32_t qh[4], ql[4];
            ldsm_x4(qh, sb + AOFF_QHI + arow * AST + acol * 2);
            ldsm_x4(ql, sb + AOFF_QLO + arow * AST + acol * 2);
            uint32_t kh[8][2], kl[8][2];
            #pragma unroll
            for (int p = 0; p < 4; p++) {
                uint32_t th[4], tl[4];
                ldsm_x4(th, kHiB + (krow4 + p * 16) * AST + bcol * 2);
                ldsm_x4(tl, kLoB + (krow4 + p * 16) * AST + bcol * 2);
                kh[2*p][0] = th[0]; kh[2*p][1] = th[1];
                kh[2*p+1][0] = th[2]; kh[2*p+1][1] = th[3];
                kl[2*p][0] = tl[0]; kl[2*p][1] = tl[1];
                kl[2*p+1][0] = tl[2]; kl[2*p+1][1] = tl[3];
            }
            #pragma unroll
            for (int nt = 0; nt < 8; nt++) {
                mma16816(s[nt], qh, kh[nt]);
                mma16816(s[nt], ql, kh[nt]);
                mma16816(s[nt], qh, kl[nt]);
            }
        }

        // ---- causal mask (diagonal tiles only) ----
        if (kt >= 2 * qt) {
            #pragma unroll
            for (int nt = 0; nt < 8; nt++) {
                int gc = kt * 64 + nt * 8 + q2;
                if (gc > grow0)     s[nt][0] = -INFINITY;
                if (gc + 1 > grow0) s[nt][1] = -INFINITY;
                if (gc > grow1)     s[nt][2] = -INFINITY;
                if (gc + 1 > grow1) s[nt][3] = -INFINITY;
            }
        }

        // ---- online softmax ----
        float mx0 = -INFINITY, mx1 = -INFINITY;
        #pragma unroll
        for (int nt = 0; nt < 8; nt++) {
            mx0 = fmaxf(mx0, fmaxf(s[nt][0], s[nt][1]));
            mx1 = fmaxf(mx1, fmaxf(s[nt][2], s[nt][3]));
        }
        mx0 = fmaxf(mx0, __shfl_xor_sync(0xffffffffu, mx0, 1));
        mx0 = fmaxf(mx0, __shfl_xor_sync(0xffffffffu, mx0, 2));
        mx1 = fmaxf(mx1, __shfl_xor_sync(0xffffffffu, mx1, 1));
        mx1 = fmaxf(mx1, __shfl_xor_sync(0xffffffffu, mx1, 2));
        float mn0 = fmaxf(m0, mx0), mn1 = fmaxf(m1, mx1);
        float c0 = __expf(m0 - mn0), c1 = __expf(m1 - mn1);
        float ps0 = 0.f, ps1 = 0.f;
        #pragma unroll
        for (int nt = 0; nt < 8; nt++) {
            s[nt][0] = __expf(s[nt][0] - mn0);
            s[nt][1] = __expf(s[nt][1] - mn0);
            s[nt][2] = __expf(s[nt][2] - mn1);
            s[nt][3] = __expf(s[nt][3] - mn1);
            ps0 += s[nt][0] + s[nt][1];
            ps1 += s[nt][2] + s[nt][3];
        }
        ps0 += __shfl_xor_sync(0xffffffffu, ps0, 1);
        ps0 += __shfl_xor_sync(0xffffffffu, ps0, 2);
        ps1 += __shfl_xor_sync(0xffffffffu, ps1, 1);
        ps1 += __shfl_xor_sync(0xffffffffu, ps1, 2);
        l0 = l0 * c0 + ps0;
        l1 = l1 * c1 + ps1;
        m0 = mn0; m1 = mn1;
        #pragma unroll
        for (int dt = 0; dt < 8; dt++) {
            o[dt][0] *= c0; o[dt][1] *= c0;
            o[dt][2] *= c1; o[dt][3] *= c1;
        }

        // ---- O += P @ Vhi (P fp16 in regs; V via x4.trans pairs) ----
        #pragma unroll
        for (int ksIdx = 0; ksIdx < 4; ksIdx++) {
            uint32_t a[4];
            a[0] = packh2(s[2*ksIdx][0],   s[2*ksIdx][1]);
            a[1] = packh2(s[2*ksIdx][2],   s[2*ksIdx][3]);
            a[2] = packh2(s[2*ksIdx+1][0], s[2*ksIdx+1][1]);
            a[3] = packh2(s[2*ksIdx+1][2], s[2*ksIdx+1][3]);
            uint32_t vbase = vHiB + (ksIdx * 16 + vrow4) * AST + vcolsel;
            #pragma unroll
            for (int p = 0; p < 4; p++) {
                uint32_t tv[4];
                ldsm_x4t(tv, vbase + p * 32);
                mma16816(o[2*p],   a, tv);
                mma16816(o[2*p+1], a, tv + 2);
            }
        }
        __syncthreads();   // reads done before next prefetch overwrites
    }

    // ---- epilogue: o/l + residual ----
    float il0 = 1.f / l0, il1 = 1.f / l1;
    int row0 = b * S_ + qt * 128 + wid * 16 + r;
    int row1 = row0 + 8;
    #pragma unroll
    for (int dt = 0; dt < 8; dt++) {
        int col = h * 64 + dt * 8 + q2;
        size_t gi0 = (size_t)row0 * E_ + col;
        size_t gi1 = (size_t)row1 * E_ + col;
        float2 x0 = *(const float2*)(x + gi0);
        float2 x1 = *(const float2*)(x + gi1);
        *(float2*)(xo + gi0) = make_float2(x0.x + o[dt][0] * il0,
                                           x0.y + o[dt][1] * il0);
        *(float2*)(xo + gi1) = make_float2(x1.x + o[dt][2] * il1,
                                           x1.y + o[dt][3] * il1);
    }
}

// ---------------- launcher -------------------------------------------------
extern "C" void kernel_launch(void* const* d_in, const int* in_sizes, int n_in,
                              void* d_out, int out_size) {
    const float* emb   = (const float*)d_in[0];
    const float* Wq    = (const float*)d_in[1];
    const float* bq    = (const float*)d_in[2];
    const float* Wk    = (const float*)d_in[3];
    const float* bk    = (const float*)d_in[4];
    const float* Wv    = (const float*)d_in[5];
    const float* bv    = (const float*)d_in[6];
    const float* ln1_w = (const float*)d_in[7];
    const float* ln1_b = (const float*)d_in[8];
    const float* ln2_w = (const float*)d_in[9];
    const float* ln2_b = (const float*)d_in[10];
    const float* W1    = (const float*)d_in[11];
    const float* b1    = (const float*)d_in[12];
    const float* W2    = (const float*)d_in[13];
    const float* b2    = (const float*)d_in[14];
    float* out = (float*)d_out;

    float *px, *pxo, *py, *pbcat;
    __half *pqh, *pql, *pxhi, *pxlo, *pyhi, *pylo, *phhi, *phlo;
    __half *pwq, *pw1, *pw2;
    cudaGetSymbolAddress((void**)&px,   g_x);
    cudaGetSymbolAddress((void**)&pxo,  g_xo);
    cudaGetSymbolAddress((void**)&py,   g_y);
    cudaGetSymbolAddress((void**)&pbcat,g_bcat);
    cudaGetSymbolAddress((void**)&pqh,  g_qkv_hi);
    cudaGetSymbolAddress((void**)&pql,  g_qkv_lo);
    cudaGetSymbolAddress((void**)&pxhi, g_xhi);
    cudaGetSymbolAddress((void**)&pxlo, g_xlo);
    cudaGetSymbolAddress((void**)&pyhi, g_yhi);
    cudaGetSymbolAddress((void**)&pylo, g_ylo);
    cudaGetSymbolAddress((void**)&phhi, g_hhi);
    cudaGetSymbolAddress((void**)&phlo, g_hlo);
    cudaGetSymbolAddress((void**)&pwq,  g_wqkv);
    cudaGetSymbolAddress((void**)&pw1,  g_w1t);
    cudaGetSymbolAddress((void**)&pw2,  g_w2t);

    cudaFuncSetAttribute(gemm_mma,
                         cudaFuncAttributeMaxDynamicSharedMemorySize, GEMM_SMEM);
    cudaFuncSetAttribute(attn_mma,
                         cudaFuncAttributeMaxDynamicSharedMemorySize, ATTN_SMEM);

    // launch 0: all prep (transposes + bias concat) in one kernel
    prep_kernel<<<11276, dim3(32, 8)>>>(Wq, Wk, Wv, W1, W2, bq, bk, bv,
                                        pwq, pw1, pw2, pbcat);

    // launch 1: LN1 -> x fp32 + hi/lo
    ln_kernel<<<M_, 256>>>(emb, ln1_w, ln1_b, px, pxhi, pxlo);

    // launch 2: fused QKV (scaled q) -> fp16 hi/lo
    gemm_mma<<<dim3(NQKV_/128, M_/128), 256, GEMM_SMEM>>>(
        pxhi, pxlo, pwq, pbcat, nullptr, nullptr, pqh, pql,
        E_, NQKV_, 3);

    // launch 3: attention + residual -> g_xo
    attn_mma<<<dim3(S_/128, H_, B_), 256, ATTN_SMEM>>>(pqh, pql, px, pxo);

    // launch 4: LN2 -> y fp32 + hi/lo
    ln_kernel<<<M_, 256>>>(pxo, ln2_w, ln2_b, py, pyhi, pylo);

    // launch 5: FFN1: h = relu(y @ W1 + b1) -> fp16 hi/lo
    gemm_mma<<<dim3(HID_/128, M_/128), 256, GEMM_SMEM>>>(
        pyhi, pylo, pw1, b1, nullptr, nullptr, phhi, phlo,
        E_, HID_, 1);

    // launch 6: FFN2: out = y + h @ W2 + b2
    gemm_mma<<<dim3(E_/128, M_/128), 256, GEMM_SMEM>>>(
        phhi, phlo, pw2, b2, py, out, nullptr, nullptr,
        HID_, E_, 2);
}

// round 8
// speedup vs baseline: 2.0188x; 1.3407x over previous
#include <cuda_runtime.h>
#include <cuda_fp16.h>
#include <cstdint>
#include <math.h>

// ---------------- problem constants ----------------
constexpr int B_  = 2;
constexpr int S_  = 2048;
constexpr int E_  = 1024;
constexpr int H_  = 16;
constexpr int DK_ = 64;
constexpr int HID_= 4096;
constexpr int M_  = B_ * S_;       // 4096 rows
constexpr int NQKV_ = 3 * E_;      // 3072 fused qkv output cols
constexpr int QKV_LD = NQKV_;

// ================= PTX helpers (base sm_103: mma.sync/ldmatrix/cp.async) ==
__device__ __forceinline__ uint32_t smem_to_u32(const void* p) {
    uint32_t a;
    asm("{ .reg .u64 t; cvta.to.shared.u64 t, %1; cvt.u32.u64 %0, t; }"
        : "=r"(a) : "l"(p));
    return a;
}
__device__ __forceinline__ void mma16816(float* d, const uint32_t* a, const uint32_t* b) {
    asm volatile("mma.sync.aligned.m16n8k16.row.col.f32.f16.f16.f32 "
        "{%0,%1,%2,%3}, {%4,%5,%6,%7}, {%8,%9}, {%0,%1,%2,%3};"
        : "+f"(d[0]), "+f"(d[1]), "+f"(d[2]), "+f"(d[3])
        : "r"(a[0]), "r"(a[1]), "r"(a[2]), "r"(a[3]), "r"(b[0]), "r"(b[1]));
}
__device__ __forceinline__ void ldsm_x4(uint32_t* r, uint32_t addr) {
    asm volatile("ldmatrix.sync.aligned.m8n8.x4.shared.b16 {%0,%1,%2,%3}, [%4];"
        : "=r"(r[0]), "=r"(r[1]), "=r"(r[2]), "=r"(r[3]) : "r"(addr));
}
__device__ __forceinline__ void ldsm_x4t(uint32_t* r, uint32_t addr) {
    asm volatile("ldmatrix.sync.aligned.m8n8.x4.trans.shared.b16 {%0,%1,%2,%3}, [%4];"
        : "=r"(r[0]), "=r"(r[1]), "=r"(r[2]), "=r"(r[3]) : "r"(addr));
}
__device__ __forceinline__ void cp_async16(uint32_t dst, const void* src) {
    asm volatile("cp.async.cg.shared.global [%0], [%1], 16;" :: "r"(dst), "l"(src));
}
#define CP_COMMIT() asm volatile("cp.async.commit_group;")
__device__ __forceinline__ uint32_t packh2(float a, float b) {
    __half2 h = __floats2half2_rn(a, b);
    return *(uint32_t*)&h;
}

// ---------------- scratch (device globals) --------------------------------
__device__ __align__(16) float g_x  [M_ * E_];
__device__ __align__(16) float g_xo [M_ * E_];
__device__ __align__(16) float g_y  [M_ * E_];
__device__ __align__(16) __half g_qkv_hi[M_ * NQKV_], g_qkv_lo[M_ * NQKV_];
__device__ __align__(16) __half g_xhi[M_ * E_],  g_xlo[M_ * E_];
__device__ __align__(16) __half g_yhi[M_ * E_];
__device__ __align__(16) __half g_hhi[M_ * HID_];
__device__ __align__(16) __half g_wqkv[NQKV_ * E_];     // weights: hi only
__device__ __align__(16) __half g_w1t[HID_ * E_];
__device__ __align__(16) __half g_w2t[E_ * HID_];
__device__ float g_bcat[NQKV_];

// ---------------- merged prep: weight transposes (hi only) + bias concat ---
__device__ __forceinline__ void transpose_tile(
        const float* __restrict__ in, __half* __restrict__ oh,
        int R, int C, int c0, int r0, float scale, int tx, int ty) {
    __shared__ float tile[32][33];
    #pragma unroll
    for (int j = 0; j < 4; j++)
        tile[ty + j * 8][tx] = in[(size_t)(r0 + ty + j * 8) * C + c0 + tx];
    __syncthreads();
    #pragma unroll
    for (int j = 0; j < 4; j++) {
        float v = tile[tx][ty + j * 8] * scale;
        oh[(size_t)(c0 + ty + j * 8) * R + r0 + tx] = __float2half_rn(v);
    }
}

__global__ void prep_kernel(const float* __restrict__ Wq, const float* __restrict__ Wk,
                            const float* __restrict__ Wv, const float* __restrict__ W1,
                            const float* __restrict__ W2,
                            const float* __restrict__ bq, const float* __restrict__ bk,
                            const float* __restrict__ bv,
                            __half* __restrict__ wqkv,
                            __half* __restrict__ w1t, __half* __restrict__ w2t,
                            float* __restrict__ bcat) {
    int id = blockIdx.x;
    int tx = threadIdx.x, ty = threadIdx.y;
    if (id < 3072) {
        int which = id >> 10;                  // 0=q,1=k,2=v
        int local = id & 1023;
        int z = local >> 6;                    // head
        int rem = local & 63;
        int cx = rem & 1, ry = rem >> 1;
        const float* src = (which == 0) ? Wq : (which == 1) ? Wk : Wv;
        float scale = (which == 0) ? 0.125f : 1.f;
        transpose_tile(src + (size_t)z * E_ * DK_,
                       wqkv + (size_t)which * 1024 * E_ + (size_t)z * DK_ * E_,
                       E_, DK_, cx * 32, ry * 32, scale, tx, ty);
    } else if (id < 7168) {
        int local = id - 3072;
        int cx = local & 127, ry = local >> 7;
        transpose_tile(W1, w1t, E_, HID_, cx * 32, ry * 32, 1.f, tx, ty);
    } else if (id < 11264) {
        int local = id - 7168;
        int cx = local & 31, ry = local >> 5;
        transpose_tile(W2, w2t, HID_, E_, cx * 32, ry * 32, 1.f, tx, ty);
    } else {
        int n = (id - 11264) * 256 + ty * 32 + tx;
        const float* src = (n < 1024) ? bq : ((n < 2048) ? bk : bv);
        float sc = (n < 1024) ? 0.125f : 1.f;
        bcat[n] = src[n & 1023] * sc;
    }
}

// ---------------- LayerNorm: fp32 out + fp16 hi (+optional lo) -------------
__global__ void ln_kernel(const float* __restrict__ in,
                          const float* __restrict__ w,
                          const float* __restrict__ b,
                          float* __restrict__ out,
                          __half* __restrict__ ohi,
                          __half* __restrict__ olo) {
    int row = blockIdx.x;
    int t = threadIdx.x;
    const float4* ip = (const float4*)(in + (size_t)row * E_);
    float4 v = ip[t];
    float s  = v.x + v.y + v.z + v.w;
    float sq = v.x*v.x + v.y*v.y + v.z*v.z + v.w*v.w;
    #pragma unroll
    for (int o = 16; o; o >>= 1) {
        s  += __shfl_xor_sync(0xffffffffu, s,  o);
        sq += __shfl_xor_sync(0xffffffffu, sq, o);
    }
    __shared__ float ss[8], ssq[8];
    __shared__ float mu_s, inv_s;
    if ((t & 31) == 0) { ss[t >> 5] = s; ssq[t >> 5] = sq; }
    __syncthreads();
    if (t < 32) {
        float s2  = (t < 8) ? ss[t]  : 0.f;
        float sq2 = (t < 8) ? ssq[t] : 0.f;
        #pragma unroll
        for (int o = 4; o; o >>= 1) {
            s2  += __shfl_xor_sync(0xffffffffu, s2,  o);
            sq2 += __shfl_xor_sync(0xffffffffu, sq2, o);
        }
        if (t == 0) {
            float mu  = s2 * (1.f / E_);
            float var = sq2 * (1.f / E_) - mu * mu;
            mu_s  = mu;
            inv_s = rsqrtf(var + 1e-5f);
        }
    }
    __syncthreads();
    float mu = mu_s, inv = inv_s;
    float4 wv = ((const float4*)w)[t];
    float4 bv = ((const float4*)b)[t];
    float4 o4;
    o4.x = (v.x - mu) * inv * wv.x + bv.x;
    o4.y = (v.y - mu) * inv * wv.y + bv.y;
    o4.z = (v.z - mu) * inv * wv.z + bv.z;
    o4.w = (v.w - mu) * inv * wv.w + bv.w;
    ((float4*)(out + (size_t)row * E_))[t] = o4;
    __half h0 = __float2half_rn(o4.x), h1 = __float2half_rn(o4.y);
    __half h2 = __float2half_rn(o4.z), h3 = __float2half_rn(o4.w);
    __half2 hp0; hp0.x = h0; hp0.y = h1;
    __half2 hp1; hp1.x = h2; hp1.y = h3;
    ((__half2*)(ohi + (size_t)row * E_))[2*t]   = hp0;
    ((__half2*)(ohi + (size_t)row * E_))[2*t+1] = hp1;
    if (olo) {
        __half2 lp0, lp1;
        lp0.x = __float2half_rn(o4.x - __half2float(h0));
        lp0.y = __float2half_rn(o4.y - __half2float(h1));
        lp1.x = __float2half_rn(o4.z - __half2float(h2));
        lp1.y = __float2half_rn(o4.w - __half2float(h3));
        ((__half2*)(olo + (size_t)row * E_))[2*t]   = lp0;
        ((__half2*)(olo + (size_t)row * E_))[2*t+1] = lp1;
    }
}

// ---------------- HMMA GEMM: C[M,N] = (Ahi[+Alo]) @ Bhi^T ------------------
// CTA tile 128x128, 8 warps of 64x32, K chunk 32, 2-stage cp.async pipeline.
// npass: 1 = A hi only | 2 = A hi+lo
// mode 2: fp32 + bias + resid | mode 3: Chi/Clo + bias | mode 4: relu -> Chi only
constexpr int GSTRIDE_B = 80;                // bytes per smem row (40 fp16)
constexpr int GTILE_B   = 128 * GSTRIDE_B;   // 10240 per array
constexpr int GBUF_B    = 3 * GTILE_B;       // 30720 per stage (Ahi,Alo,Bhi)
constexpr int GSTAGES   = 2;
constexpr int GEMM_SMEM = GSTAGES * GBUF_B;  // 61440

__global__ __launch_bounds__(256)
void gemm_mma(const __half* __restrict__ Ahi, const __half* __restrict__ Alo,
              const __half* __restrict__ Bhi,
              const float* __restrict__ bias, const float* __restrict__ resid,
              float* __restrict__ Cf,
              __half* __restrict__ Chi, __half* __restrict__ Clo,
              int K, int N, int mode, int npass) {
    extern __shared__ char smraw[];
    uint32_t sb = smem_to_u32(smraw);
    int t = threadIdx.x, lane = t & 31, wid = t >> 5;
    int bm = blockIdx.y * 128, bn = blockIdx.x * 128;
    int wm = wid & 1, wn = wid >> 1;

    const __half* gsrc[3] = {
        Ahi + (size_t)bm * K,
        (npass == 2) ? (Alo + (size_t)bm * K) : nullptr,
        Bhi + (size_t)bn * K };

    float acc[4][4][4];
    #pragma unroll
    for (int i = 0; i < 4; i++)
        #pragma unroll
        for (int j = 0; j < 4; j++)
            #pragma unroll
            for (int e = 0; e < 4; e++) acc[i][j][e] = 0.f;

    int nch = K >> 5;
    int ldrow = t >> 2, ldseg = t & 3;      // 64 rows per 256-thr pass

    // ---- prologue: stage 0 ----
    {
        #pragma unroll
        for (int arr = 0; arr < 3; arr++) {
            if (arr == 1 && npass != 2) continue;
            uint32_t dst = sb + arr * GTILE_B;
            #pragma unroll
            for (int f = 0; f < 2; f++) {
                int row = ldrow + f * 64;
                cp_async16(dst + row * GSTRIDE_B + ldseg * 16,
                           gsrc[arr] + (size_t)row * K + ldseg * 8);
            }
        }
        CP_COMMIT();
    }

    // ldmatrix lane addressing (constant across chunks)
    int arow = wm * 64 + (lane & 15);
    int acolsel = (lane >> 4) * 8;
    int brow4 = wn * 32 + ((lane >> 4) & 1) * 8 + (lane & 7);
    int bcolsel = ((lane >> 3) & 1) * 8;

    for (int c = 0; c < nch; c++) {
        if (c + 1 < nch) {
            int k0 = (c + 1) << 5;
            uint32_t base = sb + ((c + 1) & 1) * GBUF_B;
            #pragma unroll
            for (int arr = 0; arr < 3; arr++) {
                if (arr == 1 && npass != 2) continue;
                uint32_t dst = base + arr * GTILE_B;
                #pragma unroll
                for (int f = 0; f < 2; f++) {
                    int row = ldrow + f * 64;
                    cp_async16(dst + row * GSTRIDE_B + ldseg * 16,
                               gsrc[arr] + (size_t)row * K + k0 + ldseg * 8);
                }
            }
            CP_COMMIT();
            asm volatile("cp.async.wait_group 1;");
        } else {
            asm volatile("cp.async.wait_group 0;");
        }
        __syncthreads();

        uint32_t base = sb + (c & 1) * GBUF_B;
        uint32_t aHiB = base;
        uint32_t aLoB = base + GTILE_B;
        uint32_t bHiB = base + 2 * GTILE_B;

        #pragma unroll
        for (int ks = 0; ks < 2; ks++) {
            int k0 = ks * 16;
            int acol = k0 + acolsel;
            int bcol = k0 + bcolsel;

            uint32_t ah[4][4], bh[4][2];
            #pragma unroll
            for (int mt = 0; mt < 4; mt++)
                ldsm_x4(ah[mt], aHiB + (arow + mt * 16) * GSTRIDE_B + acol * 2);
            #pragma unroll
            for (int p = 0; p < 2; p++) {
                uint32_t tmp[4];
                ldsm_x4(tmp, bHiB + (brow4 + p * 16) * GSTRIDE_B + bcol * 2);
                bh[2*p][0] = tmp[0]; bh[2*p][1] = tmp[1];
                bh[2*p+1][0] = tmp[2]; bh[2*p+1][1] = tmp[3];
            }
            #pragma unroll
            for (int nt = 0; nt < 4; nt++)
                #pragma unroll
                for (int mt = 0; mt < 4; mt++)
                    mma16816(acc[mt][nt], ah[mt], bh[nt]);
            if (npass == 2) {
                uint32_t al[4][4];
                #pragma unroll
                for (int mt = 0; mt < 4; mt++)
                    ldsm_x4(al[mt], aLoB + (arow + mt * 16) * GSTRIDE_B + acol * 2);
                #pragma unroll
                for (int nt = 0; nt < 4; nt++)
                    #pragma unroll
                    for (int mt = 0; mt < 4; mt++)
                        mma16816(acc[mt][nt], al[mt], bh[nt]);
            }
        }
        __syncthreads();
    }

    // ---- epilogue ----
    int r = lane >> 2, q2 = (lane & 3) * 2;
    #pragma unroll
    for (int mt = 0; mt < 4; mt++) {
        int row0 = bm + wm * 64 + mt * 16 + r;
        #pragma unroll
        for (int nt = 0; nt < 4; nt++) {
            int col = bn + wn * 32 + nt * 8 + q2;
            float b0 = bias[col], b1 = bias[col + 1];
            float v0 = acc[mt][nt][0] + b0, v1 = acc[mt][nt][1] + b1;
            float v2 = acc[mt][nt][2] + b0, v3 = acc[mt][nt][3] + b1;
            size_t gi0 = (size_t)row0 * N + col;
            size_t gi1 = gi0 + (size_t)8 * N;
            if (mode == 2) {
                float2 r0 = *(const float2*)(resid + gi0);
                float2 r1 = *(const float2*)(resid + gi1);
                *(float2*)(Cf + gi0) = make_float2(v0 + r0.x, v1 + r0.y);
                *(float2*)(Cf + gi1) = make_float2(v2 + r1.x, v3 + r1.y);
            } else if (mode == 4) {
                v0 = fmaxf(v0, 0.f); v1 = fmaxf(v1, 0.f);
                v2 = fmaxf(v2, 0.f); v3 = fmaxf(v3, 0.f);
                __half2 hp0; hp0.x = __float2half_rn(v0); hp0.y = __float2half_rn(v1);
                __half2 hp1; hp1.x = __float2half_rn(v2); hp1.y = __float2half_rn(v3);
                *(__half2*)(Chi + gi0) = hp0;
                *(__half2*)(Chi + gi1) = hp1;
            } else {   // mode 3
                __half h0 = __float2half_rn(v0), h1 = __float2half_rn(v1);
                __half h2 = __float2half_rn(v2), h3 = __float2half_rn(v3);
                __half2 hp0; hp0.x = h0; hp0.y = h1;
                __half2 hp1; hp1.x = h2; hp1.y = h3;
                *(__half2*)(Chi + gi0) = hp0;
                *(__half2*)(Chi + gi1) = hp1;
                __half2 lp0, lp1;
                lp0.x = __float2half_rn(v0 - __half2float(h0));
                lp0.y = __float2half_rn(v1 - __half2float(h1));
                lp1.x = __float2half_rn(v2 - __half2float(h2));
                lp1.y = __float2half_rn(v3 - __half2float(h3));
                *(__half2*)(Clo + gi0) = lp0;
                *(__half2*)(Clo + gi1) = lp1;
            }
        }
    }
}

// ---------------- HMMA flash attention (fp16) ------------------------------
// CTA: 128 q rows (8 warps x 16), kv tiles of 64, double-buffered cp.async.
// QK^T: 3 passes (score accuracy). PV: 1 pass (P fp16, V hi only).
constexpr int AST = 144;                       // row stride bytes (64 fp16 + pad)
constexpr int AOFF_QHI = 0;
constexpr int AOFF_QLO = 128 * AST;            // 18432
constexpr int AOFF_KV  = 2 * 128 * AST;        // 36864
constexpr int KV_STAGE = 3 * 64 * AST;         // 27648 (Khi,Klo,Vhi)
constexpr int ATTN_SMEM = AOFF_KV + 2 * KV_STAGE;  // 92160

__device__ __forceinline__ void cp_kv_tile(uint32_t base,
        const __half* khi, const __half* klo, const __half* vhi, int t) {
    #pragma unroll
    for (int f = 0; f < 2; f++) {
        int idx = t + f * 256;
        int row = idx >> 3, seg = idx & 7;
        uint32_t o = row * AST + seg * 16;
        size_t go = (size_t)row * QKV_LD + seg * 8;
        cp_async16(base + o,                khi + go);
        cp_async16(base + 64 * AST + o,     klo + go);
        cp_async16(base + 2 * 64 * AST + o, vhi + go);
    }
}

__global__ __launch_bounds__(256)
void attn_mma(const __half* __restrict__ qkv_hi,
              const __half* __restrict__ qkv_lo,
              const float* __restrict__ x,
              float* __restrict__ xo) {
    extern __shared__ char smraw[];
    uint32_t sb = smem_to_u32(smraw);
    int qt = gridDim.x - 1 - blockIdx.x;       // heavy tiles first
    int h = blockIdx.y, b = blockIdx.z;
    int t = threadIdx.x, lane = t & 31, wid = t >> 5;

    const __half* qhi = qkv_hi + (size_t)(b * S_ + qt * 128) * QKV_LD + h * 64;
    const __half* qlo = qkv_lo + (size_t)(b * S_ + qt * 128) * QKV_LD + h * 64;
    const __half* khi0 = qkv_hi + (size_t)(b * S_) * QKV_LD + 1024 + h * 64;
    const __half* klo0 = qkv_lo + (size_t)(b * S_) * QKV_LD + 1024 + h * 64;
    const __half* vhi0 = khi0 + 1024;

    // ---- prologue: Q tile (hi+lo) + KV tile 0 ----
    #pragma unroll
    for (int f = 0; f < 4; f++) {
        int idx = t + f * 256;
        int row = idx >> 3, seg = idx & 7;
        uint32_t o = row * AST + seg * 16;
        size_t go = (size_t)row * QKV_LD + seg * 8;
        cp_async16(sb + AOFF_QHI + o, qhi + go);
        cp_async16(sb + AOFF_QLO + o, qlo + go);
    }
    cp_kv_tile(sb + AOFF_KV, khi0, klo0, vhi0, t);
    CP_COMMIT();

    float o[8][4];
    #pragma unroll
    for (int i = 0; i < 8; i++)
        #pragma unroll
        for (int j = 0; j < 4; j++) o[i][j] = 0.f;
    float m0 = -INFINITY, m1 = -INFINITY, l0 = 0.f, l1 = 0.f;

    int r = lane >> 2, q2 = (lane & 3) * 2;
    int grow0 = qt * 128 + wid * 16 + r;
    int grow1 = grow0 + 8;

    // ldmatrix addressing
    int arow = wid * 16 + (lane & 15);
    int acolsel = (lane >> 4) * 8;
    int krow4 = ((lane >> 4) & 1) * 8 + (lane & 7);    // + pair*16
    int kcolsel = ((lane >> 3) & 1) * 8;
    int vrow4 = lane & 15;                             // + ksIdx*16
    int vcolsel = ((lane >> 4) & 1) * 16;              // bytes, + pair*32

    int nkt = 2 * qt + 2;
    for (int kt = 0; kt < nkt; kt++) {
        if (kt + 1 < nkt) {
            size_t koff = (size_t)((kt + 1) * 64) * QKV_LD;
            cp_kv_tile(sb + AOFF_KV + ((kt + 1) & 1) * KV_STAGE,
                       khi0 + koff, klo0 + koff, vhi0 + koff, t);
            CP_COMMIT();
            asm volatile("cp.async.wait_group 1;");
        } else {
            asm volatile("cp.async.wait_group 0;");
        }
        __syncthreads();

        uint32_t kvb = sb + AOFF_KV + (kt & 1) * KV_STAGE;
        uint32_t kHiB = kvb, kLoB = kvb + 64 * AST;
        uint32_t vHiB = kvb + 2 * 64 * AST;

        // ---- scores S = Q K^T (3 passes, fp16 => ~2^-22 error) ----
        float s[8][4];
        #pragma unroll
        for (int i = 0; i < 8; i++)
            #pragma unroll
            for (int j = 0; j < 4; j++) s[i][j] = 0.f;

        #pragma unroll
        for (int ksIdx = 0; ksIdx < 4; ksIdx++) {
            int k0 = ksIdx * 16;
            int acol = k0 + acolsel;
            int bcol = k0 + kcolsel;
            uint32_t qh[4], ql[4];
            ldsm_x4(qh, sb + AOFF_QHI + arow * AST + acol * 2);
            ldsm_x4(ql, sb + AOFF_QLO + arow * AST + acol * 2);
            uint32_t kh[8][2], kl[8][2];
            #pragma unroll
            for (int p = 0; p < 4; p++) {
                uint32_t th[4], tl[4];
                ldsm_x4(th, kHiB + (krow4 + p * 16) * AST + bcol * 2);
                ldsm_x4(tl, kLoB + (krow4 + p * 16) * AST + bcol * 2);
                kh[2*p][0] = th[0]; kh[2*p][1] = th[1];
                kh[2*p+1][0] = th[2]; kh[2*p+1][1] = th[3];
                kl[2*p][0] = tl[0]; kl[2*p][1] = tl[1];
                kl[2*p+1][0] = tl[2]; kl[2*p+1][1] = tl[3];
            }
            #pragma unroll
            for (int nt = 0; nt < 8; nt++) {
                mma16816(s[nt], qh, kh[nt]);
                mma16816(s[nt], ql, kh[nt]);
                mma16816(s[nt], qh, kl[nt]);
            }
        }

        // ---- causal mask (diagonal tiles only) ----
        if (kt >= 2 * qt) {
            #pragma unroll
            for (int nt = 0; nt < 8; nt++) {
                int gc = kt * 64 + nt * 8 + q2;
                if (gc > grow0)     s[nt][0] = -INFINITY;
                if (gc + 1 > grow0) s[nt][1] = -INFINITY;
                if (gc > grow1)     s[nt][2] = -INFINITY;
                if (gc + 1 > grow1) s[nt][3] = -INFINITY;
            }
        }

        // ---- online softmax ----
        float mx0 = -INFINITY, mx1 = -INFINITY;
        #pragma unroll
        for (int nt = 0; nt < 8; nt++) {
            mx0 = fmaxf(mx0, fmaxf(s[nt][0], s[nt][1]));
            mx1 = fmaxf(mx1, fmaxf(s[nt][2], s[nt][3]));
        }
        mx0 = fmaxf(mx0, __shfl_xor_sync(0xffffffffu, mx0, 1));
        mx0 = fmaxf(mx0, __shfl_xor_sync(0xffffffffu, mx0, 2));
        mx1 = fmaxf(mx1, __shfl_xor_sync(0xffffffffu, mx1, 1));
        mx1 = fmaxf(mx1, __shfl_xor_sync(0xffffffffu, mx1, 2));
        float mn0 = fmaxf(m0, mx0), mn1 = fmaxf(m1, mx1);
        float c0 = __expf(m0 - mn0), c1 = __expf(m1 - mn1);
        float ps0 = 0.f, ps1 = 0.f;
        #pragma unroll
        for (int nt = 0; nt < 8; nt++) {
            s[nt][0] = __expf(s[nt][0] - mn0);
            s[nt][1] = __expf(s[nt][1] - mn0);
            s[nt][2] = __expf(s[nt][2] - mn1);
            s[nt][3] = __expf(s[nt][3] - mn1);
            ps0 += s[nt][0] + s[nt][1];
            ps1 += s[nt][2] + s[nt][3];
        }
        ps0 += __shfl_xor_sync(0xffffffffu, ps0, 1);
        ps0 += __shfl_xor_sync(0xffffffffu, ps0, 2);
        ps1 += __shfl_xor_sync(0xffffffffu, ps1, 1);
        ps1 += __shfl_xor_sync(0xffffffffu, ps1, 2);
        l0 = l0 * c0 + ps0;
        l1 = l1 * c1 + ps1;
        m0 = mn0; m1 = mn1;
        #pragma unroll
        for (int dt = 0; dt < 8; dt++) {
            o[dt][0] *= c0; o[dt][1] *= c0;
            o[dt][2] *= c1; o[dt][3] *= c1;
        }

        // ---- O += P @ Vhi (P fp16 in regs; V via x4.trans pairs) ----
        #pragma unroll
        for (int ksIdx = 0; ksIdx < 4; ksIdx++) {
            uint32_t a[4];
            a[0] = packh2(s[2*ksIdx][0],   s[2*ksIdx][1]);
            a[1] = packh2(s[2*ksIdx][2],   s[2*ksIdx][3]);
            a[2] = packh2(s[2*ksIdx+1][0], s[2*ksIdx+1][1]);
            a[3] = packh2(s[2*ksIdx+1][2], s[2*ksIdx+1][3]);
            uint32_t vbase = vHiB + (ksIdx * 16 + vrow4) * AST + vcolsel;
            #pragma unroll
            for (int p = 0; p < 4; p++) {
                uint32_t tv[4];
                ldsm_x4t(tv, vbase + p * 32);
                mma16816(o[2*p],   a, tv);
                mma16816(o[2*p+1], a, tv + 2);
            }
        }
        __syncthreads();   // reads done before next prefetch overwrites
    }

    // ---- epilogue: o/l + residual ----
    float il0 = 1.f / l0, il1 = 1.f / l1;
    int row0 = b * S_ + qt * 128 + wid * 16 + r;
    int row1 = row0 + 8;
    #pragma unroll
    for (int dt = 0; dt < 8; dt++) {
        int col = h * 64 + dt * 8 + q2;
        size_t gi0 = (size_t)row0 * E_ + col;
        size_t gi1 = (size_t)row1 * E_ + col;
        float2 x0 = *(const float2*)(x + gi0);
        float2 x1 = *(const float2*)(x + gi1);
        *(float2*)(xo + gi0) = make_float2(x0.x + o[dt][0] * il0,
                                           x0.y + o[dt][1] * il0);
        *(float2*)(xo + gi1) = make_float2(x1.x + o[dt][2] * il1,
                                           x1.y + o[dt][3] * il1);
    }
}

// ---------------- launcher -------------------------------------------------
extern "C" void kernel_launch(void* const* d_in, const int* in_sizes, int n_in,
                              void* d_out, int out_size) {
    const float* emb   = (const float*)d_in[0];
    const float* Wq    = (const float*)d_in[1];
    const float* bq    = (const float*)d_in[2];
    const float* Wk    = (const float*)d_in[3];
    const float* bk    = (const float*)d_in[4];
    const float* Wv    = (const float*)d_in[5];
    const float* bv    = (const float*)d_in[6];
    const float* ln1_w = (const float*)d_in[7];
    const float* ln1_b = (const float*)d_in[8];
    const float* ln2_w = (const float*)d_in[9];
    const float* ln2_b = (const float*)d_in[10];
    const float* W1    = (const float*)d_in[11];
    const float* b1    = (const float*)d_in[12];
    const float* W2    = (const float*)d_in[13];
    const float* b2    = (const float*)d_in[14];
    float* out = (float*)d_out;

    float *px, *pxo, *py, *pbcat;
    __half *pqh, *pql, *pxhi, *pxlo, *pyhi, *phhi;
    __half *pwq, *pw1, *pw2;
    cudaGetSymbolAddress((void**)&px,   g_x);
    cudaGetSymbolAddress((void**)&pxo,  g_xo);
    cudaGetSymbolAddress((void**)&py,   g_y);
    cudaGetSymbolAddress((void**)&pbcat,g_bcat);
    cudaGetSymbolAddress((void**)&pqh,  g_qkv_hi);
    cudaGetSymbolAddress((void**)&pql,  g_qkv_lo);
    cudaGetSymbolAddress((void**)&pxhi, g_xhi);
    cudaGetSymbolAddress((void**)&pxlo, g_xlo);
    cudaGetSymbolAddress((void**)&pyhi, g_yhi);
    cudaGetSymbolAddress((void**)&phhi, g_hhi);
    cudaGetSymbolAddress((void**)&pwq,  g_wqkv);
    cudaGetSymbolAddress((void**)&pw1,  g_w1t);
    cudaGetSymbolAddress((void**)&pw2,  g_w2t);

    cudaFuncSetAttribute(gemm_mma,
                         cudaFuncAttributeMaxDynamicSharedMemorySize, GEMM_SMEM);
    cudaFuncSetAttribute(attn_mma,
                         cudaFuncAttributeMaxDynamicSharedMemorySize, ATTN_SMEM);

    // launch 0: all prep (transposes + bias concat) in one kernel
    prep_kernel<<<11276, dim3(32, 8)>>>(Wq, Wk, Wv, W1, W2, bq, bk, bv,
                                        pwq, pw1, pw2, pbcat);

    // launch 1: LN1 -> x fp32 + hi/lo (lo needed: QKV is 2-pass)
    ln_kernel<<<M_, 256>>>(emb, ln1_w, ln1_b, px, pxhi, pxlo);

    // launch 2: fused QKV (scaled q) -> fp16 hi/lo  [2-pass, protects softmax]
    gemm_mma<<<dim3(NQKV_/128, M_/128), 256, GEMM_SMEM>>>(
        pxhi, pxlo, pwq, pbcat, nullptr, nullptr, pqh, pql,
        E_, NQKV_, 3, 2);

    // launch 3: attention + residual -> g_xo
    attn_mma<<<dim3(S_/128, H_, B_), 256, ATTN_SMEM>>>(pqh, pql, px, pxo);

    // launch 4: LN2 -> y fp32 + hi only (FFN1 single-pass)
    ln_kernel<<<M_, 256>>>(pxo, ln2_w, ln2_b, py, pyhi, nullptr);

    // launch 5: FFN1: h = relu(y @ W1 + b1) -> hi only  [1-pass]
    gemm_mma<<<dim3(HID_/128, M_/128), 256, GEMM_SMEM>>>(
        pyhi, nullptr, pw1, b1, nullptr, nullptr, phhi, nullptr,
        E_, HID_, 4, 1);

    // launch 6: FFN2: out = y + h @ W2 + b2  [1-pass]
    gemm_mma<<<dim3(E_/128, M_/128), 256, GEMM_SMEM>>>(
        phhi, nullptr, pw2, b2, py, out, nullptr, nullptr,
        HID_, E_, 2, 1);
}

// round 9
// speedup vs baseline: 2.2756x; 1.1272x over previous
#include <cuda_runtime.h>
#include <cuda_fp16.h>
#include <cstdint>
#include <math.h>

// ---------------- problem constants ----------------
constexpr int B_  = 2;
constexpr int S_  = 2048;
constexpr int E_  = 1024;
constexpr int H_  = 16;
constexpr int DK_ = 64;
constexpr int HID_= 4096;
constexpr int M_  = B_ * S_;       // 4096 rows
constexpr int NQKV_ = 3 * E_;      // 3072 fused qkv output cols
constexpr int QKV_LD = NQKV_;

// ================= PTX helpers (base sm_103: mma.sync/ldmatrix/cp.async) ==
__device__ __forceinline__ uint32_t smem_to_u32(const void* p) {
    uint32_t a;
    asm("{ .reg .u64 t; cvta.to.shared.u64 t, %1; cvt.u32.u64 %0, t; }"
        : "=r"(a) : "l"(p));
    return a;
}
__device__ __forceinline__ void mma16816(float* d, const uint32_t* a, const uint32_t* b) {
    asm volatile("mma.sync.aligned.m16n8k16.row.col.f32.f16.f16.f32 "
        "{%0,%1,%2,%3}, {%4,%5,%6,%7}, {%8,%9}, {%0,%1,%2,%3};"
        : "+f"(d[0]), "+f"(d[1]), "+f"(d[2]), "+f"(d[3])
        : "r"(a[0]), "r"(a[1]), "r"(a[2]), "r"(a[3]), "r"(b[0]), "r"(b[1]));
}
__device__ __forceinline__ void ldsm_x4(uint32_t* r, uint32_t addr) {
    asm volatile("ldmatrix.sync.aligned.m8n8.x4.shared.b16 {%0,%1,%2,%3}, [%4];"
        : "=r"(r[0]), "=r"(r[1]), "=r"(r[2]), "=r"(r[3]) : "r"(addr));
}
__device__ __forceinline__ void ldsm_x4t(uint32_t* r, uint32_t addr) {
    asm volatile("ldmatrix.sync.aligned.m8n8.x4.trans.shared.b16 {%0,%1,%2,%3}, [%4];"
        : "=r"(r[0]), "=r"(r[1]), "=r"(r[2]), "=r"(r[3]) : "r"(addr));
}
__device__ __forceinline__ void cp_async16(uint32_t dst, const void* src) {
    asm volatile("cp.async.cg.shared.global [%0], [%1], 16;" :: "r"(dst), "l"(src));
}
#define CP_COMMIT() asm volatile("cp.async.commit_group;")
__device__ __forceinline__ uint32_t packh2(float a, float b) {
    __half2 h = __floats2half2_rn(a, b);
    return *(uint32_t*)&h;
}

// ---------------- scratch (device globals) --------------------------------
__device__ __align__(16) float g_x  [M_ * E_];
__device__ __align__(16) float g_xo [M_ * E_];
__device__ __align__(16) float g_y  [M_ * E_];
__device__ __align__(16) __half g_qkv_hi[M_ * NQKV_], g_qkv_lo[M_ * NQKV_];
__device__ __align__(16) __half g_xhi[M_ * E_],  g_xlo[M_ * E_];
__device__ __align__(16) __half g_yhi[M_ * E_];
__device__ __align__(16) __half g_hhi[M_ * HID_];
__device__ __align__(16) __half g_wqkv[NQKV_ * E_];     // weights: hi only
__device__ __align__(16) __half g_w1t[HID_ * E_];
__device__ __align__(16) __half g_w2t[E_ * HID_];
__device__ float g_bcat[NQKV_];

// ---------------- merged prep: weight transposes (hi only) + bias concat ---
__device__ __forceinline__ void transpose_tile(
        const float* __restrict__ in, __half* __restrict__ oh,
        int R, int C, int c0, int r0, float scale, int tx, int ty) {
    __shared__ float tile[32][33];
    #pragma unroll
    for (int j = 0; j < 4; j++)
        tile[ty + j * 8][tx] = in[(size_t)(r0 + ty + j * 8) * C + c0 + tx];
    __syncthreads();
    #pragma unroll
    for (int j = 0; j < 4; j++) {
        float v = tile[tx][ty + j * 8] * scale;
        oh[(size_t)(c0 + ty + j * 8) * R + r0 + tx] = __float2half_rn(v);
    }
}

__global__ void prep_kernel(const float* __restrict__ Wq, const float* __restrict__ Wk,
                            const float* __restrict__ Wv, const float* __restrict__ W1,
                            const float* __restrict__ W2,
                            const float* __restrict__ bq, const float* __restrict__ bk,
                            const float* __restrict__ bv,
                            __half* __restrict__ wqkv,
                            __half* __restrict__ w1t, __half* __restrict__ w2t,
                            float* __restrict__ bcat) {
    int id = blockIdx.x;
    int tx = threadIdx.x, ty = threadIdx.y;
    if (id < 3072) {
        int which = id >> 10;                  // 0=q,1=k,2=v
        int local = id & 1023;
        int z = local >> 6;                    // head
        int rem = local & 63;
        int cx = rem & 1, ry = rem >> 1;
        const float* src = (which == 0) ? Wq : (which == 1) ? Wk : Wv;
        float scale = (which == 0) ? 0.125f : 1.f;
        transpose_tile(src + (size_t)z * E_ * DK_,
                       wqkv + (size_t)which * 1024 * E_ + (size_t)z * DK_ * E_,
                       E_, DK_, cx * 32, ry * 32, scale, tx, ty);
    } else if (id < 7168) {
        int local = id - 3072;
        int cx = local & 127, ry = local >> 7;
        transpose_tile(W1, w1t, E_, HID_, cx * 32, ry * 32, 1.f, tx, ty);
    } else if (id < 11264) {
        int local = id - 7168;
        int cx = local & 31, ry = local >> 5;
        transpose_tile(W2, w2t, HID_, E_, cx * 32, ry * 32, 1.f, tx, ty);
    } else {
        int n = (id - 11264) * 256 + ty * 32 + tx;
        const float* src = (n < 1024) ? bq : ((n < 2048) ? bk : bv);
        float sc = (n < 1024) ? 0.125f : 1.f;
        bcat[n] = src[n & 1023] * sc;
    }
}

// ---------------- LayerNorm: fp32 out + fp16 hi (+optional lo) -------------
__global__ void ln_kernel(const float* __restrict__ in,
                          const float* __restrict__ w,
                          const float* __restrict__ b,
                          float* __restrict__ out,
                          __half* __restrict__ ohi,
                          __half* __restrict__ olo) {
    int row = blockIdx.x;
    int t = threadIdx.x;
    const float4* ip = (const float4*)(in + (size_t)row * E_);
    float4 v = ip[t];
    float s  = v.x + v.y + v.z + v.w;
    float sq = v.x*v.x + v.y*v.y + v.z*v.z + v.w*v.w;
    #pragma unroll
    for (int o = 16; o; o >>= 1) {
        s  += __shfl_xor_sync(0xffffffffu, s,  o);
        sq += __shfl_xor_sync(0xffffffffu, sq, o);
    }
    __shared__ float ss[8], ssq[8];
    __shared__ float mu_s, inv_s;
    if ((t & 31) == 0) { ss[t >> 5] = s; ssq[t >> 5] = sq; }
    __syncthreads();
    if (t < 32) {
        float s2  = (t < 8) ? ss[t]  : 0.f;
        float sq2 = (t < 8) ? ssq[t] : 0.f;
        #pragma unroll
        for (int o = 4; o; o >>= 1) {
            s2  += __shfl_xor_sync(0xffffffffu, s2,  o);
            sq2 += __shfl_xor_sync(0xffffffffu, sq2, o);
        }
        if (t == 0) {
            float mu  = s2 * (1.f / E_);
            float var = sq2 * (1.f / E_) - mu * mu;
            mu_s  = mu;
            inv_s = rsqrtf(var + 1e-5f);
        }
    }
    __syncthreads();
    float mu = mu_s, inv = inv_s;
    float4 wv = ((const float4*)w)[t];
    float4 bv = ((const float4*)b)[t];
    float4 o4;
    o4.x = (v.x - mu) * inv * wv.x + bv.x;
    o4.y = (v.y - mu) * inv * wv.y + bv.y;
    o4.z = (v.z - mu) * inv * wv.z + bv.z;
    o4.w = (v.w - mu) * inv * wv.w + bv.w;
    ((float4*)(out + (size_t)row * E_))[t] = o4;
    __half h0 = __float2half_rn(o4.x), h1 = __float2half_rn(o4.y);
    __half h2 = __float2half_rn(o4.z), h3 = __float2half_rn(o4.w);
    __half2 hp0; hp0.x = h0; hp0.y = h1;
    __half2 hp1; hp1.x = h2; hp1.y = h3;
    ((__half2*)(ohi + (size_t)row * E_))[2*t]   = hp0;
    ((__half2*)(ohi + (size_t)row * E_))[2*t+1] = hp1;
    if (olo) {
        __half2 lp0, lp1;
        lp0.x = __float2half_rn(o4.x - __half2float(h0));
        lp0.y = __float2half_rn(o4.y - __half2float(h1));
        lp1.x = __float2half_rn(o4.z - __half2float(h2));
        lp1.y = __float2half_rn(o4.w - __half2float(h3));
        ((__half2*)(olo + (size_t)row * E_))[2*t]   = lp0;
        ((__half2*)(olo + (size_t)row * E_))[2*t+1] = lp1;
    }
}

// ---------------- HMMA GEMM: C[M,N] = (Ahi[+Alo]) @ Bhi^T ------------------
// CTA tile 128x128, 8 warps of 64x32, K chunk 64, 2-stage cp.async pipeline.
// npass: 1 = A hi only | 2 = A hi+lo; blocks with bn >= vcol drop to 1-pass
// (and skip the lo output store) — used for the V third of the QKV GEMM.
// mode 2: fp32 + bias + resid | mode 3: Chi/Clo + bias | mode 4: relu -> Chi only
constexpr int GSTRIDE_B = 144;               // bytes per smem row (64 fp16 + pad)
constexpr int GTILE_B   = 128 * GSTRIDE_B;   // 18432 per array
constexpr int GBUF_B    = 3 * GTILE_B;       // 55296 per stage (Ahi,Alo,Bhi)
constexpr int GSTAGES   = 2;
constexpr int GEMM_SMEM = GSTAGES * GBUF_B;  // 110592 -> 2 CTAs/SM

__global__ __launch_bounds__(256)
void gemm_mma(const __half* __restrict__ Ahi, const __half* __restrict__ Alo,
              const __half* __restrict__ Bhi,
              const float* __restrict__ bias, const float* __restrict__ resid,
              float* __restrict__ Cf,
              __half* __restrict__ Chi, __half* __restrict__ Clo,
              int K, int N, int mode, int npass, int vcol) {
    extern __shared__ char smraw[];
    uint32_t sb = smem_to_u32(smraw);
    int t = threadIdx.x, lane = t & 31, wid = t >> 5;
    int bm = blockIdx.y * 128, bn = blockIdx.x * 128;
    int wm = wid & 1, wn = wid >> 1;
    if (bn >= vcol) npass = 1;

    const __half* gsrc[3] = {
        Ahi + (size_t)bm * K,
        (npass == 2) ? (Alo + (size_t)bm * K) : nullptr,
        Bhi + (size_t)bn * K };

    float acc[4][4][4];
    #pragma unroll
    for (int i = 0; i < 4; i++)
        #pragma unroll
        for (int j = 0; j < 4; j++)
            #pragma unroll
            for (int e = 0; e < 4; e++) acc[i][j][e] = 0.f;

    int nch = K >> 6;                       // 64-wide chunks
    int ldrow = t >> 3, ldseg = t & 7;      // 32 rows per 256-thr pass

    // ---- prologue: stage 0 ----
    {
        #pragma unroll
        for (int arr = 0; arr < 3; arr++) {
            if (arr == 1 && npass != 2) continue;
            uint32_t dst = sb + arr * GTILE_B;
            #pragma unroll
            for (int f = 0; f < 4; f++) {
                int row = ldrow + f * 32;
                cp_async16(dst + row * GSTRIDE_B + ldseg * 16,
                           gsrc[arr] + (size_t)row * K + ldseg * 8);
            }
        }
        CP_COMMIT();
    }

    // ldmatrix lane addressing (constant across chunks)
    int arow = wm * 64 + (lane & 15);
    int acolsel = (lane >> 4) * 8;
    int brow4 = wn * 32 + ((lane >> 4) & 1) * 8 + (lane & 7);
    int bcolsel = ((lane >> 3) & 1) * 8;

    for (int c = 0; c < nch; c++) {
        if (c + 1 < nch) {
            int k0 = (c + 1) << 6;
            uint32_t base = sb + ((c + 1) & 1) * GBUF_B;
            #pragma unroll
            for (int arr = 0; arr < 3; arr++) {
                if (arr == 1 && npass != 2) continue;
                uint32_t dst = base + arr * GTILE_B;
                #pragma unroll
                for (int f = 0; f < 4; f++) {
                    int row = ldrow + f * 32;
                    cp_async16(dst + row * GSTRIDE_B + ldseg * 16,
                               gsrc[arr] + (size_t)row * K + k0 + ldseg * 8);
                }
            }
            CP_COMMIT();
            asm volatile("cp.async.wait_group 1;");
        } else {
            asm volatile("cp.async.wait_group 0;");
        }
        __syncthreads();

        uint32_t base = sb + (c & 1) * GBUF_B;
        uint32_t aHiB = base;
        uint32_t aLoB = base + GTILE_B;
        uint32_t bHiB = base + 2 * GTILE_B;

        #pragma unroll
        for (int ks = 0; ks < 4; ks++) {
            int k0 = ks * 16;
            int acol = k0 + acolsel;
            int bcol = k0 + bcolsel;

            uint32_t ah[4][4], bh[4][2];
            #pragma unroll
            for (int mt = 0; mt < 4; mt++)
                ldsm_x4(ah[mt], aHiB + (arow + mt * 16) * GSTRIDE_B + acol * 2);
            #pragma unroll
            for (int p = 0; p < 2; p++) {
                uint32_t tmp[4];
                ldsm_x4(tmp, bHiB + (brow4 + p * 16) * GSTRIDE_B + bcol * 2);
                bh[2*p][0] = tmp[0]; bh[2*p][1] = tmp[1];
                bh[2*p+1][0] = tmp[2]; bh[2*p+1][1] = tmp[3];
            }
            #pragma unroll
            for (int nt = 0; nt < 4; nt++)
                #pragma unroll
                for (int mt = 0; mt < 4; mt++)
                    mma16816(acc[mt][nt], ah[mt], bh[nt]);
            if (npass == 2) {
                uint32_t al[4][4];
                #pragma unroll
                for (int mt = 0; mt < 4; mt++)
                    ldsm_x4(al[mt], aLoB + (arow + mt * 16) * GSTRIDE_B + acol * 2);
                #pragma unroll
                for (int nt = 0; nt < 4; nt++)
                    #pragma unroll
                    for (int mt = 0; mt < 4; mt++)
                        mma16816(acc[mt][nt], al[mt], bh[nt]);
            }
        }
        __syncthreads();
    }

    // ---- epilogue ----
    int r = lane >> 2, q2 = (lane & 3) * 2;
    #pragma unroll
    for (int mt = 0; mt < 4; mt++) {
        int row0 = bm + wm * 64 + mt * 16 + r;
        #pragma unroll
        for (int nt = 0; nt < 4; nt++) {
            int col = bn + wn * 32 + nt * 8 + q2;
            float b0 = bias[col], b1 = bias[col + 1];
            float v0 = acc[mt][nt][0] + b0, v1 = acc[mt][nt][1] + b1;
            float v2 = acc[mt][nt][2] + b0, v3 = acc[mt][nt][3] + b1;
            size_t gi0 = (size_t)row0 * N + col;
            size_t gi1 = gi0 + (size_t)8 * N;
            if (mode == 2) {
                float2 r0 = *(const float2*)(resid + gi0);
                float2 r1 = *(const float2*)(resid + gi1);
                *(float2*)(Cf + gi0) = make_float2(v0 + r0.x, v1 + r0.y);
                *(float2*)(Cf + gi1) = make_float2(v2 + r1.x, v3 + r1.y);
            } else if (mode == 4) {
                v0 = fmaxf(v0, 0.f); v1 = fmaxf(v1, 0.f);
                v2 = fmaxf(v2, 0.f); v3 = fmaxf(v3, 0.f);
                __half2 hp0; hp0.x = __float2half_rn(v0); hp0.y = __float2half_rn(v1);
                __half2 hp1; hp1.x = __float2half_rn(v2); hp1.y = __float2half_rn(v3);
                *(__half2*)(Chi + gi0) = hp0;
                *(__half2*)(Chi + gi1) = hp1;
            } else {   // mode 3
                __half h0 = __float2half_rn(v0), h1 = __float2half_rn(v1);
                __half h2 = __float2half_rn(v2), h3 = __float2half_rn(v3);
                __half2 hp0; hp0.x = h0; hp0.y = h1;
                __half2 hp1; hp1.x = h2; hp1.y = h3;
                *(__half2*)(Chi + gi0) = hp0;
                *(__half2*)(Chi + gi1) = hp1;
                if (npass == 2) {   // q/k need lo; v (1-pass blocks) doesn't
                    __half2 lp0, lp1;
                    lp0.x = __float2half_rn(v0 - __half2float(h0));
                    lp0.y = __float2half_rn(v1 - __half2float(h1));
                    lp1.x = __float2half_rn(v2 - __half2float(h2));
                    lp1.y = __float2half_rn(v3 - __half2float(h3));
                    *(__half2*)(Clo + gi0) = lp0;
                    *(__half2*)(Clo + gi1) = lp1;
                }
            }
        }
    }
}

// ---------------- HMMA flash attention (fp16) ------------------------------
// CTA: 128 q rows (8 warps x 16), kv tiles of 64, double-buffered cp.async.
// QK^T: 3 passes (score accuracy). PV: 1 pass (P fp16, V hi only).
constexpr int AST = 144;                       // row stride bytes (64 fp16 + pad)
constexpr int AOFF_QHI = 0;
constexpr int AOFF_QLO = 128 * AST;            // 18432
constexpr int AOFF_KV  = 2 * 128 * AST;        // 36864
constexpr int KV_STAGE = 3 * 64 * AST;         // 27648 (Khi,Klo,Vhi)
constexpr int ATTN_SMEM = AOFF_KV + 2 * KV_STAGE;  // 92160

__device__ __forceinline__ void cp_kv_tile(uint32_t base,
        const __half* khi, const __half* klo, const __half* vhi, int t) {
    #pragma unroll
    for (int f = 0; f < 2; f++) {
        int idx = t + f * 256;
        int row = idx >> 3, seg = idx & 7;
        uint32_t o = row * AST + seg * 16;
        size_t go = (size_t)row * QKV_LD + seg * 8;
        cp_async16(base + o,                khi + go);
        cp_async16(base + 64 * AST + o,     klo + go);
        cp_async16(base + 2 * 64 * AST + o, vhi + go);
    }
}

__global__ __launch_bounds__(256)
void attn_mma(const __half* __restrict__ qkv_hi,
              const __half* __restrict__ qkv_lo,
              const float* __restrict__ x,
              float* __restrict__ xo) {
    extern __shared__ char smraw[];
    uint32_t sb = smem_to_u32(smraw);
    int qt = gridDim.x - 1 - blockIdx.x;       // heavy tiles first
    int h = blockIdx.y, b = blockIdx.z;
    int t = threadIdx.x, lane = t & 31, wid = t >> 5;

    const __half* qhi = qkv_hi + (size_t)(b * S_ + qt * 128) * QKV_LD + h * 64;
    const __half* qlo = qkv_lo + (size_t)(b * S_ + qt * 128) * QKV_LD + h * 64;
    const __half* khi0 = qkv_hi + (size_t)(b * S_) * QKV_LD + 1024 + h * 64;
    const __half* klo0 = qkv_lo + (size_t)(b * S_) * QKV_LD + 1024 + h * 64;
    const __half* vhi0 = khi0 + 1024;

    // ---- prologue: Q tile (hi+lo) + KV tile 0 ----
    #pragma unroll
    for (int f = 0; f < 4; f++) {
        int idx = t + f * 256;
        int row = idx >> 3, seg = idx & 7;
        uint32_t o = row * AST + seg * 16;
        size_t go = (size_t)row * QKV_LD + seg * 8;
        cp_async16(sb + AOFF_QHI + o, qhi + go);
        cp_async16(sb + AOFF_QLO + o, qlo + go);
    }
    cp_kv_tile(sb + AOFF_KV, khi0, klo0, vhi0, t);
    CP_COMMIT();

    float o[8][4];
    #pragma unroll
    for (int i = 0; i < 8; i++)
        #pragma unroll
        for (int j = 0; j < 4; j++) o[i][j] = 0.f;
    float m0 = -INFINITY, m1 = -INFINITY, l0 = 0.f, l1 = 0.f;

    int r = lane >> 2, q2 = (lane & 3) * 2;
    int grow0 = qt * 128 + wid * 16 + r;
    int grow1 = grow0 + 8;

    // ldmatrix addressing
    int arow = wid * 16 + (lane & 15);
    int acolsel = (lane >> 4) * 8;
    int krow4 = ((lane >> 4) & 1) * 8 + (lane & 7);    // + pair*16
    int kcolsel = ((lane >> 3) & 1) * 8;
    int vrow4 = lane & 15;                             // + ksIdx*16
    int vcolsel = ((lane >> 4) & 1) * 16;              // bytes, + pair*32

    int nkt = 2 * qt + 2;
    for (int kt = 0; kt < nkt; kt++) {
        if (kt + 1 < nkt) {
            size_t koff = (size_t)((kt + 1) * 64) * QKV_LD;
            cp_kv_tile(sb + AOFF_KV + ((kt + 1) & 1) * KV_STAGE,
                       khi0 + koff, klo0 + koff, vhi0 + koff, t);
            CP_COMMIT();
            asm volatile("cp.async.wait_group 1;");
        } else {
            asm volatile("cp.async.wait_group 0;");
        }
        __syncthreads();

        uint32_t kvb = sb + AOFF_KV + (kt & 1) * KV_STAGE;
        uint32_t kHiB = kvb, kLoB = kvb + 64 * AST;
        uint32_t vHiB = kvb + 2 * 64 * AST;

        // ---- scores S = Q K^T (3 passes, fp16 => ~2^-22 error) ----
        float s[8][4];
        #pragma unroll
        for (int i = 0; i < 8; i++)
            #pragma unroll
            for (int j = 0; j < 4; j++) s[i][j] = 0.f;

        #pragma unroll
        for (int ksIdx = 0; ksIdx < 4; ksIdx++) {
            int k0 = ksIdx * 16;
            int acol = k0 + acolsel;
            int bcol = k0 + kcolsel;
            uint32_t qh[4], ql[4];
            ldsm_x4(qh, sb + AOFF_QHI + arow * AST + acol * 2);
            ldsm_x4(ql, sb + AOFF_QLO + arow * AST + acol * 2);
            uint32_t kh[8][2], kl[8][2];
            #pragma unroll
            for (int p = 0; p < 4; p++) {
                uint32_t th[4], tl[4];
                ldsm_x4(th, kHiB + (krow4 + p * 16) * AST + bcol * 2);
                ldsm_x4(tl, kLoB + (krow4 + p * 16) * AST + bcol * 2);
                kh[2*p][0] = th[0]; kh[2*p][1] = th[1];
                kh[2*p+1][0] = th[2]; kh[2*p+1][1] = th[3];
                kl[2*p][0] = tl[0]; kl[2*p][1] = tl[1];
                kl[2*p+1][0] = tl[2]; kl[2*p+1][1] = tl[3];
            }
            #pragma unroll
            for (int nt = 0; nt < 8; nt++) {
                mma16816(s[nt], qh, kh[nt]);
                mma16816(s[nt], ql, kh[nt]);
                mma16816(s[nt], qh, kl[nt]);
            }
        }

        // ---- causal mask (diagonal tiles only) ----
        if (kt >= 2 * qt) {
            #pragma unroll
            for (int nt = 0; nt < 8; nt++) {
                int gc = kt * 64 + nt * 8 + q2;
                if (gc > grow0)     s[nt][0] = -INFINITY;
                if (gc + 1 > grow0) s[nt][1] = -INFINITY;
                if (gc > grow1)     s[nt][2] = -INFINITY;
                if (gc + 1 > grow1) s[nt][3] = -INFINITY;
            }
        }

        // ---- online softmax ----
        float mx0 = -INFINITY, mx1 = -INFINITY;
        #pragma unroll
        for (int nt = 0; nt < 8; nt++) {
            mx0 = fmaxf(mx0, fmaxf(s[nt][0], s[nt][1]));
            mx1 = fmaxf(mx1, fmaxf(s[nt][2], s[nt][3]));
        }
        mx0 = fmaxf(mx0, __shfl_xor_sync(0xffffffffu, mx0, 1));
        mx0 = fmaxf(mx0, __shfl_xor_sync(0xffffffffu, mx0, 2));
        mx1 = fmaxf(mx1, __shfl_xor_sync(0xffffffffu, mx1, 1));
        mx1 = fmaxf(mx1, __shfl_xor_sync(0xffffffffu, mx1, 2));
        float mn0 = fmaxf(m0, mx0), mn1 = fmaxf(m1, mx1);
        float c0 = __expf(m0 - mn0), c1 = __expf(m1 - mn1);
        float ps0 = 0.f, ps1 = 0.f;
        #pragma unroll
        for (int nt = 0; nt < 8; nt++) {
            s[nt][0] = __expf(s[nt][0] - mn0);
            s[nt][1] = __expf(s[nt][1] - mn0);
            s[nt][2] = __expf(s[nt][2] - mn1);
            s[nt][3] = __expf(s[nt][3] - mn1);
            ps0 += s[nt][0] + s[nt][1];
            ps1 += s[nt][2] + s[nt][3];
        }
        ps0 += __shfl_xor_sync(0xffffffffu, ps0, 1);
        ps0 += __shfl_xor_sync(0xffffffffu, ps0, 2);
        ps1 += __shfl_xor_sync(0xffffffffu, ps1, 1);
        ps1 += __shfl_xor_sync(0xffffffffu, ps1, 2);
        l0 = l0 * c0 + ps0;
        l1 = l1 * c1 + ps1;
        m0 = mn0; m1 = mn1;
        #pragma unroll
        for (int dt = 0; dt < 8; dt++) {
            o[dt][0] *= c0; o[dt][1] *= c0;
            o[dt][2] *= c1; o[dt][3] *= c1;
        }

        // ---- O += P @ Vhi (P fp16 in regs; V via x4.trans pairs) ----
        #pragma unroll
        for (int ksIdx = 0; ksIdx < 4; ksIdx++) {
            uint32_t a[4];
            a[0] = packh2(s[2*ksIdx][0],   s[2*ksIdx][1]);
            a[1] = packh2(s[2*ksIdx][2],   s[2*ksIdx][3]);
            a[2] = packh2(s[2*ksIdx+1][0], s[2*ksIdx+1][1]);
            a[3] = packh2(s[2*ksIdx+1][2], s[2*ksIdx+1][3]);
            uint32_t vbase = vHiB + (ksIdx * 16 + vrow4) * AST + vcolsel;
            #pragma unroll
            for (int p = 0; p < 4; p++) {
                uint32_t tv[4];
                ldsm_x4t(tv, vbase + p * 32);
                mma16816(o[2*p],   a, tv);
                mma16816(o[2*p+1], a, tv + 2);
            }
        }
        __syncthreads();   // reads done before next prefetch overwrites
    }

    // ---- epilogue: o/l + residual ----
    float il0 = 1.f / l0, il1 = 1.f / l1;
    int row0 = b * S_ + qt * 128 + wid * 16 + r;
    int row1 = row0 + 8;
    #pragma unroll
    for (int dt = 0; dt < 8; dt++) {
        int col = h * 64 + dt * 8 + q2;
        size_t gi0 = (size_t)row0 * E_ + col;
        size_t gi1 = (size_t)row1 * E_ + col;
        float2 x0 = *(const float2*)(x + gi0);
        float2 x1 = *(const float2*)(x + gi1);
        *(float2*)(xo + gi0) = make_float2(x0.x + o[dt][0] * il0,
                                           x0.y + o[dt][1] * il0);
        *(float2*)(xo + gi1) = make_float2(x1.x + o[dt][2] * il1,
                                           x1.y + o[dt][3] * il1);
    }
}

// ---------------- launcher -------------------------------------------------
extern "C" void kernel_launch(void* const* d_in, const int* in_sizes, int n_in,
                              void* d_out, int out_size) {
    const float* emb   = (const float*)d_in[0];
    const float* Wq    = (const float*)d_in[1];
    const float* bq    = (const float*)d_in[2];
    const float* Wk    = (const float*)d_in[3];
    const float* bk    = (const float*)d_in[4];
    const float* Wv    = (const float*)d_in[5];
    const float* bv    = (const float*)d_in[6];
    const float* ln1_w = (const float*)d_in[7];
    const float* ln1_b = (const float*)d_in[8];
    const float* ln2_w = (const float*)d_in[9];
    const float* ln2_b = (const float*)d_in[10];
    const float* W1    = (const float*)d_in[11];
    const float* b1    = (const float*)d_in[12];
    const float* W2    = (const float*)d_in[13];
    const float* b2    = (const float*)d_in[14];
    float* out = (float*)d_out;

    float *px, *pxo, *py, *pbcat;
    __half *pqh, *pql, *pxhi, *pxlo, *pyhi, *phhi;
    __half *pwq, *pw1, *pw2;
    cudaGetSymbolAddress((void**)&px,   g_x);
    cudaGetSymbolAddress((void**)&pxo,  g_xo);
    cudaGetSymbolAddress((void**)&py,   g_y);
    cudaGetSymbolAddress((void**)&pbcat,g_bcat);
    cudaGetSymbolAddress((void**)&pqh,  g_qkv_hi);
    cudaGetSymbolAddress((void**)&pql,  g_qkv_lo);
    cudaGetSymbolAddress((void**)&pxhi, g_xhi);
    cudaGetSymbolAddress((void**)&pxlo, g_xlo);
    cudaGetSymbolAddress((void**)&pyhi, g_yhi);
    cudaGetSymbolAddress((void**)&phhi, g_hhi);
    cudaGetSymbolAddress((void**)&pwq,  g_wqkv);
    cudaGetSymbolAddress((void**)&pw1,  g_w1t);
    cudaGetSymbolAddress((void**)&pw2,  g_w2t);

    cudaFuncSetAttribute(gemm_mma,
                         cudaFuncAttributeMaxDynamicSharedMemorySize, GEMM_SMEM);
    cudaFuncSetAttribute(attn_mma,
                         cudaFuncAttributeMaxDynamicSharedMemorySize, ATTN_SMEM);

    // launch 0: all prep (transposes + bias concat) in one kernel
    prep_kernel<<<11276, dim3(32, 8)>>>(Wq, Wk, Wv, W1, W2, bq, bk, bv,
                                        pwq, pw1, pw2, pbcat);

    // launch 1: LN1 -> x fp32 + hi/lo (lo needed: q/k are 2-pass)
    ln_kernel<<<M_, 256>>>(emb, ln1_w, ln1_b, px, pxhi, pxlo);

    // launch 2: fused QKV -> fp16 hi/lo; q/k blocks 2-pass, v blocks 1-pass
    gemm_mma<<<dim3(NQKV_/128, M_/128), 256, GEMM_SMEM>>>(
        pxhi, pxlo, pwq, pbcat, nullptr, nullptr, pqh, pql,
        E_, NQKV_, 3, 2, 2048);

    // launch 3: attention + residual -> g_xo
    attn_mma<<<dim3(S_/128, H_, B_), 256, ATTN_SMEM>>>(pqh, pql, px, pxo);

    // launch 4: LN2 -> y fp32 + hi only (FFN1 single-pass)
    ln_kernel<<<M_, 256>>>(pxo, ln2_w, ln2_b, py, pyhi, nullptr);

    // launch 5: FFN1: h = relu(y @ W1 + b1) -> hi only  [1-pass]
    gemm_mma<<<dim3(HID_/128, M_/128), 256, GEMM_SMEM>>>(
        pyhi, nullptr, pw1, b1, nullptr, nullptr, phhi, nullptr,
        E_, HID_, 4, 1, 1 << 30);

    // launch 6: FFN2: out = y + h @ W2 + b2  [1-pass]
    gemm_mma<<<dim3(E_/128, M_/128), 256, GEMM_SMEM>>>(
        phhi, nullptr, pw2, b2, py, out, nullptr, nullptr,
        HID_, E_, 2, 1, 1 << 30);
}

// round 10
// speedup vs baseline: 2.6915x; 1.1828x over previous
#include <cuda_runtime.h>
#include <cuda_fp16.h>
#include <cstdint>
#include <math.h>

// ---------------- problem constants ----------------
constexpr int B_  = 2;
constexpr int S_  = 2048;
constexpr int E_  = 1024;
constexpr int H_  = 16;
constexpr int DK_ = 64;
constexpr int HID_= 4096;
constexpr int M_  = B_ * S_;       // 4096 rows
constexpr int NQKV_ = 3 * E_;      // 3072 fused qkv output cols
constexpr int QKV_LD = NQKV_;

// ================= PTX helpers (base sm_103: mma.sync/ldmatrix/cp.async) ==
__device__ __forceinline__ uint32_t smem_to_u32(const void* p) {
    uint32_t a;
    asm("{ .reg .u64 t; cvta.to.shared.u64 t, %1; cvt.u32.u64 %0, t; }"
        : "=r"(a) : "l"(p));
    return a;
}
__device__ __forceinline__ void mma16816(float* d, const uint32_t* a, const uint32_t* b) {
    asm volatile("mma.sync.aligned.m16n8k16.row.col.f32.f16.f16.f32 "
        "{%0,%1,%2,%3}, {%4,%5,%6,%7}, {%8,%9}, {%0,%1,%2,%3};"
        : "+f"(d[0]), "+f"(d[1]), "+f"(d[2]), "+f"(d[3])
        : "r"(a[0]), "r"(a[1]), "r"(a[2]), "r"(a[3]), "r"(b[0]), "r"(b[1]));
}
__device__ __forceinline__ void ldsm_x4(uint32_t* r, uint32_t addr) {
    asm volatile("ldmatrix.sync.aligned.m8n8.x4.shared.b16 {%0,%1,%2,%3}, [%4];"
        : "=r"(r[0]), "=r"(r[1]), "=r"(r[2]), "=r"(r[3]) : "r"(addr));
}
__device__ __forceinline__ void ldsm_x4t(uint32_t* r, uint32_t addr) {
    asm volatile("ldmatrix.sync.aligned.m8n8.x4.trans.shared.b16 {%0,%1,%2,%3}, [%4];"
        : "=r"(r[0]), "=r"(r[1]), "=r"(r[2]), "=r"(r[3]) : "r"(addr));
}
__device__ __forceinline__ void cp_async16(uint32_t dst, const void* src) {
    asm volatile("cp.async.cg.shared.global [%0], [%1], 16;" :: "r"(dst), "l"(src));
}
#define CP_COMMIT() asm volatile("cp.async.commit_group;")
__device__ __forceinline__ uint32_t packh2(float a, float b) {
    __half2 h = __floats2half2_rn(a, b);
    return *(uint32_t*)&h;
}

// ---------------- scratch (device globals) --------------------------------
__device__ __align__(16) float g_x  [M_ * E_];
__device__ __align__(16) float g_xo [M_ * E_];
__device__ __align__(16) float g_y  [M_ * E_];
__device__ __align__(16) __half g_qkv[M_ * NQKV_];
__device__ __align__(16) __half g_xhi[M_ * E_];
__device__ __align__(16) __half g_yhi[M_ * E_];
__device__ __align__(16) __half g_hhi[M_ * HID_];
__device__ __align__(16) __half g_wqkv[NQKV_ * E_];
__device__ __align__(16) __half g_w1t[HID_ * E_];
__device__ __align__(16) __half g_w2t[E_ * HID_];
__device__ float g_bcat[NQKV_];

// ---------------- merged prep: weight transposes + bias concat -------------
__device__ __forceinline__ void transpose_tile(
        const float* __restrict__ in, __half* __restrict__ oh,
        int R, int C, int c0, int r0, float scale, int tx, int ty) {
    __shared__ float tile[32][33];
    #pragma unroll
    for (int j = 0; j < 4; j++)
        tile[ty + j * 8][tx] = in[(size_t)(r0 + ty + j * 8) * C + c0 + tx];
    __syncthreads();
    #pragma unroll
    for (int j = 0; j < 4; j++) {
        float v = tile[tx][ty + j * 8] * scale;
        oh[(size_t)(c0 + ty + j * 8) * R + r0 + tx] = __float2half_rn(v);
    }
}

__global__ void prep_kernel(const float* __restrict__ Wq, const float* __restrict__ Wk,
                            const float* __restrict__ Wv, const float* __restrict__ W1,
                            const float* __restrict__ W2,
                            const float* __restrict__ bq, const float* __restrict__ bk,
                            const float* __restrict__ bv,
                            __half* __restrict__ wqkv,
                            __half* __restrict__ w1t, __half* __restrict__ w2t,
                            float* __restrict__ bcat) {
    int id = blockIdx.x;
    int tx = threadIdx.x, ty = threadIdx.y;
    if (id < 3072) {
        int which = id >> 10;                  // 0=q,1=k,2=v
        int local = id & 1023;
        int z = local >> 6;                    // head
        int rem = local & 63;
        int cx = rem & 1, ry = rem >> 1;
        const float* src = (which == 0) ? Wq : (which == 1) ? Wk : Wv;
        float scale = (which == 0) ? 0.125f : 1.f;
        transpose_tile(src + (size_t)z * E_ * DK_,
                       wqkv + (size_t)which * 1024 * E_ + (size_t)z * DK_ * E_,
                       E_, DK_, cx * 32, ry * 32, scale, tx, ty);
    } else if (id < 7168) {
        int local = id - 3072;
        int cx = local & 127, ry = local >> 7;
        transpose_tile(W1, w1t, E_, HID_, cx * 32, ry * 32, 1.f, tx, ty);
    } else if (id < 11264) {
        int local = id - 7168;
        int cx = local & 31, ry = local >> 5;
        transpose_tile(W2, w2t, HID_, E_, cx * 32, ry * 32, 1.f, tx, ty);
    } else {
        int n = (id - 11264) * 256 + ty * 32 + tx;
        const float* src = (n < 1024) ? bq : ((n < 2048) ? bk : bv);
        float sc = (n < 1024) ? 0.125f : 1.f;
        bcat[n] = src[n & 1023] * sc;
    }
}

// ---------------- LayerNorm: fp32 out + fp16 hi out ------------------------
__global__ void ln_kernel(const float* __restrict__ in,
                          const float* __restrict__ w,
                          const float* __restrict__ b,
                          float* __restrict__ out,
                          __half* __restrict__ ohi) {
    int row = blockIdx.x;
    int t = threadIdx.x;
    const float4* ip = (const float4*)(in + (size_t)row * E_);
    float4 v = ip[t];
    float s  = v.x + v.y + v.z + v.w;
    float sq = v.x*v.x + v.y*v.y + v.z*v.z + v.w*v.w;
    #pragma unroll
    for (int o = 16; o; o >>= 1) {
        s  += __shfl_xor_sync(0xffffffffu, s,  o);
        sq += __shfl_xor_sync(0xffffffffu, sq, o);
    }
    __shared__ float ss[8], ssq[8];
    __shared__ float mu_s, inv_s;
    if ((t & 31) == 0) { ss[t >> 5] = s; ssq[t >> 5] = sq; }
    __syncthreads();
    if (t < 32) {
        float s2  = (t < 8) ? ss[t]  : 0.f;
        float sq2 = (t < 8) ? ssq[t] : 0.f;
        #pragma unroll
        for (int o = 4; o; o >>= 1) {
            s2  += __shfl_xor_sync(0xffffffffu, s2,  o);
            sq2 += __shfl_xor_sync(0xffffffffu, sq2, o);
        }
        if (t == 0) {
            float mu  = s2 * (1.f / E_);
            float var = sq2 * (1.f / E_) - mu * mu;
            mu_s  = mu;
            inv_s = rsqrtf(var + 1e-5f);
        }
    }
    __syncthreads();
    float mu = mu_s, inv = inv_s;
    float4 wv = ((const float4*)w)[t];
    float4 bv = ((const float4*)b)[t];
    float4 o4;
    o4.x = (v.x - mu) * inv * wv.x + bv.x;
    o4.y = (v.y - mu) * inv * wv.y + bv.y;
    o4.z = (v.z - mu) * inv * wv.z + bv.z;
    o4.w = (v.w - mu) * inv * wv.w + bv.w;
    ((float4*)(out + (size_t)row * E_))[t] = o4;
    __half2 hp0; hp0.x = __float2half_rn(o4.x); hp0.y = __float2half_rn(o4.y);
    __half2 hp1; hp1.x = __float2half_rn(o4.z); hp1.y = __float2half_rn(o4.w);
    ((__half2*)(ohi + (size_t)row * E_))[2*t]   = hp0;
    ((__half2*)(ohi + (size_t)row * E_))[2*t+1] = hp1;
}

// ---------------- HMMA GEMM: C[M,N] = Ahi @ Bhi^T (fp16, 1-pass) -----------
// CTA tile 128x128, 8 warps of 64x32, K chunk 64, 2-stage cp.async pipeline.
// mode 2: fp32 + bias + resid | mode 3: Chi + bias | mode 4: relu -> Chi
constexpr int GSTRIDE_B = 144;               // bytes per smem row (64 fp16 + pad)
constexpr int GTILE_B   = 128 * GSTRIDE_B;   // 18432 per array
constexpr int GBUF_B    = 2 * GTILE_B;       // 36864 per stage (Ahi,Bhi)
constexpr int GSTAGES   = 2;
constexpr int GEMM_SMEM = GSTAGES * GBUF_B;  // 73728

__global__ __launch_bounds__(256)
void gemm_mma(const __half* __restrict__ Ahi, const __half* __restrict__ Bhi,
              const float* __restrict__ bias, const float* __restrict__ resid,
              float* __restrict__ Cf, __half* __restrict__ Chi,
              int K, int N, int mode) {
    extern __shared__ char smraw[];
    uint32_t sb = smem_to_u32(smraw);
    int t = threadIdx.x, lane = t & 31, wid = t >> 5;
    int bm = blockIdx.y * 128, bn = blockIdx.x * 128;
    int wm = wid & 1, wn = wid >> 1;

    const __half* gsrc[2] = { Ahi + (size_t)bm * K, Bhi + (size_t)bn * K };

    float acc[4][4][4];
    #pragma unroll
    for (int i = 0; i < 4; i++)
        #pragma unroll
        for (int j = 0; j < 4; j++)
            #pragma unroll
            for (int e = 0; e < 4; e++) acc[i][j][e] = 0.f;

    int nch = K >> 6;                       // 64-wide chunks
    int ldrow = t >> 3, ldseg = t & 7;      // 32 rows per 256-thr pass

    // ---- prologue: stage 0 ----
    {
        #pragma unroll
        for (int arr = 0; arr < 2; arr++) {
            uint32_t dst = sb + arr * GTILE_B;
            #pragma unroll
            for (int f = 0; f < 4; f++) {
                int row = ldrow + f * 32;
                cp_async16(dst + row * GSTRIDE_B + ldseg * 16,
                           gsrc[arr] + (size_t)row * K + ldseg * 8);
            }
        }
        CP_COMMIT();
    }

    int arow = wm * 64 + (lane & 15);
    int acolsel = (lane >> 4) * 8;
    int brow4 = wn * 32 + ((lane >> 4) & 1) * 8 + (lane & 7);
    int bcolsel = ((lane >> 3) & 1) * 8;

    for (int c = 0; c < nch; c++) {
        if (c + 1 < nch) {
            int k0 = (c + 1) << 6;
            uint32_t base = sb + ((c + 1) & 1) * GBUF_B;
            #pragma unroll
            for (int arr = 0; arr < 2; arr++) {
                uint32_t dst = base + arr * GTILE_B;
                #pragma unroll
                for (int f = 0; f < 4; f++) {
                    int row = ldrow + f * 32;
                    cp_async16(dst + row * GSTRIDE_B + ldseg * 16,
                               gsrc[arr] + (size_t)row * K + k0 + ldseg * 8);
                }
            }
            CP_COMMIT();
            asm volatile("cp.async.wait_group 1;");
        } else {
            asm volatile("cp.async.wait_group 0;");
        }
        __syncthreads();

        uint32_t base = sb + (c & 1) * GBUF_B;
        uint32_t aHiB = base;
        uint32_t bHiB = base + GTILE_B;

        #pragma unroll
        for (int ks = 0; ks < 4; ks++) {
            int k0 = ks * 16;
            int acol = k0 + acolsel;
            int bcol = k0 + bcolsel;

            uint32_t ah[4][4], bh[4][2];
            #pragma unroll
            for (int mt = 0; mt < 4; mt++)
                ldsm_x4(ah[mt], aHiB + (arow + mt * 16) * GSTRIDE_B + acol * 2);
            #pragma unroll
            for (int p = 0; p < 2; p++) {
                uint32_t tmp[4];
                ldsm_x4(tmp, bHiB + (brow4 + p * 16) * GSTRIDE_B + bcol * 2);
                bh[2*p][0] = tmp[0]; bh[2*p][1] = tmp[1];
                bh[2*p+1][0] = tmp[2]; bh[2*p+1][1] = tmp[3];
            }
            #pragma unroll
            for (int nt = 0; nt < 4; nt++)
                #pragma unroll
                for (int mt = 0; mt < 4; mt++)
                    mma16816(acc[mt][nt], ah[mt], bh[nt]);
        }
        __syncthreads();
    }

    // ---- epilogue ----
    int r = lane >> 2, q2 = (lane & 3) * 2;
    #pragma unroll
    for (int mt = 0; mt < 4; mt++) {
        int row0 = bm + wm * 64 + mt * 16 + r;
        #pragma unroll
        for (int nt = 0; nt < 4; nt++) {
            int col = bn + wn * 32 + nt * 8 + q2;
            float b0 = bias[col], b1 = bias[col + 1];
            float v0 = acc[mt][nt][0] + b0, v1 = acc[mt][nt][1] + b1;
            float v2 = acc[mt][nt][2] + b0, v3 = acc[mt][nt][3] + b1;
            size_t gi0 = (size_t)row0 * N + col;
            size_t gi1 = gi0 + (size_t)8 * N;
            if (mode == 2) {
                float2 r0 = *(const float2*)(resid + gi0);
                float2 r1 = *(const float2*)(resid + gi1);
                *(float2*)(Cf + gi0) = make_float2(v0 + r0.x, v1 + r0.y);
                *(float2*)(Cf + gi1) = make_float2(v2 + r1.x, v3 + r1.y);
            } else {
                if (mode == 4) {
                    v0 = fmaxf(v0, 0.f); v1 = fmaxf(v1, 0.f);
                    v2 = fmaxf(v2, 0.f); v3 = fmaxf(v3, 0.f);
                }
                __half2 hp0; hp0.x = __float2half_rn(v0); hp0.y = __float2half_rn(v1);
                __half2 hp1; hp1.x = __float2half_rn(v2); hp1.y = __float2half_rn(v3);
                *(__half2*)(Chi + gi0) = hp0;
                *(__half2*)(Chi + gi1) = hp1;
            }
        }
    }
}

// ---------------- HMMA flash attention (fp16, 1-pass) ----------------------
// CTA: 128 q rows (8 warps x 16), kv tiles of 64, double-buffered cp.async.
constexpr int AST = 144;                       // row stride bytes (64 fp16 + pad)
constexpr int AOFF_Q  = 0;                     // 128 x AST
constexpr int AOFF_KV = 128 * AST;             // 18432
constexpr int KV_STAGE = 2 * 64 * AST;         // 18432 (Khi,Vhi)
constexpr int ATTN_SMEM = AOFF_KV + 2 * KV_STAGE;  // 55296 -> 3 CTAs/SM

__device__ __forceinline__ void cp_kv_tile(uint32_t base,
        const __half* khi, const __half* vhi, int t) {
    #pragma unroll
    for (int f = 0; f < 2; f++) {
        int idx = t + f * 256;
        int row = idx >> 3, seg = idx & 7;
        uint32_t o = row * AST + seg * 16;
        size_t go = (size_t)row * QKV_LD + seg * 8;
        cp_async16(base + o,            khi + go);
        cp_async16(base + 64 * AST + o, vhi + go);
    }
}

__global__ __launch_bounds__(256, 3)
void attn_mma(const __half* __restrict__ qkv,
              const float* __restrict__ x,
              float* __restrict__ xo) {
    extern __shared__ char smraw[];
    uint32_t sb = smem_to_u32(smraw);
    int qt = gridDim.x - 1 - blockIdx.x;       // heavy tiles first
    int h = blockIdx.y, b = blockIdx.z;
    int t = threadIdx.x, lane = t & 31, wid = t >> 5;

    const __half* qsrc = qkv + (size_t)(b * S_ + qt * 128) * QKV_LD + h * 64;
    const __half* khi0 = qkv + (size_t)(b * S_) * QKV_LD + 1024 + h * 64;
    const __half* vhi0 = khi0 + 1024;

    // ---- prologue: Q tile + KV tile 0 ----
    #pragma unroll
    for (int f = 0; f < 4; f++) {
        int idx = t + f * 256;
        int row = idx >> 3, seg = idx & 7;
        cp_async16(sb + AOFF_Q + row * AST + seg * 16,
                   qsrc + (size_t)row * QKV_LD + seg * 8);
    }
    cp_kv_tile(sb + AOFF_KV, khi0, vhi0, t);
    CP_COMMIT();

    float o[8][4];
    #pragma unroll
    for (int i = 0; i < 8; i++)
        #pragma unroll
        for (int j = 0; j < 4; j++) o[i][j] = 0.f;
    float m0 = -INFINITY, m1 = -INFINITY, l0 = 0.f, l1 = 0.f;

    int r = lane >> 2, q2 = (lane & 3) * 2;
    int grow0 = qt * 128 + wid * 16 + r;
    int grow1 = grow0 + 8;

    int arow = wid * 16 + (lane & 15);
    int acolsel = (lane >> 4) * 8;
    int krow4 = ((lane >> 4) & 1) * 8 + (lane & 7);    // + pair*16
    int kcolsel = ((lane >> 3) & 1) * 8;
    int vrow4 = lane & 15;                             // + ksIdx*16
    int vcolsel = ((lane >> 4) & 1) * 16;              // bytes, + pair*32

    int nkt = 2 * qt + 2;
    for (int kt = 0; kt < nkt; kt++) {
        if (kt + 1 < nkt) {
            size_t koff = (size_t)((kt + 1) * 64) * QKV_LD;
            cp_kv_tile(sb + AOFF_KV + ((kt + 1) & 1) * KV_STAGE,
                       khi0 + koff, vhi0 + koff, t);
            CP_COMMIT();
            asm volatile("cp.async.wait_group 1;");
        } else {
            asm volatile("cp.async.wait_group 0;");
        }
        __syncthreads();

        uint32_t kvb = sb + AOFF_KV + (kt & 1) * KV_STAGE;
        uint32_t kHiB = kvb;
        uint32_t vHiB = kvb + 64 * AST;

        // ---- scores S = Q K^T (single pass) ----
        float s[8][4];
        #pragma unroll
        for (int i = 0; i < 8; i++)
            #pragma unroll
            for (int j = 0; j < 4; j++) s[i][j] = 0.f;

        #pragma unroll
        for (int ksIdx = 0; ksIdx < 4; ksIdx++) {
            int k0 = ksIdx * 16;
            int acol = k0 + acolsel;
            int bcol = k0 + kcolsel;
            uint32_t qh[4];
            ldsm_x4(qh, sb + AOFF_Q + arow * AST + acol * 2);
            #pragma unroll
            for (int p = 0; p < 4; p++) {
                uint32_t th[4];
                ldsm_x4(th, kHiB + (krow4 + p * 16) * AST + bcol * 2);
                mma16816(s[2*p],   qh, th);
                mma16816(s[2*p+1], qh, th + 2);
            }
        }

        // ---- causal mask (diagonal tiles only) ----
        if (kt >= 2 * qt) {
            #pragma unroll
            for (int nt = 0; nt < 8; nt++) {
                int gc = kt * 64 + nt * 8 + q2;
                if (gc > grow0)     s[nt][0] = -INFINITY;
                if (gc + 1 > grow0) s[nt][1] = -INFINITY;
                if (gc > grow1)     s[nt][2] = -INFINITY;
                if (gc + 1 > grow1) s[nt][3] = -INFINITY;
            }
        }

        // ---- online softmax ----
        float mx0 = -INFINITY, mx1 = -INFINITY;
        #pragma unroll
        for (int nt = 0; nt < 8; nt++) {
            mx0 = fmaxf(mx0, fmaxf(s[nt][0], s[nt][1]));
            mx1 = fmaxf(mx1, fmaxf(s[nt][2], s[nt][3]));
        }
        mx0 = fmaxf(mx0, __shfl_xor_sync(0xffffffffu, mx0, 1));
        mx0 = fmaxf(mx0, __shfl_xor_sync(0xffffffffu, mx0, 2));
        mx1 = fmaxf(mx1, __shfl_xor_sync(0xffffffffu, mx1, 1));
        mx1 = fmaxf(mx1, __shfl_xor_sync(0xffffffffu, mx1, 2));
        float mn0 = fmaxf(m0, mx0), mn1 = fmaxf(m1, mx1);
        float c0 = __expf(m0 - mn0), c1 = __expf(m1 - mn1);
        float ps0 = 0.f, ps1 = 0.f;
        #pragma unroll
        for (int nt = 0; nt < 8; nt++) {
            s[nt][0] = __expf(s[nt][0] - mn0);
            s[nt][1] = __expf(s[nt][1] - mn0);
            s[nt][2] = __expf(s[nt][2] - mn1);
            s[nt][3] = __expf(s[nt][3] - mn1);
            ps0 += s[nt][0] + s[nt][1];
            ps1 += s[nt][2] + s[nt][3];
        }
        ps0 += __shfl_xor_sync(0xffffffffu, ps0, 1);
        ps0 += __shfl_xor_sync(0xffffffffu, ps0, 2);
        ps1 += __shfl_xor_sync(0xffffffffu, ps1, 1);
        ps1 += __shfl_xor_sync(0xffffffffu, ps1, 2);
        l0 = l0 * c0 + ps0;
        l1 = l1 * c1 + ps1;
        m0 = mn0; m1 = mn1;
        #pragma unroll
        for (int dt = 0; dt < 8; dt++) {
            o[dt][0] *= c0; o[dt][1] *= c0;
            o[dt][2] *= c1; o[dt][3] *= c1;
        }

        // ---- O += P @ Vhi (P fp16 in regs; V via x4.trans pairs) ----
        #pragma unroll
        for (int ksIdx = 0; ksIdx < 4; ksIdx++) {
            uint32_t a[4];
            a[0] = packh2(s[2*ksIdx][0],   s[2*ksIdx][1]);
            a[1] = packh2(s[2*ksIdx][2],   s[2*ksIdx][3]);
            a[2] = packh2(s[2*ksIdx+1][0], s[2*ksIdx+1][1]);
            a[3] = packh2(s[2*ksIdx+1][2], s[2*ksIdx+1][3]);
            uint32_t vbase = vHiB + (ksIdx * 16 + vrow4) * AST + vcolsel;
            #pragma unroll
            for (int p = 0; p < 4; p++) {
                uint32_t tv[4];
                ldsm_x4t(tv, vbase + p * 32);
                mma16816(o[2*p],   a, tv);
                mma16816(o[2*p+1], a, tv + 2);
            }
        }
        __syncthreads();   // reads done before next prefetch overwrites
    }

    // ---- epilogue: o/l + residual ----
    float il0 = 1.f / l0, il1 = 1.f / l1;
    int row0 = b * S_ + qt * 128 + wid * 16 + r;
    int row1 = row0 + 8;
    #pragma unroll
    for (int dt = 0; dt < 8; dt++) {
        int col = h * 64 + dt * 8 + q2;
        size_t gi0 = (size_t)row0 * E_ + col;
        size_t gi1 = (size_t)row1 * E_ + col;
        float2 x0 = *(const float2*)(x + gi0);
        float2 x1 = *(const float2*)(x + gi1);
        *(float2*)(xo + gi0) = make_float2(x0.x + o[dt][0] * il0,
                                           x0.y + o[dt][1] * il0);
        *(float2*)(xo + gi1) = make_float2(x1.x + o[dt][2] * il1,
                                           x1.y + o[dt][3] * il1);
    }
}

// ---------------- launcher -------------------------------------------------
extern "C" void kernel_launch(void* const* d_in, const int* in_sizes, int n_in,
                              void* d_out, int out_size) {
    const float* emb   = (const float*)d_in[0];
    const float* Wq    = (const float*)d_in[1];
    const float* bq    = (const float*)d_in[2];
    const float* Wk    = (const float*)d_in[3];
    const float* bk    = (const float*)d_in[4];
    const float* Wv    = (const float*)d_in[5];
    const float* bv    = (const float*)d_in[6];
    const float* ln1_w = (const float*)d_in[7];
    const float* ln1_b = (const float*)d_in[8];
    const float* ln2_w = (const float*)d_in[9];
    const float* ln2_b = (const float*)d_in[10];
    const float* W1    = (const float*)d_in[11];
    const float* b1    = (const float*)d_in[12];
    const float* W2    = (const float*)d_in[13];
    const float* b2    = (const float*)d_in[14];
    float* out = (float*)d_out;

    float *px, *pxo, *py, *pbcat;
    __half *pqkv, *pxhi, *pyhi, *phhi, *pwq, *pw1, *pw2;
    cudaGetSymbolAddress((void**)&px,   g_x);
    cudaGetSymbolAddress((void**)&pxo,  g_xo);
    cudaGetSymbolAddress((void**)&py,   g_y);
    cudaGetSymbolAddress((void**)&pbcat,g_bcat);
    cudaGetSymbolAddress((void**)&pqkv, g_qkv);
    cudaGetSymbolAddress((void**)&pxhi, g_xhi);
    cudaGetSymbolAddress((void**)&pyhi, g_yhi);
    cudaGetSymbolAddress((void**)&phhi, g_hhi);
    cudaGetSymbolAddress((void**)&pwq,  g_wqkv);
    cudaGetSymbolAddress((void**)&pw1,  g_w1t);
    cudaGetSymbolAddress((void**)&pw2,  g_w2t);

    cudaFuncSetAttribute(gemm_mma,
                         cudaFuncAttributeMaxDynamicSharedMemorySize, GEMM_SMEM);
    cudaFuncSetAttribute(attn_mma,
                         cudaFuncAttributeMaxDynamicSharedMemorySize, ATTN_SMEM);

    // launch 0: all prep (transposes + bias concat) in one kernel
    prep_kernel<<<11276, dim3(32, 8)>>>(Wq, Wk, Wv, W1, W2, bq, bk, bv,
                                        pwq, pw1, pw2, pbcat);

    // launch 1: LN1 -> x fp32 + fp16
    ln_kernel<<<M_, 256>>>(emb, ln1_w, ln1_b, px, pxhi);

    // launch 2: fused QKV (scaled q) -> fp16
    gemm_mma<<<dim3(NQKV_/128, M_/128), 256, GEMM_SMEM>>>(
        pxhi, pwq, pbcat, nullptr, nullptr, pqkv, E_, NQKV_, 3);

    // launch 3: attention + residual -> g_xo
    attn_mma<<<dim3(S_/128, H_, B_), 256, ATTN_SMEM>>>(pqkv, px, pxo);

    // launch 4: LN2 -> y fp32 + fp16
    ln_kernel<<<M_, 256>>>(pxo, ln2_w, ln2_b, py, pyhi);

    // launch 5: FFN1: h = relu(y @ W1 + b1) -> fp16
    gemm_mma<<<dim3(HID_/128, M_/128), 256, GEMM_SMEM>>>(
        pyhi, pw1, b1, nullptr, nullptr, phhi, E_, HID_, 4);

    // launch 6: FFN2: out = y + h @ W2 + b2
    gemm_mma<<<dim3(E_/128, M_/128), 256, GEMM_SMEM>>>(
        phhi, pw2, b2, py, out, nullptr, HID_, E_, 2);
}

// round 11
// speedup vs baseline: 2.8062x; 1.0426x over previous
#include <cuda_runtime.h>
#include <cuda_fp16.h>
#include <cstdint>
#include <math.h>

// ---------------- problem constants ----------------
constexpr int B_  = 2;
constexpr int S_  = 2048;
constexpr int E_  = 1024;
constexpr int H_  = 16;
constexpr int DK_ = 64;
constexpr int HID_= 4096;
constexpr int M_  = B_ * S_;       // 4096 rows
constexpr int NQKV_ = 3 * E_;      // 3072 fused qkv output cols
constexpr int QKV_LD = NQKV_;
constexpr float QSCALE = 0.125f * 1.4426950408889634f;   // 1/sqrt(DK) * log2(e)

// ================= PTX helpers (base sm_103: mma.sync/ldmatrix/cp.async) ==
__device__ __forceinline__ uint32_t smem_to_u32(const void* p) {
    uint32_t a;
    asm("{ .reg .u64 t; cvta.to.shared.u64 t, %1; cvt.u32.u64 %0, t; }"
        : "=r"(a) : "l"(p));
    return a;
}
__device__ __forceinline__ void mma16816(float* d, const uint32_t* a, const uint32_t* b) {
    asm volatile("mma.sync.aligned.m16n8k16.row.col.f32.f16.f16.f32 "
        "{%0,%1,%2,%3}, {%4,%5,%6,%7}, {%8,%9}, {%0,%1,%2,%3};"
        : "+f"(d[0]), "+f"(d[1]), "+f"(d[2]), "+f"(d[3])
        : "r"(a[0]), "r"(a[1]), "r"(a[2]), "r"(a[3]), "r"(b[0]), "r"(b[1]));
}
__device__ __forceinline__ void ldsm_x4(uint32_t* r, uint32_t addr) {
    asm volatile("ldmatrix.sync.aligned.m8n8.x4.shared.b16 {%0,%1,%2,%3}, [%4];"
        : "=r"(r[0]), "=r"(r[1]), "=r"(r[2]), "=r"(r[3]) : "r"(addr));
}
__device__ __forceinline__ void ldsm_x4t(uint32_t* r, uint32_t addr) {
    asm volatile("ldmatrix.sync.aligned.m8n8.x4.trans.shared.b16 {%0,%1,%2,%3}, [%4];"
        : "=r"(r[0]), "=r"(r[1]), "=r"(r[2]), "=r"(r[3]) : "r"(addr));
}
__device__ __forceinline__ void cp_async16(uint32_t dst, const void* src) {
    asm volatile("cp.async.cg.shared.global [%0], [%1], 16;" :: "r"(dst), "l"(src));
}
#define CP_COMMIT() asm volatile("cp.async.commit_group;")
#define CP_WAIT0()  asm volatile("cp.async.wait_group 0;")
__device__ __forceinline__ uint32_t packh2(float a, float b) {
    __half2 h = __floats2half2_rn(a, b);
    return *(uint32_t*)&h;
}
__device__ __forceinline__ float fexp2(float x) {
    float y;
    asm("ex2.approx.f32 %0, %1;" : "=f"(y) : "f"(x));
    return y;
}

// ---------------- scratch (device globals) --------------------------------
__device__ __align__(16) float g_x  [M_ * E_];
__device__ __align__(16) float g_xo [M_ * E_];
__device__ __align__(16) float g_y  [M_ * E_];
__device__ __align__(16) __half g_qkv[M_ * NQKV_];
__device__ __align__(16) __half g_xhi[M_ * E_];
__device__ __align__(16) __half g_yhi[M_ * E_];
__device__ __align__(16) __half g_hhi[M_ * HID_];
__device__ __align__(16) __half g_wqkv[NQKV_ * E_];
__device__ __align__(16) __half g_w1t[HID_ * E_];
__device__ __align__(16) __half g_w2t[E_ * HID_];
__device__ float g_bcat[NQKV_];

// ---------------- LayerNorm row (device fn, used by prep + ln_kernel) ------
__device__ __forceinline__ void ln_row(const float* __restrict__ in,
                                       const float* __restrict__ w,
                                       const float* __restrict__ b,
                                       float* __restrict__ out,
                                       __half* __restrict__ ohi,
                                       int row, int t) {
    const float4* ip = (const float4*)(in + (size_t)row * E_);
    float4 v = ip[t];
    float s  = v.x + v.y + v.z + v.w;
    float sq = v.x*v.x + v.y*v.y + v.z*v.z + v.w*v.w;
    #pragma unroll
    for (int o = 16; o; o >>= 1) {
        s  += __shfl_xor_sync(0xffffffffu, s,  o);
        sq += __shfl_xor_sync(0xffffffffu, sq, o);
    }
    __shared__ float ss[8], ssq[8];
    __shared__ float mu_s, inv_s;
    if ((t & 31) == 0) { ss[t >> 5] = s; ssq[t >> 5] = sq; }
    __syncthreads();
    if (t < 32) {
        float s2  = (t < 8) ? ss[t]  : 0.f;
        float sq2 = (t < 8) ? ssq[t] : 0.f;
        #pragma unroll
        for (int o = 4; o; o >>= 1) {
            s2  += __shfl_xor_sync(0xffffffffu, s2,  o);
            sq2 += __shfl_xor_sync(0xffffffffu, sq2, o);
        }
        if (t == 0) {
            float mu  = s2 * (1.f / E_);
            float var = sq2 * (1.f / E_) - mu * mu;
            mu_s  = mu;
            inv_s = rsqrtf(var + 1e-5f);
        }
    }
    __syncthreads();
    float mu = mu_s, inv = inv_s;
    float4 wv = ((const float4*)w)[t];
    float4 bv = ((const float4*)b)[t];
    float4 o4;
    o4.x = (v.x - mu) * inv * wv.x + bv.x;
    o4.y = (v.y - mu) * inv * wv.y + bv.y;
    o4.z = (v.z - mu) * inv * wv.z + bv.z;
    o4.w = (v.w - mu) * inv * wv.w + bv.w;
    ((float4*)(out + (size_t)row * E_))[t] = o4;
    __half2 hp0; hp0.x = __float2half_rn(o4.x); hp0.y = __float2half_rn(o4.y);
    __half2 hp1; hp1.x = __float2half_rn(o4.z); hp1.y = __float2half_rn(o4.w);
    ((__half2*)(ohi + (size_t)row * E_))[2*t]   = hp0;
    ((__half2*)(ohi + (size_t)row * E_))[2*t+1] = hp1;
}

__global__ void ln_kernel(const float* __restrict__ in,
                          const float* __restrict__ w,
                          const float* __restrict__ b,
                          float* __restrict__ out,
                          __half* __restrict__ ohi) {
    ln_row(in, w, b, out, ohi, blockIdx.x, threadIdx.x);
}

// ---------------- merged prep: transposes + bias concat + LN1 --------------
// blocks: [0,3072) Wq/Wk/Wv | [3072,7168) W1 | [7168,11264) W2
//         [11264,11276) bias concat | [11276,15372) LN1 rows
__device__ __forceinline__ void transpose_tile(
        const float* __restrict__ in, __half* __restrict__ oh,
        int R, int C, int c0, int r0, float scale, int tx, int ty) {
    __shared__ float tile[32][33];
    #pragma unroll
    for (int j = 0; j < 4; j++)
        tile[ty + j * 8][tx] = in[(size_t)(r0 + ty + j * 8) * C + c0 + tx];
    __syncthreads();
    #pragma unroll
    for (int j = 0; j < 4; j++) {
        float v = tile[tx][ty + j * 8] * scale;
        oh[(size_t)(c0 + ty + j * 8) * R + r0 + tx] = __float2half_rn(v);
    }
}

__global__ void prep_kernel(const float* __restrict__ Wq, const float* __restrict__ Wk,
                            const float* __restrict__ Wv, const float* __restrict__ W1,
                            const float* __restrict__ W2,
                            const float* __restrict__ bq, const float* __restrict__ bk,
                            const float* __restrict__ bv,
                            const float* __restrict__ emb,
                            const float* __restrict__ ln1_w, const float* __restrict__ ln1_b,
                            __half* __restrict__ wqkv,
                            __half* __restrict__ w1t, __half* __restrict__ w2t,
                            float* __restrict__ bcat,
                            float* __restrict__ x, __half* __restrict__ xhi) {
    int id = blockIdx.x;
    int tx = threadIdx.x, ty = threadIdx.y;
    if (id < 3072) {
        int which = id >> 10;                  // 0=q,1=k,2=v
        int local = id & 1023;
        int z = local >> 6;                    // head
        int rem = local & 63;
        int cx = rem & 1, ry = rem >> 1;
        const float* src = (which == 0) ? Wq : (which == 1) ? Wk : Wv;
        float scale = (which == 0) ? QSCALE : 1.f;
        transpose_tile(src + (size_t)z * E_ * DK_,
                       wqkv + (size_t)which * 1024 * E_ + (size_t)z * DK_ * E_,
                       E_, DK_, cx * 32, ry * 32, scale, tx, ty);
    } else if (id < 7168) {
        int local = id - 3072;
        int cx = local & 127, ry = local >> 7;
        transpose_tile(W1, w1t, E_, HID_, cx * 32, ry * 32, 1.f, tx, ty);
    } else if (id < 11264) {
        int local = id - 7168;
        int cx = local & 31, ry = local >> 5;
        transpose_tile(W2, w2t, HID_, E_, cx * 32, ry * 32, 1.f, tx, ty);
    } else if (id < 11276) {
        int n = (id - 11264) * 256 + ty * 32 + tx;
        const float* src = (n < 1024) ? bq : ((n < 2048) ? bk : bv);
        float sc = (n < 1024) ? QSCALE : 1.f;
        bcat[n] = src[n & 1023] * sc;
    } else {
        ln_row(emb, ln1_w, ln1_b, x, xhi, id - 11276, ty * 32 + tx);
    }
}

// ---------------- HMMA GEMM: C[M,N] = Ahi @ Bhi^T (fp16, 1-pass) -----------
// CTA tile 128x128, 8 warps of 64x32, K chunk 64, 2-stage, ONE sync/chunk.
// mode 2: fp32 + bias + resid | mode 3: Chi + bias | mode 4: relu -> Chi
constexpr int GSTRIDE_B = 144;               // bytes per smem row (64 fp16 + pad)
constexpr int GTILE_B   = 128 * GSTRIDE_B;   // 18432 per array
constexpr int GBUF_B    = 2 * GTILE_B;       // 36864 per stage (Ahi,Bhi)
constexpr int GEMM_SMEM = 2 * GBUF_B;        // 73728

__global__ __launch_bounds__(256)
void gemm_mma(const __half* __restrict__ Ahi, const __half* __restrict__ Bhi,
              const float* __restrict__ bias, const float* __restrict__ resid,
              float* __restrict__ Cf, __half* __restrict__ Chi,
              int K, int N, int mode) {
    extern __shared__ char smraw[];
    uint32_t sb = smem_to_u32(smraw);
    int t = threadIdx.x, lane = t & 31, wid = t >> 5;
    int bm = blockIdx.y * 128, bn = blockIdx.x * 128;
    int wm = wid & 1, wn = wid >> 1;

    const __half* gsrc[2] = { Ahi + (size_t)bm * K, Bhi + (size_t)bn * K };

    float acc[4][4][4];
    #pragma unroll
    for (int i = 0; i < 4; i++)
        #pragma unroll
        for (int j = 0; j < 4; j++)
            #pragma unroll
            for (int e = 0; e < 4; e++) acc[i][j][e] = 0.f;

    int nch = K >> 6;                       // 64-wide chunks
    int ldrow = t >> 3, ldseg = t & 7;      // 32 rows per 256-thr pass

    // ---- prologue: chunk 0 -> buf 0 ----
    {
        #pragma unroll
        for (int arr = 0; arr < 2; arr++) {
            uint32_t dst = sb + arr * GTILE_B;
            #pragma unroll
            for (int f = 0; f < 4; f++) {
                int row = ldrow + f * 32;
                cp_async16(dst + row * GSTRIDE_B + ldseg * 16,
                           gsrc[arr] + (size_t)row * K + ldseg * 8);
            }
        }
        CP_COMMIT();
    }

    int arow = wm * 64 + (lane & 15);
    int acolsel = (lane >> 4) * 8;
    int brow4 = wn * 32 + ((lane >> 4) & 1) * 8 + (lane & 7);
    int bcolsel = ((lane >> 3) & 1) * 8;

    for (int c = 0; c < nch; c++) {
        CP_WAIT0();          // chunk c (committed last iter) arrived for MY copies
        __syncthreads();     // all threads' copies visible + prev buffer free
        if (c + 1 < nch) {   // prefetch AFTER barrier: overwrite of (c+1)&1 is safe
            int k0 = (c + 1) << 6;
            uint32_t base = sb + ((c + 1) & 1) * GBUF_B;
            #pragma unroll
            for (int arr = 0; arr < 2; arr++) {
                uint32_t dst = base + arr * GTILE_B;
                #pragma unroll
                for (int f = 0; f < 4; f++) {
                    int row = ldrow + f * 32;
                    cp_async16(dst + row * GSTRIDE_B + ldseg * 16,
                               gsrc[arr] + (size_t)row * K + k0 + ldseg * 8);
                }
            }
            CP_COMMIT();
        }

        uint32_t base = sb + (c & 1) * GBUF_B;
        uint32_t aHiB = base;
        uint32_t bHiB = base + GTILE_B;

        #pragma unroll
        for (int ks = 0; ks < 4; ks++) {
            int k0 = ks * 16;
            int acol = k0 + acolsel;
            int bcol = k0 + bcolsel;

            uint32_t ah[4][4], bh[4][2];
            #pragma unroll
            for (int mt = 0; mt < 4; mt++)
                ldsm_x4(ah[mt], aHiB + (arow + mt * 16) * GSTRIDE_B + acol * 2);
            #pragma unroll
            for (int p = 0; p < 2; p++) {
                uint32_t tmp[4];
                ldsm_x4(tmp, bHiB + (brow4 + p * 16) * GSTRIDE_B + bcol * 2);
                bh[2*p][0] = tmp[0]; bh[2*p][1] = tmp[1];
                bh[2*p+1][0] = tmp[2]; bh[2*p+1][1] = tmp[3];
            }
            #pragma unroll
            for (int nt = 0; nt < 4; nt++)
                #pragma unroll
                for (int mt = 0; mt < 4; mt++)
                    mma16816(acc[mt][nt], ah[mt], bh[nt]);
        }
    }

    // ---- epilogue ----
    int r = lane >> 2, q2 = (lane & 3) * 2;
    #pragma unroll
    for (int mt = 0; mt < 4; mt++) {
        int row0 = bm + wm * 64 + mt * 16 + r;
        #pragma unroll
        for (int nt = 0; nt < 4; nt++) {
            int col = bn + wn * 32 + nt * 8 + q2;
            float b0 = bias[col], b1 = bias[col + 1];
            float v0 = acc[mt][nt][0] + b0, v1 = acc[mt][nt][1] + b1;
            float v2 = acc[mt][nt][2] + b0, v3 = acc[mt][nt][3] + b1;
            size_t gi0 = (size_t)row0 * N + col;
            size_t gi1 = gi0 + (size_t)8 * N;
            if (mode == 2) {
                float2 r0 = *(const float2*)(resid + gi0);
                float2 r1 = *(const float2*)(resid + gi1);
                *(float2*)(Cf + gi0) = make_float2(v0 + r0.x, v1 + r0.y);
                *(float2*)(Cf + gi1) = make_float2(v2 + r1.x, v3 + r1.y);
            } else {
                if (mode == 4) {
                    v0 = fmaxf(v0, 0.f); v1 = fmaxf(v1, 0.f);
                    v2 = fmaxf(v2, 0.f); v3 = fmaxf(v3, 0.f);
                }
                __half2 hp0; hp0.x = __float2half_rn(v0); hp0.y = __float2half_rn(v1);
                __half2 hp1; hp1.x = __float2half_rn(v2); hp1.y = __float2half_rn(v3);
                *(__half2*)(Chi + gi0) = hp0;
                *(__half2*)(Chi + gi1) = hp1;
            }
        }
    }
}

// ---------------- HMMA flash attention (fp16, exp2 softmax) ----------------
// CTA: 128 q rows (8 warps x 16), kv tiles of 64, 2-stage, ONE sync/tile.
constexpr int AST = 144;                       // row stride bytes (64 fp16 + pad)
constexpr int AOFF_Q  = 0;                     // 128 x AST
constexpr int AOFF_KV = 128 * AST;             // 18432
constexpr int KV_STAGE = 2 * 64 * AST;         // 18432 (Khi,Vhi)
constexpr int ATTN_SMEM = AOFF_KV + 2 * KV_STAGE;  // 55296 -> 3 CTAs/SM

__device__ __forceinline__ void cp_kv_tile(uint32_t base,
        const __half* khi, const __half* vhi, int t) {
    #pragma unroll
    for (int f = 0; f < 2; f++) {
        int idx = t + f * 256;
        int row = idx >> 3, seg = idx & 7;
        uint32_t o = row * AST + seg * 16;
        size_t go = (size_t)row * QKV_LD + seg * 8;
        cp_async16(base + o,            khi + go);
        cp_async16(base + 64 * AST + o, vhi + go);
    }
}

__global__ __launch_bounds__(256, 3)
void attn_mma(const __half* __restrict__ qkv,
              const float* __restrict__ x,
              float* __restrict__ xo) {
    extern __shared__ char smraw[];
    uint32_t sb = smem_to_u32(smraw);
    int qt = gridDim.x - 1 - blockIdx.x;       // heavy tiles first
    int h = blockIdx.y, b = blockIdx.z;
    int t = threadIdx.x, lane = t & 31, wid = t >> 5;

    const __half* qsrc = qkv + (size_t)(b * S_ + qt * 128) * QKV_LD + h * 64;
    const __half* khi0 = qkv + (size_t)(b * S_) * QKV_LD + 1024 + h * 64;
    const __half* vhi0 = khi0 + 1024;

    // ---- prologue: Q tile + KV tile 0 ----
    #pragma unroll
    for (int f = 0; f < 4; f++) {
        int idx = t + f * 256;
        int row = idx >> 3, seg = idx & 7;
        cp_async16(sb + AOFF_Q + row * AST + seg * 16,
                   qsrc + (size_t)row * QKV_LD + seg * 8);
    }
    cp_kv_tile(sb + AOFF_KV, khi0, vhi0, t);
    CP_COMMIT();

    float o[8][4];
    #pragma unroll
    for (int i = 0; i < 8; i++)
        #pragma unroll
        for (int j = 0; j < 4; j++) o[i][j] = 0.f;
    float m0 = -INFINITY, m1 = -INFINITY, l0 = 0.f, l1 = 0.f;

    int r = lane >> 2, q2 = (lane & 3) * 2;
    int grow0 = qt * 128 + wid * 16 + r;
    int grow1 = grow0 + 8;

    int arow = wid * 16 + (lane & 15);
    int acolsel = (lane >> 4) * 8;
    int krow4 = ((lane >> 4) & 1) * 8 + (lane & 7);    // + pair*16
    int kcolsel = ((lane >> 3) & 1) * 8;
    int vrow4 = lane & 15;                             // + ksIdx*16
    int vcolsel = ((lane >> 4) & 1) * 16;              // bytes, + pair*32

    int nkt = 2 * qt + 2;
    for (int kt = 0; kt < nkt; kt++) {
        CP_WAIT0();
        __syncthreads();
        if (kt + 1 < nkt) {     // prefetch after barrier: buffer reuse safe
            size_t koff = (size_t)((kt + 1) * 64) * QKV_LD;
            cp_kv_tile(sb + AOFF_KV + ((kt + 1) & 1) * KV_STAGE,
                       khi0 + koff, vhi0 + koff, t);
            CP_COMMIT();
        }

        uint32_t kvb = sb + AOFF_KV + (kt & 1) * KV_STAGE;
        uint32_t kHiB = kvb;
        uint32_t vHiB = kvb + 64 * AST;

        // ---- scores S = Q K^T (log2 domain; scale folded into Wq) ----
        float s[8][4];
        #pragma unroll
        for (int i = 0; i < 8; i++)
            #pragma unroll
            for (int j = 0; j < 4; j++) s[i][j] = 0.f;

        #pragma unroll
        for (int ksIdx = 0; ksIdx < 4; ksIdx++) {
            int k0 = ksIdx * 16;
            int acol = k0 + acolsel;
            int bcol = k0 + kcolsel;
            uint32_t qh[4];
            ldsm_x4(qh, sb + AOFF_Q + arow * AST + acol * 2);
            #pragma unroll
            for (int p = 0; p < 4; p++) {
                uint32_t th[4];
                ldsm_x4(th, kHiB + (krow4 + p * 16) * AST + bcol * 2);
                mma16816(s[2*p],   qh, th);
                mma16816(s[2*p+1], qh, th + 2);
            }
        }

        // ---- causal mask (diagonal tiles only) ----
        if (kt >= 2 * qt) {
            #pragma unroll
            for (int nt = 0; nt < 8; nt++) {
                int gc = kt * 64 + nt * 8 + q2;
                if (gc > grow0)     s[nt][0] = -INFINITY;
                if (gc + 1 > grow0) s[nt][1] = -INFINITY;
                if (gc > grow1)     s[nt][2] = -INFINITY;
                if (gc + 1 > grow1) s[nt][3] = -INFINITY;
            }
        }

        // ---- online softmax (base-2) ----
        float mx0 = -INFINITY, mx1 = -INFINITY;
        #pragma unroll
        for (int nt = 0; nt < 8; nt++) {
            mx0 = fmaxf(mx0, fmaxf(s[nt][0], s[nt][1]));
            mx1 = fmaxf(mx1, fmaxf(s[nt][2], s[nt][3]));
        }
        mx0 = fmaxf(mx0, __shfl_xor_sync(0xffffffffu, mx0, 1));
        mx0 = fmaxf(mx0, __shfl_xor_sync(0xffffffffu, mx0, 2));
        mx1 = fmaxf(mx1, __shfl_xor_sync(0xffffffffu, mx1, 1));
        mx1 = fmaxf(mx1, __shfl_xor_sync(0xffffffffu, mx1, 2));
        float mn0 = fmaxf(m0, mx0), mn1 = fmaxf(m1, mx1);
        float c0 = fexp2(m0 - mn0), c1 = fexp2(m1 - mn1);
        float ps0 = 0.f, ps1 = 0.f;
        #pragma unroll
        for (int nt = 0; nt < 8; nt++) {
            s[nt][0] = fexp2(s[nt][0] - mn0);
            s[nt][1] = fexp2(s[nt][1] - mn0);
            s[nt][2] = fexp2(s[nt][2] - mn1);
            s[nt][3] = fexp2(s[nt][3] - mn1);
            ps0 += s[nt][0] + s[nt][1];
            ps1 += s[nt][2] + s[nt][3];
        }
        ps0 += __shfl_xor_sync(0xffffffffu, ps0, 1);
        ps0 += __shfl_xor_sync(0xffffffffu, ps0, 2);
        ps1 += __shfl_xor_sync(0xffffffffu, ps1, 1);
        ps1 += __shfl_xor_sync(0xffffffffu, ps1, 2);
        l0 = l0 * c0 + ps0;
        l1 = l1 * c1 + ps1;
        m0 = mn0; m1 = mn1;
        #pragma unroll
        for (int dt = 0; dt < 8; dt++) {
            o[dt][0] *= c0; o[dt][1] *= c0;
            o[dt][2] *= c1; o[dt][3] *= c1;
        }

        // ---- O += P @ Vhi (P fp16 in regs; V via x4.trans pairs) ----
        #pragma unroll
        for (int ksIdx = 0; ksIdx < 4; ksIdx++) {
            uint32_t a[4];
            a[0] = packh2(s[2*ksIdx][0],   s[2*ksIdx][1]);
            a[1] = packh2(s[2*ksIdx][2],   s[2*ksIdx][3]);
            a[2] = packh2(s[2*ksIdx+1][0], s[2*ksIdx+1][1]);
            a[3] = packh2(s[2*ksIdx+1][2], s[2*ksIdx+1][3]);
            uint32_t vbase = vHiB + (ksIdx * 16 + vrow4) * AST + vcolsel;
            #pragma unroll
            for (int p = 0; p < 4; p++) {
                uint32_t tv[4];
                ldsm_x4t(tv, vbase + p * 32);
                mma16816(o[2*p],   a, tv);
                mma16816(o[2*p+1], a, tv + 2);
            }
        }
    }

    // ---- epilogue: o/l + residual ----
    float il0 = 1.f / l0, il1 = 1.f / l1;
    int row0 = b * S_ + qt * 128 + wid * 16 + r;
    int row1 = row0 + 8;
    #pragma unroll
    for (int dt = 0; dt < 8; dt++) {
        int col = h * 64 + dt * 8 + q2;
        size_t gi0 = (size_t)row0 * E_ + col;
        size_t gi1 = (size_t)row1 * E_ + col;
        float2 x0 = *(const float2*)(x + gi0);
        float2 x1 = *(const float2*)(x + gi1);
        *(float2*)(xo + gi0) = make_float2(x0.x + o[dt][0] * il0,
                                           x0.y + o[dt][1] * il0);
        *(float2*)(xo + gi1) = make_float2(x1.x + o[dt][2] * il1,
                                           x1.y + o[dt][3] * il1);
    }
}

// ---------------- launcher -------------------------------------------------
extern "C" void kernel_launch(void* const* d_in, const int* in_sizes, int n_in,
                              void* d_out, int out_size) {
    const float* emb   = (const float*)d_in[0];
    const float* Wq    = (const float*)d_in[1];
    const float* bq    = (const float*)d_in[2];
    const float* Wk    = (const float*)d_in[3];
    const float* bk    = (const float*)d_in[4];
    const float* Wv    = (const float*)d_in[5];
    const float* bv    = (const float*)d_in[6];
    const float* ln1_w = (const float*)d_in[7];
    const float* ln1_b = (const float*)d_in[8];
    const float* ln2_w = (const float*)d_in[9];
    const float* ln2_b = (const float*)d_in[10];
    const float* W1    = (const float*)d_in[11];
    const float* b1    = (const float*)d_in[12];
    const float* W2    = (const float*)d_in[13];
    const float* b2    = (const float*)d_in[14];
    float* out = (float*)d_out;

    float *px, *pxo, *py, *pbcat;
    __half *pqkv, *pxhi, *pyhi, *phhi, *pwq, *pw1, *pw2;
    cudaGetSymbolAddress((void**)&px,   g_x);
    cudaGetSymbolAddress((void**)&pxo,  g_xo);
    cudaGetSymbolAddress((void**)&py,   g_y);
    cudaGetSymbolAddress((void**)&pbcat,g_bcat);
    cudaGetSymbolAddress((void**)&pqkv, g_qkv);
    cudaGetSymbolAddress((void**)&pxhi, g_xhi);
    cudaGetSymbolAddress((void**)&pyhi, g_yhi);
    cudaGetSymbolAddress((void**)&phhi, g_hhi);
    cudaGetSymbolAddress((void**)&pwq,  g_wqkv);
    cudaGetSymbolAddress((void**)&pw1,  g_w1t);
    cudaGetSymbolAddress((void**)&pw2,  g_w2t);

    cudaFuncSetAttribute(gemm_mma,
                         cudaFuncAttributeMaxDynamicSharedMemorySize, GEMM_SMEM);
    cudaFuncSetAttribute(attn_mma,
                         cudaFuncAttributeMaxDynamicSharedMemorySize, ATTN_SMEM);

    // launch 0: prep (transposes + bias concat + LN1)
    prep_kernel<<<15372, dim3(32, 8)>>>(Wq, Wk, Wv, W1, W2, bq, bk, bv,
                                        emb, ln1_w, ln1_b,
                                        pwq, pw1, pw2, pbcat, px, pxhi);

    // launch 1: fused QKV (log2e-scaled q) -> fp16
    gemm_mma<<<dim3(NQKV_/128, M_/128), 256, GEMM_SMEM>>>(
        pxhi, pwq, pbcat, nullptr, nullptr, pqkv, E_, NQKV_, 3);

    // launch 2: attention + residual -> g_xo
    attn_mma<<<dim3(S_/128, H_, B_), 256, ATTN_SMEM>>>(pqkv, px, pxo);

    // launch 3: LN2 -> y fp32 + fp16
    ln_kernel<<<M_, 256>>>(pxo, ln2_w, ln2_b, py, pyhi);

    // launch 4: FFN1: h = relu(y @ W1 + b1) -> fp16
    gemm_mma<<<dim3(HID_/128, M_/128), 256, GEMM_SMEM>>>(
        pyhi, pw1, b1, nullptr, nullptr, phhi, E_, HID_, 4);

    // launch 5: FFN2: out = y + h @ W2 + b2
    gemm_mma<<<dim3(E_/128, M_/128), 256, GEMM_SMEM>>>(
        phhi, pw2, b2, py, out, nullptr, HID_, E_, 2);
}